// round 1
// baseline (speedup 1.0000x reference)
#include <cuda_runtime.h>
#include <cstdint>
#include <cstddef>
#include <math_constants.h>

// ---------------- problem constants (match reference init) ----------------
#define NN 50000   // nodes
#define NE 25000   // hyperedges
#define PE 400000  // node->edge incidences
#define ME 800000  // conv edges, edge side
#define PN 400000  // edge->node incidences
#define MN 800000  // conv edges, node side

static __host__ __device__ constexpr size_t alup(size_t x) { return (x + 255) & ~size_t(255); }

// ---------------- scratch layout (one big __device__ buffer) ----------------
constexpr size_t O_NODEH = 0;
constexpr size_t O_NODEV = O_NODEH + alup((size_t)NN * 128 * 4);
constexpr size_t O_NODES = O_NODEV + alup((size_t)NN * 128 * 4);
constexpr size_t O_DEGA  = O_NODES + alup((size_t)NN * 4 * 4);
constexpr size_t O_DINVA = O_DEGA  + alup((size_t)PE * 4);
constexpr size_t O_SEGPA = O_DINVA + alup((size_t)PE * 4);
constexpr size_t O_CNTA  = O_SEGPA + alup((size_t)(NE + 1) * 4);
constexpr size_t O_OFFA  = O_CNTA  + alup((size_t)NE * 4);
constexpr size_t O_CURA  = O_OFFA  + alup((size_t)(NE + 1) * 4);
constexpr size_t O_SRTGA = O_CURA  + alup((size_t)NE * 4);
constexpr size_t O_SRTWA = O_SRTGA + alup((size_t)ME * 4);
constexpr size_t O_POOLA = O_SRTWA + alup((size_t)ME * 4);
constexpr size_t O_EDGEX = O_POOLA + alup((size_t)NE * 128 * 4);
constexpr size_t O_EDGEH = O_EDGEX + alup((size_t)NE * 256 * 4);
constexpr size_t O_EDGEV = O_EDGEH + alup((size_t)NE * 128 * 4);
constexpr size_t O_EDGES = O_EDGEV + alup((size_t)NE * 128 * 4);
constexpr size_t O_DEGB  = O_EDGES + alup((size_t)NE * 4 * 4);
constexpr size_t O_DINVB = O_DEGB  + alup((size_t)PN * 4);
constexpr size_t O_SEGPB = O_DINVB + alup((size_t)PN * 4);
constexpr size_t O_CNTB  = O_SEGPB + alup((size_t)(NN + 1) * 4);
constexpr size_t O_OFFB  = O_CNTB  + alup((size_t)NN * 4);
constexpr size_t O_CURB  = O_OFFB  + alup((size_t)(NN + 1) * 4);
constexpr size_t O_SRTGB = O_CURB  + alup((size_t)NN * 4);
constexpr size_t O_SRTWB = O_SRTGB + alup((size_t)MN * 4);
constexpr size_t O_POOLB = O_SRTWB + alup((size_t)MN * 4);
constexpr size_t O_NODEO = O_POOLB + alup((size_t)NN * 128 * 4);
constexpr size_t O_LOGIT = O_NODEO + alup((size_t)NN * 256 * 4);
constexpr size_t O_WKSA  = O_LOGIT + alup((size_t)NN * 40 * 4);
constexpr size_t O_WKSB  = O_WKSA  + alup((size_t)128 * 4 * 4);
constexpr size_t O_INCL  = O_WKSB  + alup((size_t)256 * 4 * 4);
constexpr size_t O_BSUM  = O_INCL  + alup((size_t)50176 * 4);
constexpr size_t SCRATCH_TOTAL = O_BSUM + alup((size_t)64 * 4);

__device__ __align__(256) unsigned char g_scratch[SCRATCH_TOTAL];

// ---------------- utility kernels ----------------
__global__ void fill_int_k(int* p, int v, int n) {
    int i = blockIdx.x * blockDim.x + threadIdx.x;
    if (i < n) p[i] = v;
}

// fold Wk [K,128] with seed [4,32] -> Wks [K,4], including 1/sqrt(32)
__global__ void fold_seed_k(const float* __restrict__ Wk, const float* __restrict__ seed,
                            float* __restrict__ Wks, int K) {
    int i = blockIdx.x * blockDim.x + threadIdx.x;
    if (i >= K * 4) return;
    int f = i >> 2, h = i & 3;
    float s = 0.f;
    #pragma unroll
    for (int d = 0; d < 32; d++) s += Wk[(size_t)f * 128 + h * 32 + d] * seed[h * 32 + d];
    Wks[i] = s * 0.17677669529663687f;  // 1/sqrt(32)
}

__global__ void deg_accum_k(const int* __restrict__ dst, int m, int* __restrict__ deg) {
    int i = blockIdx.x * blockDim.x + threadIdx.x;
    if (i < m) atomicAdd(&deg[dst[i]], 1);
}

__global__ void dinv_k(const int* __restrict__ deg, float* __restrict__ dinv, int n) {
    int i = blockIdx.x * blockDim.x + threadIdx.x;
    if (i < n) dinv[i] = rsqrtf((float)deg[i]);
}

// segP[s] = lower_bound(batch, s) for s in [0, S]
__global__ void seg_starts_k(const int* __restrict__ batch, int P, int S, int* __restrict__ segP) {
    int s = blockIdx.x * blockDim.x + threadIdx.x;
    if (s > S) return;
    int lo = 0, hi = P;
    while (lo < hi) {
        int mid = (lo + hi) >> 1;
        if (batch[mid] < s) lo = mid + 1; else hi = mid;
    }
    segP[s] = lo;
}

__global__ void bucket_count_k(const int* __restrict__ dst, const int* __restrict__ batch,
                               int m, int* __restrict__ cnt) {
    int i = blockIdx.x * blockDim.x + threadIdx.x;
    if (i < m) atomicAdd(&cnt[batch[dst[i]]], 1);
}

__global__ void bucket_scatter_k(const int* __restrict__ src, const int* __restrict__ dst,
                                 const int* __restrict__ batch, const int* __restrict__ map,
                                 const float* __restrict__ dinv, const int* __restrict__ off,
                                 int* __restrict__ cursor, int m,
                                 int* __restrict__ outG, float* __restrict__ outW) {
    int i = blockIdx.x * blockDim.x + threadIdx.x;
    if (i >= m) return;
    int d = dst[i];
    int s = batch[d];
    int pos = off[s] + atomicAdd(&cursor[s], 1);
    int sc = src[i];
    outG[pos] = map[sc];
    outW[pos] = dinv[sc] * dinv[d];
}

// ---------------- prefix scan (exclusive), up to 64*1024 elements ----------------
__global__ void scan_block_k(const int* __restrict__ cnt, int n,
                             int* __restrict__ incl, int* __restrict__ bsums) {
    __shared__ int sm[1024];
    int i = blockIdx.x * 1024 + threadIdx.x;
    int v = (i < n) ? cnt[i] : 0;
    sm[threadIdx.x] = v;
    __syncthreads();
    for (int o = 1; o < 1024; o <<= 1) {
        int t = (threadIdx.x >= o) ? sm[threadIdx.x - o] : 0;
        __syncthreads();
        sm[threadIdx.x] += t;
        __syncthreads();
    }
    if (i < n) incl[i] = sm[threadIdx.x];
    if (threadIdx.x == 1023) bsums[blockIdx.x] = sm[1023];
}

__global__ void scan_bsums_k(int* bsums, int nb) {
    if (threadIdx.x == 0 && blockIdx.x == 0) {
        int run = 0;
        for (int b = 0; b < nb; b++) { int t = bsums[b]; bsums[b] = run; run += t; }
    }
}

__global__ void scan_finalize_k(const int* __restrict__ incl, const int* __restrict__ bsums,
                                int n, int* __restrict__ off) {
    int i = blockIdx.x * 1024 + threadIdx.x;
    if (i < n) off[i + 1] = incl[i] + bsums[blockIdx.x];
    if (i == 0) off[0] = 0;
}

// ---------------- SGEMM: C[M,N] = act(A[M,K] @ B[K,N] + bias), ldc-strided C ----------------
__global__ void sgemm64_k(const float* __restrict__ A, const float* __restrict__ B,
                          const float* __restrict__ bias, float* __restrict__ C,
                          int M, int N, int K, int ldc, int doRelu) {
    __shared__ float As[16][64 + 4];
    __shared__ float Bs[16][64 + 4];
    int tid = threadIdx.x;
    int row0 = blockIdx.y * 64, col0 = blockIdx.x * 64;
    int tx = tid & 15, ty = tid >> 4;
    float acc[4][4] = {};
    for (int k0 = 0; k0 < K; k0 += 16) {
        #pragma unroll
        for (int q = 0; q < 4; q++) {
            int idx = tid + q * 256;
            int r = idx >> 4, kk = idx & 15;
            int gr = row0 + r;
            As[kk][r] = (gr < M) ? A[(size_t)gr * K + k0 + kk] : 0.f;
        }
        #pragma unroll
        for (int q = 0; q < 4; q++) {
            int idx = tid + q * 256;
            int kk = idx >> 6, j = idx & 63;
            int gc = col0 + j;
            Bs[kk][j] = (gc < N) ? B[(size_t)(k0 + kk) * N + gc] : 0.f;
        }
        __syncthreads();
        #pragma unroll
        for (int kk = 0; kk < 16; kk++) {
            float a[4], b[4];
            #pragma unroll
            for (int i = 0; i < 4; i++) a[i] = As[kk][ty * 4 + i];
            #pragma unroll
            for (int j = 0; j < 4; j++) b[j] = Bs[kk][tx * 4 + j];
            #pragma unroll
            for (int i = 0; i < 4; i++)
                #pragma unroll
                for (int j = 0; j < 4; j++) acc[i][j] += a[i] * b[j];
        }
        __syncthreads();
    }
    #pragma unroll
    for (int i = 0; i < 4; i++) {
        int gr = row0 + ty * 4 + i;
        if (gr >= M) continue;
        #pragma unroll
        for (int j = 0; j < 4; j++) {
            int gc = col0 + tx * 4 + j;
            if (gc >= N) continue;
            float v = acc[i][j];
            if (bias) v += bias[gc];
            if (doRelu) v = fmaxf(v, 0.f);
            C[(size_t)gr * ldc + gc] = v;
        }
    }
}

// ---------------- small [M,4] = X[M,K] @ Wks[K,4], one warp per row ----------------
__global__ void rowdot4_k(const float* __restrict__ X, const float* __restrict__ Wks,
                          float* __restrict__ out, int M, int K) {
    int gw = (blockIdx.x * blockDim.x + threadIdx.x) >> 5;
    int lane = threadIdx.x & 31;
    if (gw >= M) return;
    const float* x = X + (size_t)gw * K;
    float a0 = 0, a1 = 0, a2 = 0, a3 = 0;
    for (int f = lane; f < K; f += 32) {
        float xv = x[f];
        const float* w = Wks + (size_t)f * 4;
        a0 += xv * w[0]; a1 += xv * w[1]; a2 += xv * w[2]; a3 += xv * w[3];
    }
    #pragma unroll
    for (int o = 16; o; o >>= 1) {
        a0 += __shfl_xor_sync(0xffffffffu, a0, o);
        a1 += __shfl_xor_sync(0xffffffffu, a1, o);
        a2 += __shfl_xor_sync(0xffffffffu, a2, o);
        a3 += __shfl_xor_sync(0xffffffffu, a3, o);
    }
    if (lane == 0) {
        float* o4 = out + (size_t)gw * 4;
        o4[0] = a0; o4[1] = a1; o4[2] = a2; o4[3] = a3;
    }
}

// ---------------- fused per-segment: GCN-conv mean + PMA softmax pool ----------------
// block = 128 threads (channel c), grid = S segments. Segments contiguous in incidence
// arrays (batch sorted); conv edges pre-sorted by destination segment.
__global__ void seg_fused_k(const float* __restrict__ H, const float* __restrict__ V,
                            const float* __restrict__ S4, const int* __restrict__ map,
                            const float* __restrict__ dinv,
                            const int* __restrict__ segP, const int* __restrict__ eOff,
                            const int* __restrict__ sG, const float* __restrict__ sW,
                            const float* __restrict__ bias,
                            float* __restrict__ outConv, int ldOut,
                            float* __restrict__ pooled) {
    int s = blockIdx.x;
    int c = threadIdx.x;
    int h = c >> 5, lane = c & 31;
    int p0 = segP[s], p1 = segP[s + 1];
    int e0 = eOff[s], e1 = eOff[s + 1];

    // conv: sum over sorted conv edges of this segment + self-loop terms
    float a0 = 0, a1 = 0, a2 = 0, a3 = 0;
    int j = e0;
    for (; j + 3 < e1; j += 4) {
        int g0 = sG[j], g1 = sG[j + 1], g2 = sG[j + 2], g3 = sG[j + 3];
        float w0 = sW[j], w1 = sW[j + 1], w2 = sW[j + 2], w3 = sW[j + 3];
        a0 += H[(size_t)g0 * 128 + c] * w0;
        a1 += H[(size_t)g1 * 128 + c] * w1;
        a2 += H[(size_t)g2 * 128 + c] * w2;
        a3 += H[(size_t)g3 * 128 + c] * w3;
    }
    for (; j < e1; j++) a0 += H[(size_t)sG[j] * 128 + c] * sW[j];
    for (int p = p0; p < p1; p++) {
        int g = map[p];
        float w = dinv[p];
        a1 += H[(size_t)g * 128 + c] * (w * w);
    }
    float acc = (a0 + a1) + (a2 + a3);
    int cnt = p1 - p0;
    float conv = (cnt > 0) ? (acc / (float)cnt + bias[c]) : 0.f;
    outConv[(size_t)s * ldOut + c] = fmaxf(conv, 0.f);

    // PMA: warp h handles head h (segment max, exp-sum, then weighted V sum)
    float m = -CUDART_INF_F;
    for (int p = p0 + lane; p < p1; p += 32)
        m = fmaxf(m, S4[(size_t)map[p] * 4 + h]);
    #pragma unroll
    for (int o = 16; o; o >>= 1) m = fmaxf(m, __shfl_xor_sync(0xffffffffu, m, o));
    float den = 0.f;
    for (int p = p0 + lane; p < p1; p += 32)
        den += __expf(S4[(size_t)map[p] * 4 + h] - m);
    #pragma unroll
    for (int o = 16; o; o >>= 1) den += __shfl_xor_sync(0xffffffffu, den, o);
    float pv = 0.f;
    for (int p = p0; p < p1; p++) {
        int g = map[p];
        float ex = __expf(S4[(size_t)g * 4 + h] - m);
        pv += ex * V[(size_t)g * 128 + c];
    }
    pooled[(size_t)s * 128 + c] = (cnt > 0) ? pv / fmaxf(den, 1e-9f) : 0.f;
}

// ---------------- log_softmax over 40 classes, one warp per row ----------------
__global__ void log_softmax40_k(const float* __restrict__ logits, float* __restrict__ out, int M) {
    int gw = (blockIdx.x * blockDim.x + threadIdx.x) >> 5;
    int lane = threadIdx.x & 31;
    if (gw >= M) return;
    const float* row = logits + (size_t)gw * 40;
    float v0 = row[lane];
    float v1 = (lane < 8) ? row[32 + lane] : -CUDART_INF_F;
    float m = fmaxf(v0, v1);
    #pragma unroll
    for (int o = 16; o; o >>= 1) m = fmaxf(m, __shfl_xor_sync(0xffffffffu, m, o));
    float e = __expf(v0 - m) + ((lane < 8) ? __expf(v1 - m) : 0.f);
    #pragma unroll
    for (int o = 16; o; o >>= 1) e += __shfl_xor_sync(0xffffffffu, e, o);
    float lse = m + logf(e);
    float* orow = out + (size_t)gw * 40;
    orow[lane] = v0 - lse;
    if (lane < 8) orow[32 + lane] = v1 - lse;
}

// ---------------- orchestration ----------------
static inline int cdiv(int a, int b) { return (a + b - 1) / b; }

extern "C" void kernel_launch(void* const* d_in, const int* in_sizes, int n_in,
                              void* d_out, int out_size) {
    (void)in_sizes; (void)n_in; (void)out_size;
    const float* node_x  = (const float*)d_in[0];
    const int* eb_map    = (const int*)d_in[1];
    const int* eb_ei     = (const int*)d_in[2];  // [0,ME)=src, [ME,2ME)=dst
    const int* eb_batch  = (const int*)d_in[3];
    const int* nb_map    = (const int*)d_in[4];
    const int* nb_ei     = (const int*)d_in[5];
    const int* nb_batch  = (const int*)d_in[6];
    const float* W1   = (const float*)d_in[7];
    const float* b1   = (const float*)d_in[8];
    const float* Wk1  = (const float*)d_in[9];
    const float* Wv1  = (const float*)d_in[10];
    const float* sd1  = (const float*)d_in[11];
    const float* Wo1  = (const float*)d_in[12];
    const float* W2   = (const float*)d_in[13];
    const float* b2   = (const float*)d_in[14];
    const float* Wk2  = (const float*)d_in[15];
    const float* Wv2  = (const float*)d_in[16];
    const float* sd2  = (const float*)d_in[17];
    const float* Wo2  = (const float*)d_in[18];
    const float* clsW = (const float*)d_in[19];
    const float* clsb = (const float*)d_in[20];
    float* out = (float*)d_out;

    void* basep = nullptr;
    cudaGetSymbolAddress(&basep, g_scratch);
    char* base = (char*)basep;
    float* nodeH  = (float*)(base + O_NODEH);
    float* nodeV  = (float*)(base + O_NODEV);
    float* nodeS  = (float*)(base + O_NODES);
    int*   degA   = (int*)  (base + O_DEGA);
    float* dinvA  = (float*)(base + O_DINVA);
    int*   segPA  = (int*)  (base + O_SEGPA);
    int*   cntA   = (int*)  (base + O_CNTA);
    int*   offA   = (int*)  (base + O_OFFA);
    int*   curA   = (int*)  (base + O_CURA);
    int*   srtGA  = (int*)  (base + O_SRTGA);
    float* srtWA  = (float*)(base + O_SRTWA);
    float* poolA  = (float*)(base + O_POOLA);
    float* edgeX  = (float*)(base + O_EDGEX);
    float* edgeH  = (float*)(base + O_EDGEH);
    float* edgeV  = (float*)(base + O_EDGEV);
    float* edgeS  = (float*)(base + O_EDGES);
    int*   degB   = (int*)  (base + O_DEGB);
    float* dinvB  = (float*)(base + O_DINVB);
    int*   segPB  = (int*)  (base + O_SEGPB);
    int*   cntB   = (int*)  (base + O_CNTB);
    int*   offB   = (int*)  (base + O_OFFB);
    int*   curB   = (int*)  (base + O_CURB);
    int*   srtGB  = (int*)  (base + O_SRTGB);
    float* srtWB  = (float*)(base + O_SRTWB);
    float* poolB  = (float*)(base + O_POOLB);
    float* nodeO  = (float*)(base + O_NODEO);
    float* logit  = (float*)(base + O_LOGIT);
    float* WksA   = (float*)(base + O_WKSA);
    float* WksB   = (float*)(base + O_WKSB);
    int*   incl   = (int*)  (base + O_INCL);
    int*   bsum   = (int*)  (base + O_BSUM);

    // fold Wk with seed
    fold_seed_k<<<1, 512>>>(Wk1, sd1, WksA, 128);
    fold_seed_k<<<1, 1024>>>(Wk2, sd2, WksB, 256);

    // ===== stage A: node -> edge =====
    {
        dim3 g(cdiv(128, 64), cdiv(NN, 64));
        sgemm64_k<<<g, 256>>>(node_x, W1,  nullptr, nodeH, NN, 128, 128, 128, 0);
        sgemm64_k<<<g, 256>>>(node_x, Wv1, nullptr, nodeV, NN, 128, 128, 128, 0);
    }
    rowdot4_k<<<cdiv(NN * 32, 256), 256>>>(node_x, WksA, nodeS, NN, 128);

    fill_int_k<<<cdiv(PE, 256), 256>>>(degA, 1, PE);  // self-loop
    deg_accum_k<<<cdiv(ME, 256), 256>>>(eb_ei + ME, ME, degA);
    dinv_k<<<cdiv(PE, 256), 256>>>(degA, dinvA, PE);

    seg_starts_k<<<cdiv(NE + 1, 256), 256>>>(eb_batch, PE, NE, segPA);

    fill_int_k<<<cdiv(NE, 256), 256>>>(cntA, 0, NE);
    bucket_count_k<<<cdiv(ME, 256), 256>>>(eb_ei + ME, eb_batch, ME, cntA);
    {
        int nb = cdiv(NE, 1024);
        scan_block_k<<<nb, 1024>>>(cntA, NE, incl, bsum);
        scan_bsums_k<<<1, 1>>>(bsum, nb);
        scan_finalize_k<<<nb, 1024>>>(incl, bsum, NE, offA);
    }
    fill_int_k<<<cdiv(NE, 256), 256>>>(curA, 0, NE);
    bucket_scatter_k<<<cdiv(ME, 256), 256>>>(eb_ei, eb_ei + ME, eb_batch, eb_map,
                                             dinvA, offA, curA, ME, srtGA, srtWA);

    seg_fused_k<<<NE, 128>>>(nodeH, nodeV, nodeS, eb_map, dinvA, segPA, offA,
                             srtGA, srtWA, b1, edgeX, 256, poolA);
    {
        dim3 g(cdiv(128, 64), cdiv(NE, 64));
        sgemm64_k<<<g, 256>>>(poolA, Wo1, nullptr, edgeX + 128, NE, 128, 128, 256, 1);
    }

    // ===== stage B: edge -> node =====
    {
        dim3 g(cdiv(128, 64), cdiv(NE, 64));
        sgemm64_k<<<g, 256>>>(edgeX, W2,  nullptr, edgeH, NE, 128, 256, 128, 0);
        sgemm64_k<<<g, 256>>>(edgeX, Wv2, nullptr, edgeV, NE, 128, 256, 128, 0);
    }
    rowdot4_k<<<cdiv(NE * 32, 256), 256>>>(edgeX, WksB, edgeS, NE, 256);

    fill_int_k<<<cdiv(PN, 256), 256>>>(degB, 1, PN);
    deg_accum_k<<<cdiv(MN, 256), 256>>>(nb_ei + MN, MN, degB);
    dinv_k<<<cdiv(PN, 256), 256>>>(degB, dinvB, PN);

    seg_starts_k<<<cdiv(NN + 1, 256), 256>>>(nb_batch, PN, NN, segPB);

    fill_int_k<<<cdiv(NN, 256), 256>>>(cntB, 0, NN);
    bucket_count_k<<<cdiv(MN, 256), 256>>>(nb_ei + MN, nb_batch, MN, cntB);
    {
        int nb = cdiv(NN, 1024);
        scan_block_k<<<nb, 1024>>>(cntB, NN, incl, bsum);
        scan_bsums_k<<<1, 1>>>(bsum, nb);
        scan_finalize_k<<<nb, 1024>>>(incl, bsum, NN, offB);
    }
    fill_int_k<<<cdiv(NN, 256), 256>>>(curB, 0, NN);
    bucket_scatter_k<<<cdiv(MN, 256), 256>>>(nb_ei, nb_ei + MN, nb_batch, nb_map,
                                             dinvB, offB, curB, MN, srtGB, srtWB);

    seg_fused_k<<<NN, 128>>>(edgeH, edgeV, edgeS, nb_map, dinvB, segPB, offB,
                             srtGB, srtWB, b2, nodeO, 256, poolB);
    {
        dim3 g(cdiv(128, 64), cdiv(NN, 64));
        sgemm64_k<<<g, 256>>>(poolB, Wo2, nullptr, nodeO + 128, NN, 128, 128, 256, 1);
    }

    // ===== classifier =====
    {
        dim3 g(cdiv(40, 64), cdiv(NN, 64));
        sgemm64_k<<<g, 256>>>(nodeO, clsW, clsb, logit, NN, 40, 256, 40, 0);
    }
    log_softmax40_k<<<cdiv(NN * 32, 128), 128>>>(logit, out, NN);
}

// round 2
// speedup vs baseline: 1.2600x; 1.2600x over previous
#include <cuda_runtime.h>
#include <cstdint>
#include <cstddef>
#include <math_constants.h>

// ---------------- problem constants (match reference init) ----------------
#define NN 50000   // nodes
#define NE 25000   // hyperedges
#define PE 400000  // node->edge incidences
#define ME 800000  // conv edges, edge side
#define PN 400000  // edge->node incidences
#define MN 800000  // conv edges, node side

static __host__ __device__ constexpr size_t alup(size_t x) { return (x + 255) & ~size_t(255); }

// ---------------- scratch layout (one big __device__ buffer) ----------------
constexpr size_t O_NODEH = 0;
constexpr size_t O_NODEV = O_NODEH + alup((size_t)NN * 128 * 4);
constexpr size_t O_NODES = O_NODEV + alup((size_t)NN * 128 * 4);
constexpr size_t O_DEGA  = O_NODES + alup((size_t)NN * 4 * 4);
constexpr size_t O_DINVA = O_DEGA  + alup((size_t)PE * 4);
constexpr size_t O_SEGPA = O_DINVA + alup((size_t)PE * 4);
constexpr size_t O_CNTA  = O_SEGPA + alup((size_t)(NE + 1) * 4);
constexpr size_t O_OFFA  = O_CNTA  + alup((size_t)NE * 4);
constexpr size_t O_CURA  = O_OFFA  + alup((size_t)(NE + 1) * 4);
constexpr size_t O_SRTGA = O_CURA  + alup((size_t)NE * 4);
constexpr size_t O_SRTWA = O_SRTGA + alup((size_t)ME * 4);
constexpr size_t O_POOLA = O_SRTWA + alup((size_t)ME * 4);
constexpr size_t O_EDGEX = O_POOLA + alup((size_t)NE * 128 * 4);
constexpr size_t O_EDGEH = O_EDGEX + alup((size_t)NE * 256 * 4);
constexpr size_t O_EDGEV = O_EDGEH + alup((size_t)NE * 128 * 4);
constexpr size_t O_EDGES = O_EDGEV + alup((size_t)NE * 128 * 4);
constexpr size_t O_DEGB  = O_EDGES + alup((size_t)NE * 4 * 4);
constexpr size_t O_DINVB = O_DEGB  + alup((size_t)PN * 4);
constexpr size_t O_SEGPB = O_DINVB + alup((size_t)PN * 4);
constexpr size_t O_CNTB  = O_SEGPB + alup((size_t)(NN + 1) * 4);
constexpr size_t O_OFFB  = O_CNTB  + alup((size_t)NN * 4);
constexpr size_t O_CURB  = O_OFFB  + alup((size_t)(NN + 1) * 4);
constexpr size_t O_SRTGB = O_CURB  + alup((size_t)NN * 4);
constexpr size_t O_SRTWB = O_SRTGB + alup((size_t)MN * 4);
constexpr size_t O_POOLB = O_SRTWB + alup((size_t)MN * 4);
constexpr size_t O_NODEO = O_POOLB + alup((size_t)NN * 128 * 4);
constexpr size_t O_LOGIT = O_NODEO + alup((size_t)NN * 256 * 4);
constexpr size_t O_WKSA  = O_LOGIT + alup((size_t)NN * 40 * 4);
constexpr size_t O_WKSB  = O_WKSA  + alup((size_t)128 * 4 * 4);
constexpr size_t O_INCL  = O_WKSB  + alup((size_t)256 * 4 * 4);
constexpr size_t O_BSUM  = O_INCL  + alup((size_t)50176 * 4);
constexpr size_t SCRATCH_TOTAL = O_BSUM + alup((size_t)64 * 4);

__device__ __align__(256) unsigned char g_scratch[SCRATCH_TOTAL];

// ---------------- utility kernels ----------------
__global__ void fill_int_k(int* p, int v, int n) {
    int i = blockIdx.x * blockDim.x + threadIdx.x;
    if (i < n) p[i] = v;
}

// fold Wk [K,128] with seed [4,32] -> Wks [K,4], including 1/sqrt(32)
__global__ void fold_seed_k(const float* __restrict__ Wk, const float* __restrict__ seed,
                            float* __restrict__ Wks, int K) {
    int i = blockIdx.x * blockDim.x + threadIdx.x;
    if (i >= K * 4) return;
    int f = i >> 2, h = i & 3;
    float s = 0.f;
    #pragma unroll
    for (int d = 0; d < 32; d++) s += Wk[(size_t)f * 128 + h * 32 + d] * seed[h * 32 + d];
    Wks[i] = s * 0.17677669529663687f;  // 1/sqrt(32)
}

__global__ void deg_accum_k(const int* __restrict__ dst, int m, int* __restrict__ deg) {
    int i = blockIdx.x * blockDim.x + threadIdx.x;
    if (i < m) atomicAdd(&deg[dst[i]], 1);
}

__global__ void dinv_k(const int* __restrict__ deg, float* __restrict__ dinv, int n) {
    int i = blockIdx.x * blockDim.x + threadIdx.x;
    if (i < n) dinv[i] = rsqrtf((float)deg[i]);
}

// segP[s] = lower_bound(batch, s) for s in [0, S]
__global__ void seg_starts_k(const int* __restrict__ batch, int P, int S, int* __restrict__ segP) {
    int s = blockIdx.x * blockDim.x + threadIdx.x;
    if (s > S) return;
    int lo = 0, hi = P;
    while (lo < hi) {
        int mid = (lo + hi) >> 1;
        if (batch[mid] < s) lo = mid + 1; else hi = mid;
    }
    segP[s] = lo;
}

__global__ void bucket_count_k(const int* __restrict__ dst, const int* __restrict__ batch,
                               int m, int* __restrict__ cnt) {
    int i = blockIdx.x * blockDim.x + threadIdx.x;
    if (i < m) atomicAdd(&cnt[batch[dst[i]]], 1);
}

__global__ void bucket_scatter_k(const int* __restrict__ src, const int* __restrict__ dst,
                                 const int* __restrict__ batch, const int* __restrict__ map,
                                 const float* __restrict__ dinv, const int* __restrict__ off,
                                 int* __restrict__ cursor, int m,
                                 int* __restrict__ outG, float* __restrict__ outW) {
    int i = blockIdx.x * blockDim.x + threadIdx.x;
    if (i >= m) return;
    int d = dst[i];
    int s = batch[d];
    int pos = off[s] + atomicAdd(&cursor[s], 1);
    int sc = src[i];
    outG[pos] = map[sc];
    outW[pos] = dinv[sc] * dinv[d];
}

// ---------------- prefix scan (exclusive), up to 64*1024 elements ----------------
__global__ void scan_block_k(const int* __restrict__ cnt, int n,
                             int* __restrict__ incl, int* __restrict__ bsums) {
    __shared__ int sm[1024];
    int i = blockIdx.x * 1024 + threadIdx.x;
    int v = (i < n) ? cnt[i] : 0;
    sm[threadIdx.x] = v;
    __syncthreads();
    for (int o = 1; o < 1024; o <<= 1) {
        int t = (threadIdx.x >= o) ? sm[threadIdx.x - o] : 0;
        __syncthreads();
        sm[threadIdx.x] += t;
        __syncthreads();
    }
    if (i < n) incl[i] = sm[threadIdx.x];
    if (threadIdx.x == 1023) bsums[blockIdx.x] = sm[1023];
}

__global__ void scan_bsums_k(int* bsums, int nb) {
    if (threadIdx.x == 0 && blockIdx.x == 0) {
        int run = 0;
        for (int b = 0; b < nb; b++) { int t = bsums[b]; bsums[b] = run; run += t; }
    }
}

__global__ void scan_finalize_k(const int* __restrict__ incl, const int* __restrict__ bsums,
                                int n, int* __restrict__ off) {
    int i = blockIdx.x * 1024 + threadIdx.x;
    if (i < n) off[i + 1] = incl[i] + bsums[blockIdx.x];
    if (i == 0) off[0] = 0;
}

// ---------------- SGEMM 128x128 tile, 8x8 per thread, float4 fragments ----------------
// C[M,N] = act(A[M,K] @ B[K,N] + bias). Requires N <= gridDim.x*128, K % 8 == 0.
__global__ void __launch_bounds__(256, 2)
sgemm128_k(const float* __restrict__ A, const float* __restrict__ B,
           const float* __restrict__ bias, float* __restrict__ C,
           int M, int N, int K, int ldc, int doRelu) {
    __shared__ float As[8][128];
    __shared__ float Bs[8][128];
    int tid = threadIdx.x;
    int row0 = blockIdx.y * 128, col0 = blockIdx.x * 128;
    int tx = tid & 15, ty = tid >> 4;

    int arow = tid >> 1;
    int acol = (tid & 1) * 4;
    int brow = tid >> 5;
    int bcol = (tid & 31) * 4;

    float acc[8][8] = {};

    for (int k0 = 0; k0 < K; k0 += 8) {
        // A tile 128x8 -> As transposed
        float4 av = make_float4(0.f, 0.f, 0.f, 0.f);
        int gr = row0 + arow;
        if (gr < M) av = *(const float4*)&A[(size_t)gr * K + k0 + acol];
        As[acol + 0][arow] = av.x;
        As[acol + 1][arow] = av.y;
        As[acol + 2][arow] = av.z;
        As[acol + 3][arow] = av.w;
        // B tile 8x128
        float4 bv = make_float4(0.f, 0.f, 0.f, 0.f);
        int gc = col0 + bcol;
        if (gc + 3 < N) bv = *(const float4*)&B[(size_t)(k0 + brow) * N + gc];
        else {
            if (gc + 0 < N) bv.x = B[(size_t)(k0 + brow) * N + gc + 0];
            if (gc + 1 < N) bv.y = B[(size_t)(k0 + brow) * N + gc + 1];
            if (gc + 2 < N) bv.z = B[(size_t)(k0 + brow) * N + gc + 2];
        }
        *(float4*)&Bs[brow][bcol] = bv;
        __syncthreads();

        #pragma unroll
        for (int k = 0; k < 8; k++) {
            float4 a0 = *(const float4*)&As[k][ty * 4];
            float4 a1 = *(const float4*)&As[k][64 + ty * 4];
            float4 b0 = *(const float4*)&Bs[k][tx * 4];
            float4 b1 = *(const float4*)&Bs[k][64 + tx * 4];
            float ar[8] = {a0.x, a0.y, a0.z, a0.w, a1.x, a1.y, a1.z, a1.w};
            float br[8] = {b0.x, b0.y, b0.z, b0.w, b1.x, b1.y, b1.z, b1.w};
            #pragma unroll
            for (int i = 0; i < 8; i++)
                #pragma unroll
                for (int j = 0; j < 8; j++) acc[i][j] += ar[i] * br[j];
        }
        __syncthreads();
    }

    #pragma unroll
    for (int i = 0; i < 8; i++) {
        int gr = row0 + ((i < 4) ? (ty * 4 + i) : (64 + ty * 4 + i - 4));
        if (gr >= M) continue;
        #pragma unroll
        for (int j = 0; j < 8; j++) {
            int gc = col0 + ((j < 4) ? (tx * 4 + j) : (64 + tx * 4 + j - 4));
            if (gc >= N) continue;
            float v = acc[i][j];
            if (bias) v += bias[gc];
            if (doRelu) v = fmaxf(v, 0.f);
            C[(size_t)gr * ldc + gc] = v;
        }
    }
}

// ---------------- SGEMM 64x64 (kept for classifier N=40) ----------------
__global__ void sgemm64_k(const float* __restrict__ A, const float* __restrict__ B,
                          const float* __restrict__ bias, float* __restrict__ C,
                          int M, int N, int K, int ldc, int doRelu) {
    __shared__ float As[16][64 + 4];
    __shared__ float Bs[16][64 + 4];
    int tid = threadIdx.x;
    int row0 = blockIdx.y * 64, col0 = blockIdx.x * 64;
    int tx = tid & 15, ty = tid >> 4;
    float acc[4][4] = {};
    for (int k0 = 0; k0 < K; k0 += 16) {
        #pragma unroll
        for (int q = 0; q < 4; q++) {
            int idx = tid + q * 256;
            int r = idx >> 4, kk = idx & 15;
            int gr = row0 + r;
            As[kk][r] = (gr < M) ? A[(size_t)gr * K + k0 + kk] : 0.f;
        }
        #pragma unroll
        for (int q = 0; q < 4; q++) {
            int idx = tid + q * 256;
            int kk = idx >> 6, j = idx & 63;
            int gc = col0 + j;
            Bs[kk][j] = (gc < N) ? B[(size_t)(k0 + kk) * N + gc] : 0.f;
        }
        __syncthreads();
        #pragma unroll
        for (int kk = 0; kk < 16; kk++) {
            float a[4], b[4];
            #pragma unroll
            for (int i = 0; i < 4; i++) a[i] = As[kk][ty * 4 + i];
            #pragma unroll
            for (int j = 0; j < 4; j++) b[j] = Bs[kk][tx * 4 + j];
            #pragma unroll
            for (int i = 0; i < 4; i++)
                #pragma unroll
                for (int j = 0; j < 4; j++) acc[i][j] += a[i] * b[j];
        }
        __syncthreads();
    }
    #pragma unroll
    for (int i = 0; i < 4; i++) {
        int gr = row0 + ty * 4 + i;
        if (gr >= M) continue;
        #pragma unroll
        for (int j = 0; j < 4; j++) {
            int gc = col0 + tx * 4 + j;
            if (gc >= N) continue;
            float v = acc[i][j];
            if (bias) v += bias[gc];
            if (doRelu) v = fmaxf(v, 0.f);
            C[(size_t)gr * ldc + gc] = v;
        }
    }
}

// ---------------- small [M,4] = X[M,K] @ Wks[K,4], one warp per row, float4 ----------------
__global__ void rowdot4_k(const float* __restrict__ X, const float* __restrict__ Wks,
                          float* __restrict__ out, int M, int K) {
    int gw = (blockIdx.x * blockDim.x + threadIdx.x) >> 5;
    int lane = threadIdx.x & 31;
    if (gw >= M) return;
    const float* x = X + (size_t)gw * K;
    float a0 = 0, a1 = 0, a2 = 0, a3 = 0;
    for (int f0 = lane * 4; f0 < K; f0 += 128) {
        float4 xv = *(const float4*)&x[f0];
        float4 w0 = *(const float4*)&Wks[(size_t)(f0 + 0) * 4];
        float4 w1 = *(const float4*)&Wks[(size_t)(f0 + 1) * 4];
        float4 w2 = *(const float4*)&Wks[(size_t)(f0 + 2) * 4];
        float4 w3 = *(const float4*)&Wks[(size_t)(f0 + 3) * 4];
        a0 += xv.x * w0.x + xv.y * w1.x + xv.z * w2.x + xv.w * w3.x;
        a1 += xv.x * w0.y + xv.y * w1.y + xv.z * w2.y + xv.w * w3.y;
        a2 += xv.x * w0.z + xv.y * w1.z + xv.z * w2.z + xv.w * w3.z;
        a3 += xv.x * w0.w + xv.y * w1.w + xv.z * w2.w + xv.w * w3.w;
    }
    #pragma unroll
    for (int o = 16; o; o >>= 1) {
        a0 += __shfl_xor_sync(0xffffffffu, a0, o);
        a1 += __shfl_xor_sync(0xffffffffu, a1, o);
        a2 += __shfl_xor_sync(0xffffffffu, a2, o);
        a3 += __shfl_xor_sync(0xffffffffu, a3, o);
    }
    if (lane == 0) {
        float* o4 = out + (size_t)gw * 4;
        o4[0] = a0; o4[1] = a1; o4[2] = a2; o4[3] = a3;
    }
}

// ---------------- fused per-segment: GCN-conv mean + PMA softmax pool ----------------
// Warp per segment, lane handles 4 channels (float4). block = 256 threads = 8 segments.
__global__ void seg_fused_k(const float* __restrict__ H, const float* __restrict__ V,
                            const float* __restrict__ S4, const int* __restrict__ map,
                            const float* __restrict__ dinv,
                            const int* __restrict__ segP, const int* __restrict__ eOff,
                            const int* __restrict__ sG, const float* __restrict__ sW,
                            const float* __restrict__ bias,
                            float* __restrict__ outConv, int ldOut,
                            float* __restrict__ pooled, int S) {
    int w = (blockIdx.x * blockDim.x + threadIdx.x) >> 5;
    if (w >= S) return;
    int lane = threadIdx.x & 31;
    int h = lane >> 3;
    int s = w;
    const float4* H4 = (const float4*)H;
    const float4* V4 = (const float4*)V;

    int p0 = segP[s], p1 = segP[s + 1];
    int e0 = eOff[s], e1 = eOff[s + 1];

    // ---- conv edge gather (sorted by segment) ----
    float4 acc = make_float4(0.f, 0.f, 0.f, 0.f);
    int j = e0;
    for (; j + 3 < e1; j += 4) {
        int g0 = sG[j], g1 = sG[j + 1], g2 = sG[j + 2], g3 = sG[j + 3];
        float w0 = sW[j], w1 = sW[j + 1], w2 = sW[j + 2], w3 = sW[j + 3];
        float4 h0 = H4[(size_t)g0 * 32 + lane];
        float4 h1 = H4[(size_t)g1 * 32 + lane];
        float4 h2 = H4[(size_t)g2 * 32 + lane];
        float4 h3 = H4[(size_t)g3 * 32 + lane];
        acc.x += h0.x * w0 + h1.x * w1 + h2.x * w2 + h3.x * w3;
        acc.y += h0.y * w0 + h1.y * w1 + h2.y * w2 + h3.y * w3;
        acc.z += h0.z * w0 + h1.z * w1 + h2.z * w2 + h3.z * w3;
        acc.w += h0.w * w0 + h1.w * w1 + h2.w * w2 + h3.w * w3;
    }
    for (; j < e1; j++) {
        int g = sG[j]; float wt = sW[j];
        float4 hv = H4[(size_t)g * 32 + lane];
        acc.x += hv.x * wt; acc.y += hv.y * wt; acc.z += hv.z * wt; acc.w += hv.w * wt;
    }

    // ---- PMA pass 1: segment max + exp-sum of scores (per-head, lane-redundant) ----
    float m = -CUDART_INF_F;
    for (int p = p0; p < p1; p++)
        m = fmaxf(m, S4[(size_t)map[p] * 4 + h]);
    float den = 0.f;
    for (int p = p0; p < p1; p++)
        den += __expf(S4[(size_t)map[p] * 4 + h] - m);

    // ---- combined pass: self-loop conv terms + weighted V sum ----
    float4 pv = make_float4(0.f, 0.f, 0.f, 0.f);
    int p = p0;
    for (; p + 1 < p1; p += 2) {
        int ga = map[p], gb = map[p + 1];
        float da = dinv[p], db = dinv[p + 1];
        float wa = da * da, wb = db * db;
        float ea = __expf(S4[(size_t)ga * 4 + h] - m);
        float eb = __expf(S4[(size_t)gb * 4 + h] - m);
        float4 ha = H4[(size_t)ga * 32 + lane];
        float4 hb = H4[(size_t)gb * 32 + lane];
        float4 va = V4[(size_t)ga * 32 + lane];
        float4 vb = V4[(size_t)gb * 32 + lane];
        acc.x += ha.x * wa + hb.x * wb;  pv.x += va.x * ea + vb.x * eb;
        acc.y += ha.y * wa + hb.y * wb;  pv.y += va.y * ea + vb.y * eb;
        acc.z += ha.z * wa + hb.z * wb;  pv.z += va.z * ea + vb.z * eb;
        acc.w += ha.w * wa + hb.w * wb;  pv.w += va.w * ea + vb.w * eb;
    }
    for (; p < p1; p++) {
        int g = map[p];
        float d = dinv[p];
        float wt = d * d;
        float e = __expf(S4[(size_t)g * 4 + h] - m);
        float4 hv = H4[(size_t)g * 32 + lane];
        float4 vv = V4[(size_t)g * 32 + lane];
        acc.x += hv.x * wt;  pv.x += vv.x * e;
        acc.y += hv.y * wt;  pv.y += vv.y * e;
        acc.z += hv.z * wt;  pv.z += vv.z * e;
        acc.w += hv.w * wt;  pv.w += vv.w * e;
    }

    int cnt = p1 - p0;
    float4 ob;
    if (cnt > 0) {
        float inv = 1.f / (float)cnt;
        float4 b4 = *(const float4*)&bias[lane * 4];
        ob.x = fmaxf(acc.x * inv + b4.x, 0.f);
        ob.y = fmaxf(acc.y * inv + b4.y, 0.f);
        ob.z = fmaxf(acc.z * inv + b4.z, 0.f);
        ob.w = fmaxf(acc.w * inv + b4.w, 0.f);
    } else {
        ob = make_float4(0.f, 0.f, 0.f, 0.f);
    }
    *(float4*)&outConv[(size_t)s * ldOut + lane * 4] = ob;

    float dn = 1.f / fmaxf(den, 1e-9f);
    float4 op;
    op.x = pv.x * dn; op.y = pv.y * dn; op.z = pv.z * dn; op.w = pv.w * dn;
    if (cnt == 0) op = make_float4(0.f, 0.f, 0.f, 0.f);
    *(float4*)&pooled[(size_t)s * 128 + lane * 4] = op;
}

// ---------------- log_softmax over 40 classes, one warp per row ----------------
__global__ void log_softmax40_k(const float* __restrict__ logits, float* __restrict__ out, int M) {
    int gw = (blockIdx.x * blockDim.x + threadIdx.x) >> 5;
    int lane = threadIdx.x & 31;
    if (gw >= M) return;
    const float* row = logits + (size_t)gw * 40;
    float v0 = row[lane];
    float v1 = (lane < 8) ? row[32 + lane] : -CUDART_INF_F;
    float m = fmaxf(v0, v1);
    #pragma unroll
    for (int o = 16; o; o >>= 1) m = fmaxf(m, __shfl_xor_sync(0xffffffffu, m, o));
    float e = __expf(v0 - m) + ((lane < 8) ? __expf(v1 - m) : 0.f);
    #pragma unroll
    for (int o = 16; o; o >>= 1) e += __shfl_xor_sync(0xffffffffu, e, o);
    float lse = m + logf(e);
    float* orow = out + (size_t)gw * 40;
    orow[lane] = v0 - lse;
    if (lane < 8) orow[32 + lane] = v1 - lse;
}

// ---------------- orchestration ----------------
static inline int cdiv(int a, int b) { return (a + b - 1) / b; }

extern "C" void kernel_launch(void* const* d_in, const int* in_sizes, int n_in,
                              void* d_out, int out_size) {
    (void)in_sizes; (void)n_in; (void)out_size;
    const float* node_x  = (const float*)d_in[0];
    const int* eb_map    = (const int*)d_in[1];
    const int* eb_ei     = (const int*)d_in[2];  // [0,ME)=src, [ME,2ME)=dst
    const int* eb_batch  = (const int*)d_in[3];
    const int* nb_map    = (const int*)d_in[4];
    const int* nb_ei     = (const int*)d_in[5];
    const int* nb_batch  = (const int*)d_in[6];
    const float* W1   = (const float*)d_in[7];
    const float* b1   = (const float*)d_in[8];
    const float* Wk1  = (const float*)d_in[9];
    const float* Wv1  = (const float*)d_in[10];
    const float* sd1  = (const float*)d_in[11];
    const float* Wo1  = (const float*)d_in[12];
    const float* W2   = (const float*)d_in[13];
    const float* b2   = (const float*)d_in[14];
    const float* Wk2  = (const float*)d_in[15];
    const float* Wv2  = (const float*)d_in[16];
    const float* sd2  = (const float*)d_in[17];
    const float* Wo2  = (const float*)d_in[18];
    const float* clsW = (const float*)d_in[19];
    const float* clsb = (const float*)d_in[20];
    float* out = (float*)d_out;

    void* basep = nullptr;
    cudaGetSymbolAddress(&basep, g_scratch);
    char* base = (char*)basep;
    float* nodeH  = (float*)(base + O_NODEH);
    float* nodeV  = (float*)(base + O_NODEV);
    float* nodeS  = (float*)(base + O_NODES);
    int*   degA   = (int*)  (base + O_DEGA);
    float* dinvA  = (float*)(base + O_DINVA);
    int*   segPA  = (int*)  (base + O_SEGPA);
    int*   cntA   = (int*)  (base + O_CNTA);
    int*   offA   = (int*)  (base + O_OFFA);
    int*   curA   = (int*)  (base + O_CURA);
    int*   srtGA  = (int*)  (base + O_SRTGA);
    float* srtWA  = (float*)(base + O_SRTWA);
    float* poolA  = (float*)(base + O_POOLA);
    float* edgeX  = (float*)(base + O_EDGEX);
    float* edgeH  = (float*)(base + O_EDGEH);
    float* edgeV  = (float*)(base + O_EDGEV);
    float* edgeS  = (float*)(base + O_EDGES);
    int*   degB   = (int*)  (base + O_DEGB);
    float* dinvB  = (float*)(base + O_DINVB);
    int*   segPB  = (int*)  (base + O_SEGPB);
    int*   cntB   = (int*)  (base + O_CNTB);
    int*   offB   = (int*)  (base + O_OFFB);
    int*   curB   = (int*)  (base + O_CURB);
    int*   srtGB  = (int*)  (base + O_SRTGB);
    float* srtWB  = (float*)(base + O_SRTWB);
    float* poolB  = (float*)(base + O_POOLB);
    float* nodeO  = (float*)(base + O_NODEO);
    float* logit  = (float*)(base + O_LOGIT);
    float* WksA   = (float*)(base + O_WKSA);
    float* WksB   = (float*)(base + O_WKSB);
    int*   incl   = (int*)  (base + O_INCL);
    int*   bsum   = (int*)  (base + O_BSUM);

    // fold Wk with seed
    fold_seed_k<<<1, 512>>>(Wk1, sd1, WksA, 128);
    fold_seed_k<<<1, 1024>>>(Wk2, sd2, WksB, 256);

    // ===== stage A: node -> edge =====
    {
        dim3 g(1, cdiv(NN, 128));
        sgemm128_k<<<g, 256>>>(node_x, W1,  nullptr, nodeH, NN, 128, 128, 128, 0);
        sgemm128_k<<<g, 256>>>(node_x, Wv1, nullptr, nodeV, NN, 128, 128, 128, 0);
    }
    rowdot4_k<<<cdiv(NN * 32, 256), 256>>>(node_x, WksA, nodeS, NN, 128);

    fill_int_k<<<cdiv(PE, 256), 256>>>(degA, 1, PE);  // self-loop
    deg_accum_k<<<cdiv(ME, 256), 256>>>(eb_ei + ME, ME, degA);
    dinv_k<<<cdiv(PE, 256), 256>>>(degA, dinvA, PE);

    seg_starts_k<<<cdiv(NE + 1, 256), 256>>>(eb_batch, PE, NE, segPA);

    fill_int_k<<<cdiv(NE, 256), 256>>>(cntA, 0, NE);
    bucket_count_k<<<cdiv(ME, 256), 256>>>(eb_ei + ME, eb_batch, ME, cntA);
    {
        int nb = cdiv(NE, 1024);
        scan_block_k<<<nb, 1024>>>(cntA, NE, incl, bsum);
        scan_bsums_k<<<1, 1>>>(bsum, nb);
        scan_finalize_k<<<nb, 1024>>>(incl, bsum, NE, offA);
    }
    fill_int_k<<<cdiv(NE, 256), 256>>>(curA, 0, NE);
    bucket_scatter_k<<<cdiv(ME, 256), 256>>>(eb_ei, eb_ei + ME, eb_batch, eb_map,
                                             dinvA, offA, curA, ME, srtGA, srtWA);

    seg_fused_k<<<cdiv(NE * 32, 256), 256>>>(nodeH, nodeV, nodeS, eb_map, dinvA, segPA, offA,
                                             srtGA, srtWA, b1, edgeX, 256, poolA, NE);
    {
        dim3 g(1, cdiv(NE, 128));
        sgemm128_k<<<g, 256>>>(poolA, Wo1, nullptr, edgeX + 128, NE, 128, 128, 256, 1);
    }

    // ===== stage B: edge -> node =====
    {
        dim3 g(1, cdiv(NE, 128));
        sgemm128_k<<<g, 256>>>(edgeX, W2,  nullptr, edgeH, NE, 128, 256, 128, 0);
        sgemm128_k<<<g, 256>>>(edgeX, Wv2, nullptr, edgeV, NE, 128, 256, 128, 0);
    }
    rowdot4_k<<<cdiv(NE * 32, 256), 256>>>(edgeX, WksB, edgeS, NE, 256);

    fill_int_k<<<cdiv(PN, 256), 256>>>(degB, 1, PN);
    deg_accum_k<<<cdiv(MN, 256), 256>>>(nb_ei + MN, MN, degB);
    dinv_k<<<cdiv(PN, 256), 256>>>(degB, dinvB, PN);

    seg_starts_k<<<cdiv(NN + 1, 256), 256>>>(nb_batch, PN, NN, segPB);

    fill_int_k<<<cdiv(NN, 256), 256>>>(cntB, 0, NN);
    bucket_count_k<<<cdiv(MN, 256), 256>>>(nb_ei + MN, nb_batch, MN, cntB);
    {
        int nb = cdiv(NN, 1024);
        scan_block_k<<<nb, 1024>>>(cntB, NN, incl, bsum);
        scan_bsums_k<<<1, 1>>>(bsum, nb);
        scan_finalize_k<<<nb, 1024>>>(incl, bsum, NN, offB);
    }
    fill_int_k<<<cdiv(NN, 256), 256>>>(curB, 0, NN);
    bucket_scatter_k<<<cdiv(MN, 256), 256>>>(nb_ei, nb_ei + MN, nb_batch, nb_map,
                                             dinvB, offB, curB, MN, srtGB, srtWB);

    seg_fused_k<<<cdiv(NN * 32, 256), 256>>>(edgeH, edgeV, edgeS, nb_map, dinvB, segPB, offB,
                                             srtGB, srtWB, b2, nodeO, 256, poolB, NN);
    {
        dim3 g(1, cdiv(NN, 128));
        sgemm128_k<<<g, 256>>>(poolB, Wo2, nullptr, nodeO + 128, NN, 128, 128, 256, 1);
    }

    // ===== classifier =====
    {
        dim3 g(cdiv(40, 64), cdiv(NN, 64));
        sgemm64_k<<<g, 256>>>(nodeO, clsW, clsb, logit, NN, 40, 256, 40, 0);
    }
    log_softmax40_k<<<cdiv(NN * 32, 128), 128>>>(logit, out, NN);
}

// round 4
// speedup vs baseline: 1.5582x; 1.2367x over previous
#include <cuda_runtime.h>
#include <cuda_bf16.h>
#include <mma.h>
#include <cstdint>
#include <cstddef>
#include <math_constants.h>

using namespace nvcuda;

// ---------------- problem constants ----------------
#define NN 50000
#define NE 25000
#define PE 400000
#define ME 800000
#define PN 400000
#define MN 800000

static __host__ __device__ constexpr size_t alup(size_t x) { return (x + 255) & ~size_t(255); }

// ---------------- scratch layout ----------------
constexpr size_t O_NODEH = 0;
constexpr size_t O_NODEV = O_NODEH + alup((size_t)NN * 128 * 4);
constexpr size_t O_NODES = O_NODEV + alup((size_t)NN * 128 * 4);
constexpr size_t O_DEGA  = O_NODES + alup((size_t)NN * 4 * 4);
constexpr size_t O_DINVA = O_DEGA  + alup((size_t)PE * 4);
constexpr size_t O_SEGPA = O_DINVA + alup((size_t)PE * 4);
constexpr size_t O_CNTA  = O_SEGPA + alup((size_t)(NE + 1) * 4);
constexpr size_t O_OFFA  = O_CNTA  + alup((size_t)NE * 4);
constexpr size_t O_CURA  = O_OFFA  + alup((size_t)(NE + 1) * 4);
constexpr size_t O_SRTGA = O_CURA  + alup((size_t)NE * 4);
constexpr size_t O_SRTWA = O_SRTGA + alup((size_t)ME * 4);
constexpr size_t O_POOLA = O_SRTWA + alup((size_t)ME * 4);
constexpr size_t O_EDGEX = O_POOLA + alup((size_t)NE * 128 * 4);
constexpr size_t O_EDGEH = O_EDGEX + alup((size_t)NE * 256 * 4);
constexpr size_t O_EDGEV = O_EDGEH + alup((size_t)NE * 128 * 4);
constexpr size_t O_EDGES = O_EDGEV + alup((size_t)NE * 128 * 4);
constexpr size_t O_DEGB  = O_EDGES + alup((size_t)NE * 4 * 4);
constexpr size_t O_DINVB = O_DEGB  + alup((size_t)PN * 4);
constexpr size_t O_SEGPB = O_DINVB + alup((size_t)PN * 4);
constexpr size_t O_CNTB  = O_SEGPB + alup((size_t)(NN + 1) * 4);
constexpr size_t O_OFFB  = O_CNTB  + alup((size_t)NN * 4);
constexpr size_t O_CURB  = O_OFFB  + alup((size_t)(NN + 1) * 4);
constexpr size_t O_SRTGB = O_CURB  + alup((size_t)NN * 4);
constexpr size_t O_SRTWB = O_SRTGB + alup((size_t)MN * 4);
constexpr size_t O_POOLB = O_SRTWB + alup((size_t)MN * 4);
constexpr size_t O_NODEO = O_POOLB + alup((size_t)NN * 128 * 4);
constexpr size_t O_WKSA  = O_NODEO + alup((size_t)NN * 256 * 4);
constexpr size_t O_WKSB  = O_WKSA  + alup((size_t)128 * 4 * 4);
constexpr size_t O_INCL  = O_WKSB  + alup((size_t)256 * 4 * 4);
constexpr size_t O_BSUM  = O_INCL  + alup((size_t)50176 * 4);
constexpr size_t O_WAH   = O_BSUM  + alup((size_t)64 * 4);
constexpr size_t O_WAL   = O_WAH   + alup((size_t)256 * 128 * 2);
constexpr size_t O_WO1H  = O_WAL   + alup((size_t)256 * 128 * 2);
constexpr size_t O_WO1L  = O_WO1H  + alup((size_t)128 * 128 * 2);
constexpr size_t O_WBH   = O_WO1L  + alup((size_t)128 * 128 * 2);
constexpr size_t O_WBL   = O_WBH   + alup((size_t)256 * 256 * 2);
constexpr size_t O_WO2H  = O_WBL   + alup((size_t)256 * 256 * 2);
constexpr size_t O_WO2L  = O_WO2H  + alup((size_t)128 * 128 * 2);
constexpr size_t O_WCH   = O_WO2L  + alup((size_t)128 * 128 * 2);
constexpr size_t O_WCL   = O_WCH   + alup((size_t)64 * 256 * 2);
constexpr size_t SCRATCH_TOTAL = O_WCL + alup((size_t)64 * 256 * 2);

__device__ __align__(256) unsigned char g_scratch[SCRATCH_TOTAL];

// ---------------- weight prep: W[K,N] fp32 -> hi/lo bf16 transposed [n_off+N, ldK] ----------------
__global__ void prep_w_k(const float* __restrict__ W, int K, int N,
                         __nv_bfloat16* __restrict__ hi, __nv_bfloat16* __restrict__ lo,
                         int n_off, int ldK) {
    int i = blockIdx.x * blockDim.x + threadIdx.x;
    if (i >= K * N) return;
    int k = i / N, n = i % N;
    float v = W[i];
    __nv_bfloat16 h = __float2bfloat16(v);
    float r = v - __bfloat162float(h);
    hi[(size_t)(n_off + n) * ldK + k] = h;
    lo[(size_t)(n_off + n) * ldK + k] = __float2bfloat16(r);
}

// ---------------- WMMA bf16 GEMM (hi/lo 3-term split, fp32 accum) ----------------
// C[M, NT*gridDim.y] = A[M, K] @ Bt^T, Bt = [ncols, K] row-major (pre-transposed).
// Block: 256 thr, 128 x NT tile; warps 4x2; warp tile 32 x NT/2.
// MODE 0: cols<128 -> out0[128], else out1[128].  MODE 1: relu -> out0 (ldc).
// MODE 2: bias + log-softmax over first 40 cols -> out0[M,40] (NT=64).
template<int KC, int NT, int MODE>
__global__ void __launch_bounds__(256, 2)
wgemm_k(const float* __restrict__ A, int M,
        const __nv_bfloat16* __restrict__ Bhi, const __nv_bfloat16* __restrict__ Blo,
        const float* __restrict__ bias,
        float* __restrict__ out0, float* __restrict__ out1, int ldc) {
    constexpr int K = KC * 16;
    constexpr int WN = NT / 2;      // warp n extent
    constexpr int NTI = WN / 16;    // wmma n tiles per warp
    constexpr int NTS = NT + 4;     // padded staging stride (floats)

    extern __shared__ char smc[];
    __nv_bfloat16* sAh = (__nv_bfloat16*)smc;
    __nv_bfloat16* sAl = sAh + 128 * 24;
    __nv_bfloat16* sBh = sAl + 128 * 24;
    __nv_bfloat16* sBl = sBh + NT * 24;
    float* stg = (float*)smc;       // reused after k-loop

    int tid = threadIdx.x;
    int wid = tid >> 5;
    int wm = wid >> 1, wn = wid & 1;
    int row0 = blockIdx.x * 128;
    int col0 = blockIdx.y * NT;

    wmma::fragment<wmma::accumulator, 16, 16, 16, float> acc[2][NTI];
    #pragma unroll
    for (int m = 0; m < 2; m++)
        #pragma unroll
        for (int n = 0; n < NTI; n++) wmma::fill_fragment(acc[m][n], 0.0f);

    for (int kc = 0; kc < KC; kc++) {
        int k0 = kc * 16;
        // A chunk: 128x16 fp32 -> hi/lo bf16 smem (each thread: 8 values)
        {
            int r = tid >> 1, kk = (tid & 1) * 8;
            int gr = row0 + r;
            float4 v0 = make_float4(0.f, 0.f, 0.f, 0.f), v1 = v0;
            if (gr < M) {
                const float* ap = A + (size_t)gr * K + k0 + kk;
                v0 = *(const float4*)ap;
                v1 = *(const float4*)(ap + 4);
            }
            float vv[8] = {v0.x, v0.y, v0.z, v0.w, v1.x, v1.y, v1.z, v1.w};
            ushort hs[8], ls[8];
            #pragma unroll
            for (int q = 0; q < 8; q++) {
                __nv_bfloat16 h = __float2bfloat16(vv[q]);
                hs[q] = __bfloat16_as_ushort(h);
                ls[q] = __bfloat16_as_ushort(__float2bfloat16(vv[q] - __bfloat162float(h)));
            }
            uint4 hp, lp;
            hp.x = hs[0] | ((uint32_t)hs[1] << 16); hp.y = hs[2] | ((uint32_t)hs[3] << 16);
            hp.z = hs[4] | ((uint32_t)hs[5] << 16); hp.w = hs[6] | ((uint32_t)hs[7] << 16);
            lp.x = ls[0] | ((uint32_t)ls[1] << 16); lp.y = ls[2] | ((uint32_t)ls[3] << 16);
            lp.z = ls[4] | ((uint32_t)ls[5] << 16); lp.w = ls[6] | ((uint32_t)ls[7] << 16);
            *(uint4*)&sAh[r * 24 + kk] = hp;
            *(uint4*)&sAl[r * 24 + kk] = lp;
        }
        // B chunk: NT x 16 bf16 hi/lo from global (row-major [n, K])
        for (int i = tid; i < NT * 2; i += 256) {
            int n = i >> 1, kk = (i & 1) * 8;
            size_t g = (size_t)(col0 + n) * K + k0 + kk;
            *(uint4*)&sBh[n * 24 + kk] = *(const uint4*)(Bhi + g);
            *(uint4*)&sBl[n * 24 + kk] = *(const uint4*)(Blo + g);
        }
        __syncthreads();

        wmma::fragment<wmma::matrix_a, 16, 16, 16, __nv_bfloat16, wmma::row_major> ah[2], al[2];
        #pragma unroll
        for (int m = 0; m < 2; m++) {
            wmma::load_matrix_sync(ah[m], sAh + (wm * 32 + m * 16) * 24, 24);
            wmma::load_matrix_sync(al[m], sAl + (wm * 32 + m * 16) * 24, 24);
        }
        #pragma unroll
        for (int n = 0; n < NTI; n++) {
            wmma::fragment<wmma::matrix_b, 16, 16, 16, __nv_bfloat16, wmma::col_major> bh, bl;
            wmma::load_matrix_sync(bh, sBh + (wn * WN + n * 16) * 24, 24);
            wmma::load_matrix_sync(bl, sBl + (wn * WN + n * 16) * 24, 24);
            #pragma unroll
            for (int m = 0; m < 2; m++) {
                wmma::mma_sync(acc[m][n], ah[m], bh, acc[m][n]);
                wmma::mma_sync(acc[m][n], ah[m], bl, acc[m][n]);
                wmma::mma_sync(acc[m][n], al[m], bh, acc[m][n]);
            }
        }
        __syncthreads();
    }

    // stage accumulators to padded smem
    #pragma unroll
    for (int m = 0; m < 2; m++)
        #pragma unroll
        for (int n = 0; n < NTI; n++)
            wmma::store_matrix_sync(stg + (wm * 32 + m * 16) * NTS + wn * WN + n * 16,
                                    acc[m][n], NTS, wmma::mem_row_major);
    __syncthreads();

    if (MODE == 2) {
        if (tid < 128) {
            int gr = row0 + tid;
            if (gr < M) {
                const float* row = stg + tid * NTS;
                float v[40];
                float mx = -CUDART_INF_F;
                #pragma unroll
                for (int c = 0; c < 40; c++) { v[c] = row[c] + bias[c]; mx = fmaxf(mx, v[c]); }
                float s = 0.f;
                #pragma unroll
                for (int c = 0; c < 40; c++) s += expf(v[c] - mx);
                float lse = mx + logf(s);
                #pragma unroll
                for (int c = 0; c < 40; c += 4) {
                    float4 f = make_float4(v[c] - lse, v[c+1] - lse, v[c+2] - lse, v[c+3] - lse);
                    *(float4*)&out0[(size_t)gr * 40 + c] = f;
                }
            }
        }
    } else {
        for (int idx = tid; idx < 128 * (NT / 4); idx += 256) {
            int r = idx / (NT / 4), c4 = (idx % (NT / 4)) * 4;
            int gr = row0 + r;
            if (gr >= M) continue;
            float4 f = *(const float4*)&stg[r * NTS + c4];
            if (MODE == 1) {
                f.x = fmaxf(f.x, 0.f); f.y = fmaxf(f.y, 0.f);
                f.z = fmaxf(f.z, 0.f); f.w = fmaxf(f.w, 0.f);
                *(float4*)&out0[(size_t)gr * ldc + col0 + c4] = f;
            } else {
                int gc = col0 + c4;
                if (gc < 128) *(float4*)&out0[(size_t)gr * 128 + gc] = f;
                else          *(float4*)&out1[(size_t)gr * 128 + gc - 128] = f;
            }
        }
    }
}

// ---------------- utility kernels ----------------
__global__ void fill_int_k(int* p, int v, int n) {
    int i = blockIdx.x * blockDim.x + threadIdx.x;
    if (i < n) p[i] = v;
}

__global__ void fold_seed_k(const float* __restrict__ Wk, const float* __restrict__ seed,
                            float* __restrict__ Wks, int K) {
    int i = blockIdx.x * blockDim.x + threadIdx.x;
    if (i >= K * 4) return;
    int f = i >> 2, h = i & 3;
    float s = 0.f;
    #pragma unroll
    for (int d = 0; d < 32; d++) s += Wk[(size_t)f * 128 + h * 32 + d] * seed[h * 32 + d];
    Wks[i] = s * 0.17677669529663687f;
}

__global__ void deg_accum_k(const int* __restrict__ dst, int m, int* __restrict__ deg) {
    int i = blockIdx.x * blockDim.x + threadIdx.x;
    if (i < m) atomicAdd(&deg[dst[i]], 1);
}

__global__ void dinv_k(const int* __restrict__ deg, float* __restrict__ dinv, int n) {
    int i = blockIdx.x * blockDim.x + threadIdx.x;
    if (i < n) dinv[i] = rsqrtf((float)deg[i]);
}

__global__ void seg_starts_k(const int* __restrict__ batch, int P, int S, int* __restrict__ segP) {
    int s = blockIdx.x * blockDim.x + threadIdx.x;
    if (s > S) return;
    int lo = 0, hi = P;
    while (lo < hi) {
        int mid = (lo + hi) >> 1;
        if (batch[mid] < s) lo = mid + 1; else hi = mid;
    }
    segP[s] = lo;
}

__global__ void bucket_count_k(const int* __restrict__ dst, const int* __restrict__ batch,
                               int m, int* __restrict__ cnt) {
    int i = blockIdx.x * blockDim.x + threadIdx.x;
    if (i < m) atomicAdd(&cnt[batch[dst[i]]], 1);
}

__global__ void bucket_scatter_k(const int* __restrict__ src, const int* __restrict__ dst,
                                 const int* __restrict__ batch, const int* __restrict__ map,
                                 const float* __restrict__ dinv, const int* __restrict__ off,
                                 int* __restrict__ cursor, int m,
                                 int* __restrict__ outG, float* __restrict__ outW) {
    int i = blockIdx.x * blockDim.x + threadIdx.x;
    if (i >= m) return;
    int d = dst[i];
    int s = batch[d];
    int pos = off[s] + atomicAdd(&cursor[s], 1);
    int sc = src[i];
    outG[pos] = map[sc];
    outW[pos] = dinv[sc] * dinv[d];
}

__global__ void scan_block_k(const int* __restrict__ cnt, int n,
                             int* __restrict__ incl, int* __restrict__ bsums) {
    __shared__ int sm[1024];
    int i = blockIdx.x * 1024 + threadIdx.x;
    int v = (i < n) ? cnt[i] : 0;
    sm[threadIdx.x] = v;
    __syncthreads();
    for (int o = 1; o < 1024; o <<= 1) {
        int t = (threadIdx.x >= o) ? sm[threadIdx.x - o] : 0;
        __syncthreads();
        sm[threadIdx.x] += t;
        __syncthreads();
    }
    if (i < n) incl[i] = sm[threadIdx.x];
    if (threadIdx.x == 1023) bsums[blockIdx.x] = sm[1023];
}

__global__ void scan_bsums_k(int* bsums, int nb) {
    if (threadIdx.x == 0 && blockIdx.x == 0) {
        int run = 0;
        for (int b = 0; b < nb; b++) { int t = bsums[b]; bsums[b] = run; run += t; }
    }
}

__global__ void scan_finalize_k(const int* __restrict__ incl, const int* __restrict__ bsums,
                                int n, int* __restrict__ off) {
    int i = blockIdx.x * 1024 + threadIdx.x;
    if (i < n) off[i + 1] = incl[i] + bsums[blockIdx.x];
    if (i == 0) off[0] = 0;
}

__global__ void rowdot4_k(const float* __restrict__ X, const float* __restrict__ Wks,
                          float* __restrict__ out, int M, int K) {
    int gw = (blockIdx.x * blockDim.x + threadIdx.x) >> 5;
    int lane = threadIdx.x & 31;
    if (gw >= M) return;
    const float* x = X + (size_t)gw * K;
    float a0 = 0, a1 = 0, a2 = 0, a3 = 0;
    for (int f0 = lane * 4; f0 < K; f0 += 128) {
        float4 xv = *(const float4*)&x[f0];
        float4 w0 = *(const float4*)&Wks[(size_t)(f0 + 0) * 4];
        float4 w1 = *(const float4*)&Wks[(size_t)(f0 + 1) * 4];
        float4 w2 = *(const float4*)&Wks[(size_t)(f0 + 2) * 4];
        float4 w3 = *(const float4*)&Wks[(size_t)(f0 + 3) * 4];
        a0 += xv.x * w0.x + xv.y * w1.x + xv.z * w2.x + xv.w * w3.x;
        a1 += xv.x * w0.y + xv.y * w1.y + xv.z * w2.y + xv.w * w3.y;
        a2 += xv.x * w0.z + xv.y * w1.z + xv.z * w2.z + xv.w * w3.z;
        a3 += xv.x * w0.w + xv.y * w1.w + xv.z * w2.w + xv.w * w3.w;
    }
    #pragma unroll
    for (int o = 16; o; o >>= 1) {
        a0 += __shfl_xor_sync(0xffffffffu, a0, o);
        a1 += __shfl_xor_sync(0xffffffffu, a1, o);
        a2 += __shfl_xor_sync(0xffffffffu, a2, o);
        a3 += __shfl_xor_sync(0xffffffffu, a3, o);
    }
    if (lane == 0) {
        float* o4 = out + (size_t)gw * 4;
        o4[0] = a0; o4[1] = a1; o4[2] = a2; o4[3] = a3;
    }
}

// ---------------- fused per-segment: GCN-conv mean + PMA softmax pool ----------------
// Warp per segment; max pass then single combined pass (self-loop + den + V).
__global__ void seg_fused_k(const float* __restrict__ H, const float* __restrict__ V,
                            const float* __restrict__ S4, const int* __restrict__ map,
                            const float* __restrict__ dinv,
                            const int* __restrict__ segP, const int* __restrict__ eOff,
                            const int* __restrict__ sG, const float* __restrict__ sW,
                            const float* __restrict__ bias,
                            float* __restrict__ outConv, int ldOut,
                            float* __restrict__ pooled, int S) {
    int w = (blockIdx.x * blockDim.x + threadIdx.x) >> 5;
    if (w >= S) return;
    int lane = threadIdx.x & 31;
    int h = lane >> 3;
    int s = w;
    const float4* H4 = (const float4*)H;
    const float4* V4 = (const float4*)V;

    int p0 = segP[s], p1 = segP[s + 1];
    int e0 = eOff[s], e1 = eOff[s + 1];

    float4 acc = make_float4(0.f, 0.f, 0.f, 0.f);
    int j = e0;
    for (; j + 3 < e1; j += 4) {
        int g0 = sG[j], g1 = sG[j + 1], g2 = sG[j + 2], g3 = sG[j + 3];
        float w0 = sW[j], w1 = sW[j + 1], w2 = sW[j + 2], w3 = sW[j + 3];
        float4 h0 = H4[(size_t)g0 * 32 + lane];
        float4 h1 = H4[(size_t)g1 * 32 + lane];
        float4 h2 = H4[(size_t)g2 * 32 + lane];
        float4 h3 = H4[(size_t)g3 * 32 + lane];
        acc.x += h0.x * w0 + h1.x * w1 + h2.x * w2 + h3.x * w3;
        acc.y += h0.y * w0 + h1.y * w1 + h2.y * w2 + h3.y * w3;
        acc.z += h0.z * w0 + h1.z * w1 + h2.z * w2 + h3.z * w3;
        acc.w += h0.w * w0 + h1.w * w1 + h2.w * w2 + h3.w * w3;
    }
    for (; j < e1; j++) {
        int g = sG[j]; float wt = sW[j];
        float4 hv = H4[(size_t)g * 32 + lane];
        acc.x += hv.x * wt; acc.y += hv.y * wt; acc.z += hv.z * wt; acc.w += hv.w * wt;
    }

    // pass 1: per-head segment max
    float m = -CUDART_INF_F;
    for (int p = p0; p < p1; p++)
        m = fmaxf(m, S4[(size_t)map[p] * 4 + h]);

    // pass 2 (combined): self-loop conv + exp-sum + weighted V
    float den = 0.f;
    float4 pv = make_float4(0.f, 0.f, 0.f, 0.f);
    int p = p0;
    for (; p + 1 < p1; p += 2) {
        int ga = map[p], gb = map[p + 1];
        float da = dinv[p], db = dinv[p + 1];
        float wa = da * da, wb = db * db;
        float ea = __expf(S4[(size_t)ga * 4 + h] - m);
        float eb = __expf(S4[(size_t)gb * 4 + h] - m);
        den += ea + eb;
        float4 ha = H4[(size_t)ga * 32 + lane];
        float4 hb = H4[(size_t)gb * 32 + lane];
        float4 va = V4[(size_t)ga * 32 + lane];
        float4 vb = V4[(size_t)gb * 32 + lane];
        acc.x += ha.x * wa + hb.x * wb;  pv.x += va.x * ea + vb.x * eb;
        acc.y += ha.y * wa + hb.y * wb;  pv.y += va.y * ea + vb.y * eb;
        acc.z += ha.z * wa + hb.z * wb;  pv.z += va.z * ea + vb.z * eb;
        acc.w += ha.w * wa + hb.w * wb;  pv.w += va.w * ea + vb.w * eb;
    }
    for (; p < p1; p++) {
        int g = map[p];
        float d = dinv[p];
        float wt = d * d;
        float e = __expf(S4[(size_t)g * 4 + h] - m);
        den += e;
        float4 hv = H4[(size_t)g * 32 + lane];
        float4 vv = V4[(size_t)g * 32 + lane];
        acc.x += hv.x * wt;  pv.x += vv.x * e;
        acc.y += hv.y * wt;  pv.y += vv.y * e;
        acc.z += hv.z * wt;  pv.z += vv.z * e;
        acc.w += hv.w * wt;  pv.w += vv.w * e;
    }

    int cnt = p1 - p0;
    float4 ob;
    if (cnt > 0) {
        float inv = 1.f / (float)cnt;
        float4 b4 = *(const float4*)&bias[lane * 4];
        ob.x = fmaxf(acc.x * inv + b4.x, 0.f);
        ob.y = fmaxf(acc.y * inv + b4.y, 0.f);
        ob.z = fmaxf(acc.z * inv + b4.z, 0.f);
        ob.w = fmaxf(acc.w * inv + b4.w, 0.f);
    } else {
        ob = make_float4(0.f, 0.f, 0.f, 0.f);
    }
    *(float4*)&outConv[(size_t)s * ldOut + lane * 4] = ob;

    float dn = 1.f / fmaxf(den, 1e-9f);
    float4 op;
    op.x = pv.x * dn; op.y = pv.y * dn; op.z = pv.z * dn; op.w = pv.w * dn;
    if (cnt == 0) op = make_float4(0.f, 0.f, 0.f, 0.f);
    *(float4*)&pooled[(size_t)s * 128 + lane * 4] = op;
}

// ---------------- orchestration ----------------
static inline int cdiv(int a, int b) { return (a + b - 1) / b; }

extern "C" void kernel_launch(void* const* d_in, const int* in_sizes, int n_in,
                              void* d_out, int out_size) {
    (void)in_sizes; (void)n_in; (void)out_size;
    const float* node_x  = (const float*)d_in[0];
    const int* eb_map    = (const int*)d_in[1];
    const int* eb_ei     = (const int*)d_in[2];
    const int* eb_batch  = (const int*)d_in[3];
    const int* nb_map    = (const int*)d_in[4];
    const int* nb_ei     = (const int*)d_in[5];
    const int* nb_batch  = (const int*)d_in[6];
    const float* W1   = (const float*)d_in[7];
    const float* b1   = (const float*)d_in[8];
    const float* Wk1  = (const float*)d_in[9];
    const float* Wv1  = (const float*)d_in[10];
    const float* sd1  = (const float*)d_in[11];
    const float* Wo1  = (const float*)d_in[12];
    const float* W2   = (const float*)d_in[13];
    const float* b2   = (const float*)d_in[14];
    const float* Wk2  = (const float*)d_in[15];
    const float* Wv2  = (const float*)d_in[16];
    const float* sd2  = (const float*)d_in[17];
    const float* Wo2  = (const float*)d_in[18];
    const float* clsW = (const float*)d_in[19];
    const float* clsb = (const float*)d_in[20];
    float* out = (float*)d_out;

    void* basep = nullptr;
    cudaGetSymbolAddress(&basep, g_scratch);
    char* base = (char*)basep;
    float* nodeH  = (float*)(base + O_NODEH);
    float* nodeV  = (float*)(base + O_NODEV);
    float* nodeS  = (float*)(base + O_NODES);
    int*   degA   = (int*)  (base + O_DEGA);
    float* dinvA  = (float*)(base + O_DINVA);
    int*   segPA  = (int*)  (base + O_SEGPA);
    int*   cntA   = (int*)  (base + O_CNTA);
    int*   offA   = (int*)  (base + O_OFFA);
    int*   curA   = (int*)  (base + O_CURA);
    int*   srtGA  = (int*)  (base + O_SRTGA);
    float* srtWA  = (float*)(base + O_SRTWA);
    float* poolA  = (float*)(base + O_POOLA);
    float* edgeX  = (float*)(base + O_EDGEX);
    float* edgeH  = (float*)(base + O_EDGEH);
    float* edgeV  = (float*)(base + O_EDGEV);
    float* edgeS  = (float*)(base + O_EDGES);
    int*   degB   = (int*)  (base + O_DEGB);
    float* dinvB  = (float*)(base + O_DINVB);
    int*   segPB  = (int*)  (base + O_SEGPB);
    int*   cntB   = (int*)  (base + O_CNTB);
    int*   offB   = (int*)  (base + O_OFFB);
    int*   curB   = (int*)  (base + O_CURB);
    int*   srtGB  = (int*)  (base + O_SRTGB);
    float* srtWB  = (float*)(base + O_SRTWB);
    float* poolB  = (float*)(base + O_POOLB);
    float* nodeO  = (float*)(base + O_NODEO);
    float* WksA   = (float*)(base + O_WKSA);
    float* WksB   = (float*)(base + O_WKSB);
    int*   incl   = (int*)  (base + O_INCL);
    int*   bsum   = (int*)  (base + O_BSUM);
    __nv_bfloat16* WAh  = (__nv_bfloat16*)(base + O_WAH);
    __nv_bfloat16* WAl  = (__nv_bfloat16*)(base + O_WAL);
    __nv_bfloat16* WO1h = (__nv_bfloat16*)(base + O_WO1H);
    __nv_bfloat16* WO1l = (__nv_bfloat16*)(base + O_WO1L);
    __nv_bfloat16* WBh  = (__nv_bfloat16*)(base + O_WBH);
    __nv_bfloat16* WBl  = (__nv_bfloat16*)(base + O_WBL);
    __nv_bfloat16* WO2h = (__nv_bfloat16*)(base + O_WO2H);
    __nv_bfloat16* WO2l = (__nv_bfloat16*)(base + O_WO2L);
    __nv_bfloat16* WCh  = (__nv_bfloat16*)(base + O_WCH);
    __nv_bfloat16* WCl  = (__nv_bfloat16*)(base + O_WCL);

    // smem sizes
    constexpr int SM128 = 128 * (128 + 4) * 4;       // staging dominates: 67584
    constexpr int SM64  = 128 * (64 + 4) * 4;        // 34816
    cudaFuncSetAttribute(wgemm_k<8, 128, 0>,  cudaFuncAttributeMaxDynamicSharedMemorySize, SM128);
    cudaFuncSetAttribute(wgemm_k<8, 128, 1>,  cudaFuncAttributeMaxDynamicSharedMemorySize, SM128);
    cudaFuncSetAttribute(wgemm_k<16, 128, 0>, cudaFuncAttributeMaxDynamicSharedMemorySize, SM128);
    cudaFuncSetAttribute(wgemm_k<16, 64, 2>,  cudaFuncAttributeMaxDynamicSharedMemorySize, SM64);

    // ---- weight prep ----
    prep_w_k<<<cdiv(128 * 128, 256), 256>>>(W1,  128, 128, WAh,  WAl,  0,   128);
    prep_w_k<<<cdiv(128 * 128, 256), 256>>>(Wv1, 128, 128, WAh,  WAl,  128, 128);
    prep_w_k<<<cdiv(128 * 128, 256), 256>>>(Wo1, 128, 128, WO1h, WO1l, 0,   128);
    prep_w_k<<<cdiv(256 * 128, 256), 256>>>(W2,  256, 128, WBh,  WBl,  0,   256);
    prep_w_k<<<cdiv(256 * 128, 256), 256>>>(Wv2, 256, 128, WBh,  WBl,  128, 256);
    prep_w_k<<<cdiv(128 * 128, 256), 256>>>(Wo2, 128, 128, WO2h, WO2l, 0,   128);
    fill_int_k<<<cdiv(64 * 256 * 2 / 4, 256), 256>>>((int*)WCh, 0, 64 * 256 * 2 / 4);
    fill_int_k<<<cdiv(64 * 256 * 2 / 4, 256), 256>>>((int*)WCl, 0, 64 * 256 * 2 / 4);
    prep_w_k<<<cdiv(256 * 40, 256), 256>>>(clsW, 256, 40, WCh, WCl, 0, 256);

    fold_seed_k<<<1, 512>>>(Wk1, sd1, WksA, 128);
    fold_seed_k<<<1, 1024>>>(Wk2, sd2, WksB, 256);

    // ===== stage A: node -> edge =====
    {
        dim3 g(cdiv(NN, 128), 2);
        wgemm_k<8, 128, 0><<<g, 256, SM128>>>(node_x, NN, WAh, WAl, nullptr, nodeH, nodeV, 0);
    }
    rowdot4_k<<<cdiv(NN * 32, 256), 256>>>(node_x, WksA, nodeS, NN, 128);

    fill_int_k<<<cdiv(PE, 256), 256>>>(degA, 1, PE);
    deg_accum_k<<<cdiv(ME, 256), 256>>>(eb_ei + ME, ME, degA);
    dinv_k<<<cdiv(PE, 256), 256>>>(degA, dinvA, PE);

    seg_starts_k<<<cdiv(NE + 1, 256), 256>>>(eb_batch, PE, NE, segPA);

    fill_int_k<<<cdiv(NE, 256), 256>>>(cntA, 0, NE);
    bucket_count_k<<<cdiv(ME, 256), 256>>>(eb_ei + ME, eb_batch, ME, cntA);
    {
        int nb = cdiv(NE, 1024);
        scan_block_k<<<nb, 1024>>>(cntA, NE, incl, bsum);
        scan_bsums_k<<<1, 1>>>(bsum, nb);
        scan_finalize_k<<<nb, 1024>>>(incl, bsum, NE, offA);
    }
    fill_int_k<<<cdiv(NE, 256), 256>>>(curA, 0, NE);
    bucket_scatter_k<<<cdiv(ME, 256), 256>>>(eb_ei, eb_ei + ME, eb_batch, eb_map,
                                             dinvA, offA, curA, ME, srtGA, srtWA);

    seg_fused_k<<<cdiv(NE * 32, 256), 256>>>(nodeH, nodeV, nodeS, eb_map, dinvA, segPA, offA,
                                             srtGA, srtWA, b1, edgeX, 256, poolA, NE);
    {
        dim3 g(cdiv(NE, 128), 1);
        wgemm_k<8, 128, 1><<<g, 256, SM128>>>(poolA, NE, WO1h, WO1l, nullptr,
                                              edgeX + 128, nullptr, 256);
    }

    // ===== stage B: edge -> node =====
    {
        dim3 g(cdiv(NE, 128), 2);
        wgemm_k<16, 128, 0><<<g, 256, SM128>>>(edgeX, NE, WBh, WBl, nullptr, edgeH, edgeV, 0);
    }
    rowdot4_k<<<cdiv(NE * 32, 256), 256>>>(edgeX, WksB, edgeS, NE, 256);

    fill_int_k<<<cdiv(PN, 256), 256>>>(degB, 1, PN);
    deg_accum_k<<<cdiv(MN, 256), 256>>>(nb_ei + MN, MN, degB);
    dinv_k<<<cdiv(PN, 256), 256>>>(degB, dinvB, PN);

    seg_starts_k<<<cdiv(NN + 1, 256), 256>>>(nb_batch, PN, NN, segPB);

    fill_int_k<<<cdiv(NN, 256), 256>>>(cntB, 0, NN);
    bucket_count_k<<<cdiv(MN, 256), 256>>>(nb_ei + MN, nb_batch, MN, cntB);
    {
        int nb = cdiv(NN, 1024);
        scan_block_k<<<nb, 1024>>>(cntB, NN, incl, bsum);
        scan_bsums_k<<<1, 1>>>(bsum, nb);
        scan_finalize_k<<<nb, 1024>>>(incl, bsum, NN, offB);
    }
    fill_int_k<<<cdiv(NN, 256), 256>>>(curB, 0, NN);
    bucket_scatter_k<<<cdiv(MN, 256), 256>>>(nb_ei, nb_ei + MN, nb_batch, nb_map,
                                             dinvB, offB, curB, MN, srtGB, srtWB);

    seg_fused_k<<<cdiv(NN * 32, 256), 256>>>(edgeH, edgeV, edgeS, nb_map, dinvB, segPB, offB,
                                             srtGB, srtWB, b2, nodeO, 256, poolB, NN);
    {
        dim3 g(cdiv(NN, 128), 1);
        wgemm_k<8, 128, 1><<<g, 256, SM128>>>(poolB, NN, WO2h, WO2l, nullptr,
                                              nodeO + 128, nullptr, 256);
    }

    // ===== classifier + fused log_softmax =====
    {
        dim3 g(cdiv(NN, 128), 1);
        wgemm_k<16, 64, 2><<<g, 256, SM64>>>(nodeO, NN, WCh, WCl, clsb, out, nullptr, 40);
    }
}

// round 6
// speedup vs baseline: 1.8268x; 1.1724x over previous
#include <cuda_runtime.h>
#include <cuda_bf16.h>
#include <mma.h>
#include <cstdint>
#include <cstddef>
#include <math_constants.h>

using namespace nvcuda;

// ---------------- problem constants ----------------
#define NN 50000
#define NE 25000
#define PE 400000
#define ME 800000
#define PN 400000
#define MN 800000
#define NNP 50048   // NN padded to 128-row multiple (GEMM full-tile stores)
#define NEP 25088   // NE padded

static __host__ __device__ constexpr size_t alup(size_t x) { return (x + 255) & ~size_t(255); }

// ---------------- scratch layout ----------------
constexpr size_t O_NODEH = 0;
constexpr size_t O_NODEV = O_NODEH + alup((size_t)NNP * 128 * 4);
constexpr size_t O_NODES = O_NODEV + alup((size_t)NNP * 128 * 4);
constexpr size_t O_DEGA  = O_NODES + alup((size_t)NN * 4 * 4);
constexpr size_t O_DINVA = O_DEGA  + alup((size_t)PE * 4);
constexpr size_t O_SEGPA = O_DINVA + alup((size_t)PE * 4);
constexpr size_t O_CNTA  = O_SEGPA + alup((size_t)(NE + 1) * 4);
constexpr size_t O_OFFA  = O_CNTA  + alup((size_t)NE * 4);
constexpr size_t O_CURA  = O_OFFA  + alup((size_t)(NE + 1) * 4);
constexpr size_t O_SRTGA = O_CURA  + alup((size_t)NE * 4);
constexpr size_t O_SRTWA = O_SRTGA + alup((size_t)ME * 4);
constexpr size_t O_POOLA = O_SRTWA + alup((size_t)ME * 4);
constexpr size_t O_EDGEX = O_POOLA + alup((size_t)NE * 128 * 4);
constexpr size_t O_EDGEH = O_EDGEX + alup((size_t)NEP * 256 * 4);
constexpr size_t O_EDGEV = O_EDGEH + alup((size_t)NEP * 128 * 4);
constexpr size_t O_EDGES = O_EDGEV + alup((size_t)NEP * 128 * 4);
constexpr size_t O_DEGB  = O_EDGES + alup((size_t)NE * 4 * 4);
constexpr size_t O_DINVB = O_DEGB  + alup((size_t)PN * 4);
constexpr size_t O_SEGPB = O_DINVB + alup((size_t)PN * 4);
constexpr size_t O_CNTB  = O_SEGPB + alup((size_t)(NN + 1) * 4);
constexpr size_t O_OFFB  = O_CNTB  + alup((size_t)NN * 4);
constexpr size_t O_CURB  = O_OFFB  + alup((size_t)(NN + 1) * 4);
constexpr size_t O_SRTGB = O_CURB  + alup((size_t)NN * 4);
constexpr size_t O_SRTWB = O_SRTGB + alup((size_t)MN * 4);
constexpr size_t O_POOLB = O_SRTWB + alup((size_t)MN * 4);
constexpr size_t O_NODEO = O_POOLB + alup((size_t)NN * 128 * 4);
constexpr size_t O_WKSA  = O_NODEO + alup((size_t)NNP * 256 * 4);
constexpr size_t O_WKSB  = O_WKSA  + alup((size_t)128 * 4 * 4);
constexpr size_t O_INCLA = O_WKSB  + alup((size_t)256 * 4 * 4);
constexpr size_t O_BSUMA = O_INCLA + alup((size_t)NE * 4);
constexpr size_t O_INCLB = O_BSUMA + alup((size_t)64 * 4);
constexpr size_t O_BSUMB = O_INCLB + alup((size_t)NN * 4);
constexpr size_t O_WAH   = O_BSUMB + alup((size_t)64 * 4);
constexpr size_t O_WAL   = O_WAH   + alup((size_t)256 * 128 * 2);
constexpr size_t O_WO1H  = O_WAL   + alup((size_t)256 * 128 * 2);
constexpr size_t O_WO1L  = O_WO1H  + alup((size_t)128 * 128 * 2);
constexpr size_t O_WBH   = O_WO1L  + alup((size_t)128 * 128 * 2);
constexpr size_t O_WBL   = O_WBH   + alup((size_t)256 * 256 * 2);
constexpr size_t O_WO2H  = O_WBL   + alup((size_t)256 * 256 * 2);
constexpr size_t O_WO2L  = O_WO2H  + alup((size_t)128 * 128 * 2);
constexpr size_t O_WCH   = O_WO2L  + alup((size_t)128 * 128 * 2);
constexpr size_t O_WCL   = O_WCH   + alup((size_t)64 * 256 * 2);
constexpr size_t SCRATCH_TOTAL = O_WCL + alup((size_t)64 * 256 * 2);

__device__ __align__(256) unsigned char g_scratch[SCRATCH_TOTAL];

// ---------------- shared device helpers ----------------
__device__ __forceinline__ void cvt_store(const float* W, int N, int i,
                                          __nv_bfloat16* hi, __nv_bfloat16* lo,
                                          int n_off, int ldK) {
    int k = i / N, n = i % N;
    float v = W[i];
    __nv_bfloat16 h = __float2bfloat16(v);
    float r = v - __bfloat162float(h);
    hi[(size_t)(n_off + n) * ldK + k] = h;
    lo[(size_t)(n_off + n) * ldK + k] = __float2bfloat16(r);
}

__device__ __forceinline__ void fold_one(const float* Wk, const float* seed,
                                         float* Wks, int i) {
    int f = i >> 2, h = i & 3;
    float s = 0.f;
    #pragma unroll
    for (int d = 0; d < 32; d++) s += Wk[(size_t)f * 128 + h * 32 + d] * seed[h * 32 + d];
    Wks[i] = s * 0.17677669529663687f;
}

__device__ __forceinline__ void rowdot_body(const float* __restrict__ X,
                                            const float* __restrict__ Wks,
                                            float* __restrict__ out,
                                            int row, int K, int lane) {
    const float* x = X + (size_t)row * K;
    float a0 = 0, a1 = 0, a2 = 0, a3 = 0;
    for (int f0 = lane * 4; f0 < K; f0 += 128) {
        float4 xv = *(const float4*)&x[f0];
        float4 w0 = *(const float4*)&Wks[(size_t)(f0 + 0) * 4];
        float4 w1 = *(const float4*)&Wks[(size_t)(f0 + 1) * 4];
        float4 w2 = *(const float4*)&Wks[(size_t)(f0 + 2) * 4];
        float4 w3 = *(const float4*)&Wks[(size_t)(f0 + 3) * 4];
        a0 += xv.x * w0.x + xv.y * w1.x + xv.z * w2.x + xv.w * w3.x;
        a1 += xv.x * w0.y + xv.y * w1.y + xv.z * w2.y + xv.w * w3.y;
        a2 += xv.x * w0.z + xv.y * w1.z + xv.z * w2.z + xv.w * w3.z;
        a3 += xv.x * w0.w + xv.y * w1.w + xv.z * w2.w + xv.w * w3.w;
    }
    #pragma unroll
    for (int o = 16; o; o >>= 1) {
        a0 += __shfl_xor_sync(0xffffffffu, a0, o);
        a1 += __shfl_xor_sync(0xffffffffu, a1, o);
        a2 += __shfl_xor_sync(0xffffffffu, a2, o);
        a3 += __shfl_xor_sync(0xffffffffu, a3, o);
    }
    if (lane == 0) {
        float* o4 = out + (size_t)row * 4;
        o4[0] = a0; o4[1] = a1; o4[2] = a2; o4[3] = a3;
    }
}

__device__ __forceinline__ void seg_start_one(const int* __restrict__ batch, int P, int s,
                                              int* __restrict__ segP) {
    int lo = 0, hi = P;
    while (lo < hi) {
        int mid = (lo + hi) >> 1;
        if (batch[mid] < s) lo = mid + 1; else hi = mid;
    }
    segP[s] = lo;
}

// ---------------- misc0: init + seg_starts (both) + all weight prep ----------------
constexpr int M0_R1 = PE;
constexpr int M0_R2 = M0_R1 + PN;
constexpr int M0_R3 = M0_R2 + NE;
constexpr int M0_R4 = M0_R3 + NN;
constexpr int M0_R5 = M0_R4 + NE + 1;
constexpr int M0_R6 = M0_R5 + NN + 1;
constexpr int M0_R7 = M0_R6 + 148992;

__global__ void misc0_k(
    const int* __restrict__ eb_batch, const int* __restrict__ nb_batch,
    int* degA, int* cntA, int* curA, int* degB, int* cntB, int* curB,
    int* segPA, int* segPB,
    const float* __restrict__ W1, const float* __restrict__ Wv1, const float* __restrict__ Wo1,
    const float* __restrict__ W2, const float* __restrict__ Wv2, const float* __restrict__ Wo2,
    const float* __restrict__ clsW,
    const float* __restrict__ Wk1, const float* __restrict__ sd1,
    const float* __restrict__ Wk2, const float* __restrict__ sd2,
    __nv_bfloat16* WAh, __nv_bfloat16* WAl, __nv_bfloat16* WO1h, __nv_bfloat16* WO1l,
    __nv_bfloat16* WBh, __nv_bfloat16* WBl, __nv_bfloat16* WO2h, __nv_bfloat16* WO2l,
    __nv_bfloat16* WCh, __nv_bfloat16* WCl, float* WksA, float* WksB) {
    int i = blockIdx.x * blockDim.x + threadIdx.x;
    if (i < M0_R1)      degA[i] = 0;
    else if (i < M0_R2) degB[i - M0_R1] = 0;
    else if (i < M0_R3) { int j = i - M0_R2; cntA[j] = 0; curA[j] = 0; }
    else if (i < M0_R4) { int j = i - M0_R3; cntB[j] = 0; curB[j] = 0; }
    else if (i < M0_R5) seg_start_one(eb_batch, PE, i - M0_R4, segPA);
    else if (i < M0_R6) seg_start_one(nb_batch, PN, i - M0_R5, segPB);
    else if (i < M0_R7) {
        int j = i - M0_R6;
        if (j < 16384)       cvt_store(W1,  128, j, WAh, WAl, 0, 128);
        else if (j < 32768)  cvt_store(Wv1, 128, j - 16384, WAh, WAl, 128, 128);
        else if (j < 49152)  cvt_store(Wo1, 128, j - 32768, WO1h, WO1l, 0, 128);
        else if (j < 81920)  cvt_store(W2,  128, j - 49152, WBh, WBl, 0, 256);
        else if (j < 114688) cvt_store(Wv2, 128, j - 81920, WBh, WBl, 128, 256);
        else if (j < 131072) cvt_store(Wo2, 128, j - 114688, WO2h, WO2l, 0, 128);
        else if (j < 141312) cvt_store(clsW, 40, j - 131072, WCh, WCl, 0, 256);
        else if (j < 147456) {
            int q = j - 141312;
            size_t p = (size_t)(40 + q / 256) * 256 + (q % 256);
            WCh[p] = __float2bfloat16(0.f);
            WCl[p] = __float2bfloat16(0.f);
        }
        else if (j < 147968) fold_one(Wk1, sd1, WksA, j - 147456);
        else                 fold_one(Wk2, sd2, WksB, j - 147968);
    }
}

// ---------------- WMMA bf16 GEMM (hi/lo 3-term split, fp32 accum) + optional piggyback ----------------
struct XArgs {
    const int* dstA; const int* batA; int* degA; int* cntA;
    const int* dstB; const int* batB; int* degB; int* cntB;
    const float* X; const float* Wks; float* S; int M;
};

// EXTRA 0: none. EXTRA 1: degcount both stages (blocks >= gemmGX, y==0).
// EXTRA 2: rowdot4 (K=256) for xa.M rows.
template<int KC, int NT, int MODE, int EXTRA>
__global__ void __launch_bounds__(256, 2)
wgemm_k(const float* __restrict__ A, int M,
        const __nv_bfloat16* __restrict__ Bhi, const __nv_bfloat16* __restrict__ Blo,
        const float* __restrict__ bias,
        float* __restrict__ out0, float* __restrict__ out1, int ldc,
        int gemmGX, XArgs xa) {
    if (EXTRA && blockIdx.x >= gemmGX) {
        if (blockIdx.y != 0) return;
        int id = (blockIdx.x - gemmGX) * 256 + threadIdx.x;
        if (EXTRA == 1) {
            if (id < ME) {
                int d = xa.dstA[id];
                atomicAdd(&xa.degA[d], 1);
                atomicAdd(&xa.cntA[xa.batA[d]], 1);
            } else if (id < ME + MN) {
                id -= ME;
                int d = xa.dstB[id];
                atomicAdd(&xa.degB[d], 1);
                atomicAdd(&xa.cntB[xa.batB[d]], 1);
            }
        } else {
            int gw = id >> 5;
            if (gw < xa.M) rowdot_body(xa.X, xa.Wks, xa.S, gw, 256, threadIdx.x & 31);
        }
        return;
    }

    constexpr int K = KC * 16;
    constexpr int WN = NT / 2;
    constexpr int NTI = WN / 16;
    constexpr int NTS = NT + 4;

    extern __shared__ char smc[];
    __nv_bfloat16* sAh = (__nv_bfloat16*)smc;
    __nv_bfloat16* sAl = sAh + 128 * 24;
    __nv_bfloat16* sBh = sAl + 128 * 24;
    __nv_bfloat16* sBl = sBh + NT * 24;
    float* stg = (float*)smc;

    int tid = threadIdx.x;
    int wid = tid >> 5;
    int wm = wid >> 1, wn = wid & 1;
    int row0 = blockIdx.x * 128;
    int col0 = blockIdx.y * NT;

    wmma::fragment<wmma::accumulator, 16, 16, 16, float> acc[2][NTI];
    #pragma unroll
    for (int m = 0; m < 2; m++)
        #pragma unroll
        for (int n = 0; n < NTI; n++) wmma::fill_fragment(acc[m][n], 0.0f);

    for (int kc = 0; kc < KC; kc++) {
        int k0 = kc * 16;
        {
            int r = tid >> 1, kk = (tid & 1) * 8;
            int gr = row0 + r;
            float4 v0 = make_float4(0.f, 0.f, 0.f, 0.f), v1 = v0;
            if (gr < M) {
                const float* ap = A + (size_t)gr * K + k0 + kk;
                v0 = *(const float4*)ap;
                v1 = *(const float4*)(ap + 4);
            }
            float vv[8] = {v0.x, v0.y, v0.z, v0.w, v1.x, v1.y, v1.z, v1.w};
            ushort hs[8], ls[8];
            #pragma unroll
            for (int q = 0; q < 8; q++) {
                __nv_bfloat16 h = __float2bfloat16(vv[q]);
                hs[q] = __bfloat16_as_ushort(h);
                ls[q] = __bfloat16_as_ushort(__float2bfloat16(vv[q] - __bfloat162float(h)));
            }
            uint4 hp, lp;
            hp.x = hs[0] | ((uint32_t)hs[1] << 16); hp.y = hs[2] | ((uint32_t)hs[3] << 16);
            hp.z = hs[4] | ((uint32_t)hs[5] << 16); hp.w = hs[6] | ((uint32_t)hs[7] << 16);
            lp.x = ls[0] | ((uint32_t)ls[1] << 16); lp.y = ls[2] | ((uint32_t)ls[3] << 16);
            lp.z = ls[4] | ((uint32_t)ls[5] << 16); lp.w = ls[6] | ((uint32_t)ls[7] << 16);
            *(uint4*)&sAh[r * 24 + kk] = hp;
            *(uint4*)&sAl[r * 24 + kk] = lp;
        }
        for (int i = tid; i < NT * 2; i += 256) {
            int n = i >> 1, kk = (i & 1) * 8;
            size_t g = (size_t)(col0 + n) * K + k0 + kk;
            *(uint4*)&sBh[n * 24 + kk] = *(const uint4*)(Bhi + g);
            *(uint4*)&sBl[n * 24 + kk] = *(const uint4*)(Blo + g);
        }
        __syncthreads();

        wmma::fragment<wmma::matrix_a, 16, 16, 16, __nv_bfloat16, wmma::row_major> ah[2], al[2];
        #pragma unroll
        for (int m = 0; m < 2; m++) {
            wmma::load_matrix_sync(ah[m], sAh + (wm * 32 + m * 16) * 24, 24);
            wmma::load_matrix_sync(al[m], sAl + (wm * 32 + m * 16) * 24, 24);
        }
        #pragma unroll
        for (int n = 0; n < NTI; n++) {
            wmma::fragment<wmma::matrix_b, 16, 16, 16, __nv_bfloat16, wmma::col_major> bh, bl;
            wmma::load_matrix_sync(bh, sBh + (wn * WN + n * 16) * 24, 24);
            wmma::load_matrix_sync(bl, sBl + (wn * WN + n * 16) * 24, 24);
            #pragma unroll
            for (int m = 0; m < 2; m++) {
                wmma::mma_sync(acc[m][n], ah[m], bh, acc[m][n]);
                wmma::mma_sync(acc[m][n], ah[m], bl, acc[m][n]);
                wmma::mma_sync(acc[m][n], al[m], bh, acc[m][n]);
            }
        }
        __syncthreads();
    }

    if (MODE == 2) {
        #pragma unroll
        for (int m = 0; m < 2; m++)
            #pragma unroll
            for (int n = 0; n < NTI; n++)
                wmma::store_matrix_sync(stg + (wm * 32 + m * 16) * NTS + wn * WN + n * 16,
                                        acc[m][n], NTS, wmma::mem_row_major);
        __syncthreads();
        if (tid < 128) {
            int gr = row0 + tid;
            if (gr < M) {
                const float* row = stg + tid * NTS;
                float v[40];
                float mx = -CUDART_INF_F;
                #pragma unroll
                for (int c = 0; c < 40; c++) { v[c] = row[c] + bias[c]; mx = fmaxf(mx, v[c]); }
                float s = 0.f;
                #pragma unroll
                for (int c = 0; c < 40; c++) s += expf(v[c] - mx);
                float lse = mx + logf(s);
                #pragma unroll
                for (int c = 0; c < 40; c += 4) {
                    float4 f = make_float4(v[c] - lse, v[c+1] - lse, v[c+2] - lse, v[c+3] - lse);
                    *(float4*)&out0[(size_t)gr * 40 + c] = f;
                }
            }
        }
    } else {
        #pragma unroll
        for (int m = 0; m < 2; m++) {
            int gr0 = row0 + wm * 32 + m * 16;
            #pragma unroll
            for (int n = 0; n < NTI; n++) {
                int gc = col0 + wn * WN + n * 16;
                if (MODE == 1) {
                    #pragma unroll
                    for (int t = 0; t < acc[m][n].num_elements; t++)
                        acc[m][n].x[t] = fmaxf(acc[m][n].x[t], 0.f);
                    wmma::store_matrix_sync(out0 + (size_t)gr0 * ldc + gc, acc[m][n],
                                            ldc, wmma::mem_row_major);
                } else {
                    float* dst = (gc < 128) ? (out0 + (size_t)gr0 * 128 + gc)
                                            : (out1 + (size_t)gr0 * 128 + gc - 128);
                    wmma::store_matrix_sync(dst, acc[m][n], 128, wmma::mem_row_major);
                }
            }
        }
    }
}

// ---------------- misc1: both scans + both dinv + rowdot4-A (1024-thread blocks) ----------------
constexpr int NBA = (NE + 1023) / 1024;           // 25
constexpr int NBB = (NN + 1023) / 1024;           // 49
constexpr int DINV_B = (PE + PN + 1023) / 1024;   // 782
constexpr int RDA_B = (NN + 31) / 32;             // 1563

__device__ __forceinline__ void scan_body(const int* __restrict__ cnt, int n,
                                          int* __restrict__ incl, int* __restrict__ bsums,
                                          int b) {
    __shared__ int sm[1024];
    int i = b * 1024 + threadIdx.x;
    int v = (i < n) ? cnt[i] : 0;
    sm[threadIdx.x] = v;
    __syncthreads();
    for (int o = 1; o < 1024; o <<= 1) {
        int t = (threadIdx.x >= o) ? sm[threadIdx.x - o] : 0;
        __syncthreads();
        sm[threadIdx.x] += t;
        __syncthreads();
    }
    if (i < n) incl[i] = sm[threadIdx.x];
    if (threadIdx.x == 1023) bsums[b] = sm[1023];
}

__global__ void misc1_k(const int* __restrict__ cntA, int* inclA, int* bsumA,
                        const int* __restrict__ cntB, int* inclB, int* bsumB,
                        const int* __restrict__ degA, float* dinvA,
                        const int* __restrict__ degB, float* dinvB,
                        const float* __restrict__ X, const float* __restrict__ Wks,
                        float* S) {
    int b = blockIdx.x;
    if (b < NBA) { scan_body(cntA, NE, inclA, bsumA, b); return; }
    b -= NBA;
    if (b < NBB) { scan_body(cntB, NN, inclB, bsumB, b); return; }
    b -= NBB;
    if (b < DINV_B) {
        int i = b * 1024 + threadIdx.x;
        if (i < PE) dinvA[i] = rsqrtf((float)(degA[i] + 1));
        else if (i < PE + PN) dinvB[i - PE] = rsqrtf((float)(degB[i - PE] + 1));
        return;
    }
    b -= DINV_B;
    int gw = b * 32 + (threadIdx.x >> 5);
    if (gw < NN) rowdot_body(X, Wks, S, gw, 128, threadIdx.x & 31);
}

__global__ void bsums2_k(int* bsumA, int nbA, int* bsumB, int nbB) {
    if (threadIdx.x != 0) return;
    int* p = (blockIdx.x == 0) ? bsumA : bsumB;
    int nb = (blockIdx.x == 0) ? nbA : nbB;
    int run = 0;
    for (int b = 0; b < nb; b++) { int t = p[b]; p[b] = run; run += t; }
}

__global__ void fin2_k(const int* __restrict__ inclA, const int* __restrict__ bsumA, int* offA,
                       const int* __restrict__ inclB, const int* __restrict__ bsumB, int* offB) {
    int b = blockIdx.x;
    if (b < NBA) {
        int i = b * 1024 + threadIdx.x;
        if (i < NE) offA[i + 1] = inclA[i] + bsumA[b];
        if (i == 0) offA[0] = 0;
    } else {
        b -= NBA;
        int i = b * 1024 + threadIdx.x;
        if (i < NN) offB[i + 1] = inclB[i] + bsumB[b];
        if (i == 0) offB[0] = 0;
    }
}

__device__ __forceinline__ void scatter_one(const int* src, const int* dst, const int* batch,
                                            const int* map, const float* dinv, const int* off,
                                            int* cursor, int i, int* outG, float* outW) {
    int d = dst[i];
    int s = batch[d];
    int pos = off[s] + atomicAdd(&cursor[s], 1);
    int sc = src[i];
    outG[pos] = map[sc];
    outW[pos] = dinv[sc] * dinv[d];
}

__global__ void scatter2_k(const int* eb_ei, const int* eb_batch, const int* eb_map,
                           const float* dinvA, const int* offA, int* curA,
                           int* srtGA, float* srtWA,
                           const int* nb_ei, const int* nb_batch, const int* nb_map,
                           const float* dinvB, const int* offB, int* curB,
                           int* srtGB, float* srtWB) {
    int i = blockIdx.x * blockDim.x + threadIdx.x;
    if (i < ME)
        scatter_one(eb_ei, eb_ei + ME, eb_batch, eb_map, dinvA, offA, curA, i, srtGA, srtWA);
    else if (i < ME + MN)
        scatter_one(nb_ei, nb_ei + MN, nb_batch, nb_map, dinvB, offB, curB, i - ME, srtGB, srtWB);
}

// ---------------- fused per-segment: GCN-conv mean + PMA softmax pool ----------------
__global__ void seg_fused_k(const float* __restrict__ H, const float* __restrict__ V,
                            const float* __restrict__ S4, const int* __restrict__ map,
                            const float* __restrict__ dinv,
                            const int* __restrict__ segP, const int* __restrict__ eOff,
                            const int* __restrict__ sG, const float* __restrict__ sW,
                            const float* __restrict__ bias,
                            float* __restrict__ outConv, int ldOut,
                            float* __restrict__ pooled, int S) {
    int w = (blockIdx.x * blockDim.x + threadIdx.x) >> 5;
    if (w >= S) return;
    int lane = threadIdx.x & 31;
    int h = lane >> 3;
    int s = w;
    const float4* H4 = (const float4*)H;
    const float4* V4 = (const float4*)V;

    int p0 = segP[s], p1 = segP[s + 1];
    int e0 = eOff[s], e1 = eOff[s + 1];

    float4 acc = make_float4(0.f, 0.f, 0.f, 0.f);
    int j = e0;
    for (; j + 3 < e1; j += 4) {
        int g0 = sG[j], g1 = sG[j + 1], g2 = sG[j + 2], g3 = sG[j + 3];
        float w0 = sW[j], w1 = sW[j + 1], w2 = sW[j + 2], w3 = sW[j + 3];
        float4 h0 = H4[(size_t)g0 * 32 + lane];
        float4 h1 = H4[(size_t)g1 * 32 + lane];
        float4 h2 = H4[(size_t)g2 * 32 + lane];
        float4 h3 = H4[(size_t)g3 * 32 + lane];
        acc.x += h0.x * w0 + h1.x * w1 + h2.x * w2 + h3.x * w3;
        acc.y += h0.y * w0 + h1.y * w1 + h2.y * w2 + h3.y * w3;
        acc.z += h0.z * w0 + h1.z * w1 + h2.z * w2 + h3.z * w3;
        acc.w += h0.w * w0 + h1.w * w1 + h2.w * w2 + h3.w * w3;
    }
    for (; j < e1; j++) {
        int g = sG[j]; float wt = sW[j];
        float4 hv = H4[(size_t)g * 32 + lane];
        acc.x += hv.x * wt; acc.y += hv.y * wt; acc.z += hv.z * wt; acc.w += hv.w * wt;
    }

    float m = -CUDART_INF_F;
    for (int p = p0; p < p1; p++)
        m = fmaxf(m, S4[(size_t)map[p] * 4 + h]);

    float den = 0.f;
    float4 pv = make_float4(0.f, 0.f, 0.f, 0.f);
    int p = p0;
    for (; p + 1 < p1; p += 2) {
        int ga = map[p], gb = map[p + 1];
        float da = dinv[p], db = dinv[p + 1];
        float wa = da * da, wb = db * db;
        float ea = __expf(S4[(size_t)ga * 4 + h] - m);
        float eb = __expf(S4[(size_t)gb * 4 + h] - m);
        den += ea + eb;
        float4 ha = H4[(size_t)ga * 32 + lane];
        float4 hb = H4[(size_t)gb * 32 + lane];
        float4 va = V4[(size_t)ga * 32 + lane];
        float4 vb = V4[(size_t)gb * 32 + lane];
        acc.x += ha.x * wa + hb.x * wb;  pv.x += va.x * ea + vb.x * eb;
        acc.y += ha.y * wa + hb.y * wb;  pv.y += va.y * ea + vb.y * eb;
        acc.z += ha.z * wa + hb.z * wb;  pv.z += va.z * ea + vb.z * eb;
        acc.w += ha.w * wa + hb.w * wb;  pv.w += va.w * ea + vb.w * eb;
    }
    for (; p < p1; p++) {
        int g = map[p];
        float d = dinv[p];
        float wt = d * d;
        float e = __expf(S4[(size_t)g * 4 + h] - m);
        den += e;
        float4 hv = H4[(size_t)g * 32 + lane];
        float4 vv = V4[(size_t)g * 32 + lane];
        acc.x += hv.x * wt;  pv.x += vv.x * e;
        acc.y += hv.y * wt;  pv.y += vv.y * e;
        acc.z += hv.z * wt;  pv.z += vv.z * e;
        acc.w += hv.w * wt;  pv.w += vv.w * e;
    }

    int cnt = p1 - p0;
    float4 ob;
    if (cnt > 0) {
        float inv = 1.f / (float)cnt;
        float4 b4 = *(const float4*)&bias[lane * 4];
        ob.x = fmaxf(acc.x * inv + b4.x, 0.f);
        ob.y = fmaxf(acc.y * inv + b4.y, 0.f);
        ob.z = fmaxf(acc.z * inv + b4.z, 0.f);
        ob.w = fmaxf(acc.w * inv + b4.w, 0.f);
    } else {
        ob = make_float4(0.f, 0.f, 0.f, 0.f);
    }
    *(float4*)&outConv[(size_t)s * ldOut + lane * 4] = ob;

    float dn = 1.f / fmaxf(den, 1e-9f);
    float4 op;
    op.x = pv.x * dn; op.y = pv.y * dn; op.z = pv.z * dn; op.w = pv.w * dn;
    if (cnt == 0) op = make_float4(0.f, 0.f, 0.f, 0.f);
    *(float4*)&pooled[(size_t)s * 128 + lane * 4] = op;
}

// ---------------- orchestration (single stream, graph-safe) ----------------
static inline int cdiv(int a, int b) { return (a + b - 1) / b; }

extern "C" void kernel_launch(void* const* d_in, const int* in_sizes, int n_in,
                              void* d_out, int out_size) {
    (void)in_sizes; (void)n_in; (void)out_size;
    const float* node_x  = (const float*)d_in[0];
    const int* eb_map    = (const int*)d_in[1];
    const int* eb_ei     = (const int*)d_in[2];
    const int* eb_batch  = (const int*)d_in[3];
    const int* nb_map    = (const int*)d_in[4];
    const int* nb_ei     = (const int*)d_in[5];
    const int* nb_batch  = (const int*)d_in[6];
    const float* W1   = (const float*)d_in[7];
    const float* b1   = (const float*)d_in[8];
    const float* Wk1  = (const float*)d_in[9];
    const float* Wv1  = (const float*)d_in[10];
    const float* sd1  = (const float*)d_in[11];
    const float* Wo1  = (const float*)d_in[12];
    const float* W2   = (const float*)d_in[13];
    const float* b2   = (const float*)d_in[14];
    const float* Wk2  = (const float*)d_in[15];
    const float* Wv2  = (const float*)d_in[16];
    const float* sd2  = (const float*)d_in[17];
    const float* Wo2  = (const float*)d_in[18];
    const float* clsW = (const float*)d_in[19];
    const float* clsb = (const float*)d_in[20];
    float* out = (float*)d_out;

    void* basep = nullptr;
    cudaGetSymbolAddress(&basep, g_scratch);
    char* base = (char*)basep;
    float* nodeH  = (float*)(base + O_NODEH);
    float* nodeV  = (float*)(base + O_NODEV);
    float* nodeS  = (float*)(base + O_NODES);
    int*   degA   = (int*)  (base + O_DEGA);
    float* dinvA  = (float*)(base + O_DINVA);
    int*   segPA  = (int*)  (base + O_SEGPA);
    int*   cntA   = (int*)  (base + O_CNTA);
    int*   offA   = (int*)  (base + O_OFFA);
    int*   curA   = (int*)  (base + O_CURA);
    int*   srtGA  = (int*)  (base + O_SRTGA);
    float* srtWA  = (float*)(base + O_SRTWA);
    float* poolA  = (float*)(base + O_POOLA);
    float* edgeX  = (float*)(base + O_EDGEX);
    float* edgeH  = (float*)(base + O_EDGEH);
    float* edgeV  = (float*)(base + O_EDGEV);
    float* edgeS  = (float*)(base + O_EDGES);
    int*   degB   = (int*)  (base + O_DEGB);
    float* dinvB  = (float*)(base + O_DINVB);
    int*   segPB  = (int*)  (base + O_SEGPB);
    int*   cntB   = (int*)  (base + O_CNTB);
    int*   offB   = (int*)  (base + O_OFFB);
    int*   curB   = (int*)  (base + O_CURB);
    int*   srtGB  = (int*)  (base + O_SRTGB);
    float* srtWB  = (float*)(base + O_SRTWB);
    float* poolB  = (float*)(base + O_POOLB);
    float* nodeO  = (float*)(base + O_NODEO);
    float* WksA   = (float*)(base + O_WKSA);
    float* WksB   = (float*)(base + O_WKSB);
    int*   inclA  = (int*)  (base + O_INCLA);
    int*   bsumA  = (int*)  (base + O_BSUMA);
    int*   inclB  = (int*)  (base + O_INCLB);
    int*   bsumB  = (int*)  (base + O_BSUMB);
    __nv_bfloat16* WAh  = (__nv_bfloat16*)(base + O_WAH);
    __nv_bfloat16* WAl  = (__nv_bfloat16*)(base + O_WAL);
    __nv_bfloat16* WO1h = (__nv_bfloat16*)(base + O_WO1H);
    __nv_bfloat16* WO1l = (__nv_bfloat16*)(base + O_WO1L);
    __nv_bfloat16* WBh  = (__nv_bfloat16*)(base + O_WBH);
    __nv_bfloat16* WBl  = (__nv_bfloat16*)(base + O_WBL);
    __nv_bfloat16* WO2h = (__nv_bfloat16*)(base + O_WO2H);
    __nv_bfloat16* WO2l = (__nv_bfloat16*)(base + O_WO2L);
    __nv_bfloat16* WCh  = (__nv_bfloat16*)(base + O_WCH);
    __nv_bfloat16* WCl  = (__nv_bfloat16*)(base + O_WCL);

    constexpr int SMAB128 = (128 * 24 * 2 + 128 * 24 * 2) * 2;  // 24576
    constexpr int SMCLS   = 128 * (64 + 4) * 4;                 // 34816

    XArgs xnone = {};
    XArgs xdeg = { eb_ei + ME, eb_batch, degA, cntA,
                   nb_ei + MN, nb_batch, degB, cntB,
                   nullptr, nullptr, nullptr, 0 };
    XArgs xrdB = { nullptr, nullptr, nullptr, nullptr,
                   nullptr, nullptr, nullptr, nullptr,
                   edgeX, WksB, edgeS, NE };

    // L1: init + seg_starts + all weight prep (everything input-only)
    misc0_k<<<cdiv(M0_R7, 256), 256>>>(eb_batch, nb_batch,
                                       degA, cntA, curA, degB, cntB, curB, segPA, segPB,
                                       W1, Wv1, Wo1, W2, Wv2, Wo2, clsW,
                                       Wk1, sd1, Wk2, sd2,
                                       WAh, WAl, WO1h, WO1l, WBh, WBl,
                                       WO2h, WO2l, WCh, WCl, WksA, WksB);

    // L2: stage-A GEMM  ∥  degcount (both stages) as extra blocks
    {
        int gx = cdiv(NN, 128);
        int extra = cdiv(ME + MN, 256);
        dim3 g(gx + extra, 2);
        wgemm_k<8, 128, 0, 1><<<g, 256, SMAB128>>>(node_x, NN, WAh, WAl, nullptr,
                                                   nodeH, nodeV, 0, gx, xdeg);
    }

    // L3: both scans + both dinv + rowdot4-A
    misc1_k<<<NBA + NBB + DINV_B + RDA_B, 1024>>>(cntA, inclA, bsumA, cntB, inclB, bsumB,
                                                  degA, dinvA, degB, dinvB,
                                                  node_x, WksA, nodeS);
    // L4/L5: scan tail
    bsums2_k<<<2, 1>>>(bsumA, NBA, bsumB, NBB);
    fin2_k<<<NBA + NBB, 1024>>>(inclA, bsumA, offA, inclB, bsumB, offB);

    // L6: both scatters
    scatter2_k<<<cdiv(ME + MN, 256), 256>>>(eb_ei, eb_batch, eb_map, dinvA, offA, curA,
                                            srtGA, srtWA,
                                            nb_ei, nb_batch, nb_map, dinvB, offB, curB,
                                            srtGB, srtWB);

    // L7: stage-A fused segment kernel
    seg_fused_k<<<cdiv(NE * 32, 256), 256>>>(nodeH, nodeV, nodeS, eb_map, dinvA, segPA, offA,
                                             srtGA, srtWA, b1, edgeX, 256, poolA, NE);
    // L8: Wo1
    {
        int gx = cdiv(NE, 128);
        dim3 g(gx, 1);
        wgemm_k<8, 128, 1, 0><<<g, 256, SMAB128>>>(poolA, NE, WO1h, WO1l, nullptr,
                                                   edgeX + 128, nullptr, 256, gx, xnone);
    }

    // L9: stage-B GEMM  ∥  rowdot4-B as extra blocks
    {
        int gx = cdiv(NE, 128);
        int extra = cdiv(NE * 32, 256);
        dim3 g(gx + extra, 2);
        wgemm_k<16, 128, 0, 2><<<g, 256, SMAB128>>>(edgeX, NE, WBh, WBl, nullptr,
                                                    edgeH, edgeV, 0, gx, xrdB);
    }

    // L10: stage-B fused segment kernel
    seg_fused_k<<<cdiv(NN * 32, 256), 256>>>(edgeH, edgeV, edgeS, nb_map, dinvB, segPB, offB,
                                             srtGB, srtWB, b2, nodeO, 256, poolB, NN);
    // L11: Wo2
    {
        int gx = cdiv(NN, 128);
        dim3 g(gx, 1);
        wgemm_k<8, 128, 1, 0><<<g, 256, SMAB128>>>(poolB, NN, WO2h, WO2l, nullptr,
                                                   nodeO + 128, nullptr, 256, gx, xnone);
    }

    // L12: classifier + fused log-softmax
    {
        int gx = cdiv(NN, 128);
        dim3 g(gx, 1);
        wgemm_k<16, 64, 2, 0><<<g, 256, SMCLS>>>(nodeO, NN, WCh, WCl, clsb,
                                                 out, nullptr, 40, gx, xnone);
    }
}

// round 7
// speedup vs baseline: 1.8449x; 1.0099x over previous
#include <cuda_runtime.h>
#include <cuda_bf16.h>
#include <mma.h>
#include <cstdint>
#include <cstddef>
#include <math_constants.h>

using namespace nvcuda;

// ---------------- problem constants ----------------
#define NN 50000
#define NE 25000
#define PE 400000
#define ME 800000
#define PN 400000
#define MN 800000
#define NNP 50048
#define NEP 25088

static __host__ __device__ constexpr size_t alup(size_t x) { return (x + 255) & ~size_t(255); }

// ---------------- scratch layout ----------------
constexpr size_t O_NODEH = 0;
constexpr size_t O_NODEV = O_NODEH + alup((size_t)NNP * 128 * 4);
constexpr size_t O_NODES = O_NODEV + alup((size_t)NNP * 128 * 4);
constexpr size_t O_DEGA  = O_NODES + alup((size_t)NN * 4 * 4);
constexpr size_t O_DINVA = O_DEGA  + alup((size_t)PE * 4);
constexpr size_t O_SEGPA = O_DINVA + alup((size_t)PE * 4);
constexpr size_t O_CNTA  = O_SEGPA + alup((size_t)(NE + 1) * 4);
constexpr size_t O_OFFA  = O_CNTA  + alup((size_t)NE * 4);
constexpr size_t O_CURA  = O_OFFA  + alup((size_t)(NE + 1) * 4);
constexpr size_t O_SRTGA = O_CURA  + alup((size_t)NE * 4);
constexpr size_t O_SRTWA = O_SRTGA + alup((size_t)ME * 4);
constexpr size_t O_POOLA = O_SRTWA + alup((size_t)ME * 4);
constexpr size_t O_EDGEX = O_POOLA + alup((size_t)NE * 128 * 4);
constexpr size_t O_EDGEH = O_EDGEX + alup((size_t)NEP * 256 * 4);
constexpr size_t O_EDGEV = O_EDGEH + alup((size_t)NEP * 128 * 4);
constexpr size_t O_EDGES = O_EDGEV + alup((size_t)NEP * 128 * 4);
constexpr size_t O_DEGB  = O_EDGES + alup((size_t)NE * 4 * 4);
constexpr size_t O_DINVB = O_DEGB  + alup((size_t)PN * 4);
constexpr size_t O_SEGPB = O_DINVB + alup((size_t)PN * 4);
constexpr size_t O_CNTB  = O_SEGPB + alup((size_t)(NN + 1) * 4);
constexpr size_t O_OFFB  = O_CNTB  + alup((size_t)NN * 4);
constexpr size_t O_CURB  = O_OFFB  + alup((size_t)(NN + 1) * 4);
constexpr size_t O_SRTGB = O_CURB  + alup((size_t)NN * 4);
constexpr size_t O_SRTWB = O_SRTGB + alup((size_t)MN * 4);
constexpr size_t O_POOLB = O_SRTWB + alup((size_t)MN * 4);
constexpr size_t O_NODEO = O_POOLB + alup((size_t)NN * 128 * 4);
constexpr size_t O_WKSA  = O_NODEO + alup((size_t)NNP * 256 * 4);
constexpr size_t O_WKSB  = O_WKSA  + alup((size_t)128 * 4 * 4);
constexpr size_t O_INCLA = O_WKSB  + alup((size_t)256 * 4 * 4);
constexpr size_t O_BSUMA = O_INCLA + alup((size_t)NE * 4);
constexpr size_t O_INCLB = O_BSUMA + alup((size_t)64 * 4);
constexpr size_t O_BSUMB = O_INCLB + alup((size_t)NN * 4);
constexpr size_t O_WAH   = O_BSUMB + alup((size_t)64 * 4);
constexpr size_t O_WAL   = O_WAH   + alup((size_t)256 * 128 * 2);
constexpr size_t O_WO1H  = O_WAL   + alup((size_t)256 * 128 * 2);
constexpr size_t O_WO1L  = O_WO1H  + alup((size_t)128 * 128 * 2);
constexpr size_t O_WBH   = O_WO1L  + alup((size_t)128 * 128 * 2);
constexpr size_t O_WBL   = O_WBH   + alup((size_t)256 * 256 * 2);
constexpr size_t O_WO2H  = O_WBL   + alup((size_t)256 * 256 * 2);
constexpr size_t O_WO2L  = O_WO2H  + alup((size_t)128 * 128 * 2);
constexpr size_t O_WCH   = O_WO2L  + alup((size_t)128 * 128 * 2);
constexpr size_t O_WCL   = O_WCH   + alup((size_t)64 * 256 * 2);
constexpr size_t SCRATCH_TOTAL = O_WCL + alup((size_t)64 * 256 * 2);

__device__ __align__(256) unsigned char g_scratch[SCRATCH_TOTAL];

// ---------------- shared device helpers ----------------
__device__ __forceinline__ void cvt_store(const float* W, int N, int i,
                                          __nv_bfloat16* hi, __nv_bfloat16* lo,
                                          int n_off, int ldK) {
    int k = i / N, n = i % N;
    float v = W[i];
    __nv_bfloat16 h = __float2bfloat16(v);
    float r = v - __bfloat162float(h);
    hi[(size_t)(n_off + n) * ldK + k] = h;
    lo[(size_t)(n_off + n) * ldK + k] = __float2bfloat16(r);
}

__device__ __forceinline__ void fold_one(const float* Wk, const float* seed,
                                         float* Wks, int i) {
    int f = i >> 2, h = i & 3;
    float s = 0.f;
    #pragma unroll
    for (int d = 0; d < 32; d++) s += Wk[(size_t)f * 128 + h * 32 + d] * seed[h * 32 + d];
    Wks[i] = s * 0.17677669529663687f;
}

__device__ __forceinline__ void rowdot_body(const float* __restrict__ X,
                                            const float* __restrict__ Wks,
                                            float* __restrict__ out,
                                            int row, int K, int lane) {
    const float* x = X + (size_t)row * K;
    float a0 = 0, a1 = 0, a2 = 0, a3 = 0;
    for (int f0 = lane * 4; f0 < K; f0 += 128) {
        float4 xv = *(const float4*)&x[f0];
        float4 w0 = *(const float4*)&Wks[(size_t)(f0 + 0) * 4];
        float4 w1 = *(const float4*)&Wks[(size_t)(f0 + 1) * 4];
        float4 w2 = *(const float4*)&Wks[(size_t)(f0 + 2) * 4];
        float4 w3 = *(const float4*)&Wks[(size_t)(f0 + 3) * 4];
        a0 += xv.x * w0.x + xv.y * w1.x + xv.z * w2.x + xv.w * w3.x;
        a1 += xv.x * w0.y + xv.y * w1.y + xv.z * w2.y + xv.w * w3.y;
        a2 += xv.x * w0.z + xv.y * w1.z + xv.z * w2.z + xv.w * w3.z;
        a3 += xv.x * w0.w + xv.y * w1.w + xv.z * w2.w + xv.w * w3.w;
    }
    #pragma unroll
    for (int o = 16; o; o >>= 1) {
        a0 += __shfl_xor_sync(0xffffffffu, a0, o);
        a1 += __shfl_xor_sync(0xffffffffu, a1, o);
        a2 += __shfl_xor_sync(0xffffffffu, a2, o);
        a3 += __shfl_xor_sync(0xffffffffu, a3, o);
    }
    if (lane == 0) {
        float* o4 = out + (size_t)row * 4;
        o4[0] = a0; o4[1] = a1; o4[2] = a2; o4[3] = a3;
    }
}

__device__ __forceinline__ void seg_start_one(const int* __restrict__ batch, int P, int s,
                                              int* __restrict__ segP) {
    int lo = 0, hi = P;
    while (lo < hi) {
        int mid = (lo + hi) >> 1;
        if (batch[mid] < s) lo = mid + 1; else hi = mid;
    }
    segP[s] = lo;
}

// ---------------- misc0: init + seg_starts (both) + all weight prep ----------------
constexpr int M0_R1 = PE;
constexpr int M0_R2 = M0_R1 + PN;
constexpr int M0_R3 = M0_R2 + NE;
constexpr int M0_R4 = M0_R3 + NN;
constexpr int M0_R5 = M0_R4 + NE + 1;
constexpr int M0_R6 = M0_R5 + NN + 1;
constexpr int M0_R7 = M0_R6 + 148992;

__global__ void misc0_k(
    const int* __restrict__ eb_batch, const int* __restrict__ nb_batch,
    int* degA, int* cntA, int* curA, int* degB, int* cntB, int* curB,
    int* segPA, int* segPB,
    const float* __restrict__ W1, const float* __restrict__ Wv1, const float* __restrict__ Wo1,
    const float* __restrict__ W2, const float* __restrict__ Wv2, const float* __restrict__ Wo2,
    const float* __restrict__ clsW,
    const float* __restrict__ Wk1, const float* __restrict__ sd1,
    const float* __restrict__ Wk2, const float* __restrict__ sd2,
    __nv_bfloat16* WAh, __nv_bfloat16* WAl, __nv_bfloat16* WO1h, __nv_bfloat16* WO1l,
    __nv_bfloat16* WBh, __nv_bfloat16* WBl, __nv_bfloat16* WO2h, __nv_bfloat16* WO2l,
    __nv_bfloat16* WCh, __nv_bfloat16* WCl, float* WksA, float* WksB) {
    int i = blockIdx.x * blockDim.x + threadIdx.x;
    if (i < M0_R1)      degA[i] = 0;
    else if (i < M0_R2) degB[i - M0_R1] = 0;
    else if (i < M0_R3) { int j = i - M0_R2; cntA[j] = 0; curA[j] = 0; }
    else if (i < M0_R4) { int j = i - M0_R3; cntB[j] = 0; curB[j] = 0; }
    else if (i < M0_R5) seg_start_one(eb_batch, PE, i - M0_R4, segPA);
    else if (i < M0_R6) seg_start_one(nb_batch, PN, i - M0_R5, segPB);
    else if (i < M0_R7) {
        int j = i - M0_R6;
        if (j < 16384)       cvt_store(W1,  128, j, WAh, WAl, 0, 128);
        else if (j < 32768)  cvt_store(Wv1, 128, j - 16384, WAh, WAl, 128, 128);
        else if (j < 49152)  cvt_store(Wo1, 128, j - 32768, WO1h, WO1l, 0, 128);
        else if (j < 81920)  cvt_store(W2,  128, j - 49152, WBh, WBl, 0, 256);
        else if (j < 114688) cvt_store(Wv2, 128, j - 81920, WBh, WBl, 128, 256);
        else if (j < 131072) cvt_store(Wo2, 128, j - 114688, WO2h, WO2l, 0, 128);
        else if (j < 141312) cvt_store(clsW, 40, j - 131072, WCh, WCl, 0, 256);
        else if (j < 147456) {
            int q = j - 141312;
            size_t p = (size_t)(40 + q / 256) * 256 + (q % 256);
            WCh[p] = __float2bfloat16(0.f);
            WCl[p] = __float2bfloat16(0.f);
        }
        else if (j < 147968) fold_one(Wk1, sd1, WksA, j - 147456);
        else                 fold_one(Wk2, sd2, WksB, j - 147968);
    }
}

// ---------------- WMMA bf16 GEMM (hi/lo 3-term split) + optional piggyback ----------------
struct XArgs {
    const int* dstA; const int* batA; int* degA; int* cntA;
    const int* dstB; const int* batB; int* degB; int* cntB;
    const float* X; const float* Wks; float* S; int M;
};

template<int KC, int NT, int MODE, int EXTRA>
__global__ void __launch_bounds__(256, 2)
wgemm_k(const float* __restrict__ A, int M,
        const __nv_bfloat16* __restrict__ Bhi, const __nv_bfloat16* __restrict__ Blo,
        const float* __restrict__ bias,
        float* __restrict__ out0, float* __restrict__ out1, int ldc,
        int gemmGX, XArgs xa) {
    if (EXTRA && blockIdx.x >= gemmGX) {
        if (blockIdx.y != 0) return;
        int id = (blockIdx.x - gemmGX) * 256 + threadIdx.x;
        if (EXTRA == 1) {
            if (id < ME) {
                int d = xa.dstA[id];
                atomicAdd(&xa.degA[d], 1);
                atomicAdd(&xa.cntA[xa.batA[d]], 1);
            } else if (id < ME + MN) {
                id -= ME;
                int d = xa.dstB[id];
                atomicAdd(&xa.degB[d], 1);
                atomicAdd(&xa.cntB[xa.batB[d]], 1);
            }
        } else {
            int gw = id >> 5;
            if (gw < xa.M) rowdot_body(xa.X, xa.Wks, xa.S, gw, 256, threadIdx.x & 31);
        }
        return;
    }

    constexpr int K = KC * 16;
    constexpr int WN = NT / 2;
    constexpr int NTI = WN / 16;
    constexpr int NTS = NT + 4;

    extern __shared__ char smc[];
    __nv_bfloat16* sAh = (__nv_bfloat16*)smc;
    __nv_bfloat16* sAl = sAh + 128 * 24;
    __nv_bfloat16* sBh = sAl + 128 * 24;
    __nv_bfloat16* sBl = sBh + NT * 24;
    float* stg = (float*)smc;

    int tid = threadIdx.x;
    int wid = tid >> 5;
    int wm = wid >> 1, wn = wid & 1;
    int row0 = blockIdx.x * 128;
    int col0 = blockIdx.y * NT;

    wmma::fragment<wmma::accumulator, 16, 16, 16, float> acc[2][NTI];
    #pragma unroll
    for (int m = 0; m < 2; m++)
        #pragma unroll
        for (int n = 0; n < NTI; n++) wmma::fill_fragment(acc[m][n], 0.0f);

    for (int kc = 0; kc < KC; kc++) {
        int k0 = kc * 16;
        {
            int r = tid >> 1, kk = (tid & 1) * 8;
            int gr = row0 + r;
            float4 v0 = make_float4(0.f, 0.f, 0.f, 0.f), v1 = v0;
            if (gr < M) {
                const float* ap = A + (size_t)gr * K + k0 + kk;
                v0 = *(const float4*)ap;
                v1 = *(const float4*)(ap + 4);
            }
            float vv[8] = {v0.x, v0.y, v0.z, v0.w, v1.x, v1.y, v1.z, v1.w};
            ushort hs[8], ls[8];
            #pragma unroll
            for (int q = 0; q < 8; q++) {
                __nv_bfloat16 h = __float2bfloat16(vv[q]);
                hs[q] = __bfloat16_as_ushort(h);
                ls[q] = __bfloat16_as_ushort(__float2bfloat16(vv[q] - __bfloat162float(h)));
            }
            uint4 hp, lp;
            hp.x = hs[0] | ((uint32_t)hs[1] << 16); hp.y = hs[2] | ((uint32_t)hs[3] << 16);
            hp.z = hs[4] | ((uint32_t)hs[5] << 16); hp.w = hs[6] | ((uint32_t)hs[7] << 16);
            lp.x = ls[0] | ((uint32_t)ls[1] << 16); lp.y = ls[2] | ((uint32_t)ls[3] << 16);
            lp.z = ls[4] | ((uint32_t)ls[5] << 16); lp.w = ls[6] | ((uint32_t)ls[7] << 16);
            *(uint4*)&sAh[r * 24 + kk] = hp;
            *(uint4*)&sAl[r * 24 + kk] = lp;
        }
        for (int i = tid; i < NT * 2; i += 256) {
            int n = i >> 1, kk = (i & 1) * 8;
            size_t g = (size_t)(col0 + n) * K + k0 + kk;
            *(uint4*)&sBh[n * 24 + kk] = *(const uint4*)(Bhi + g);
            *(uint4*)&sBl[n * 24 + kk] = *(const uint4*)(Blo + g);
        }
        __syncthreads();

        wmma::fragment<wmma::matrix_a, 16, 16, 16, __nv_bfloat16, wmma::row_major> ah[2], al[2];
        #pragma unroll
        for (int m = 0; m < 2; m++) {
            wmma::load_matrix_sync(ah[m], sAh + (wm * 32 + m * 16) * 24, 24);
            wmma::load_matrix_sync(al[m], sAl + (wm * 32 + m * 16) * 24, 24);
        }
        #pragma unroll
        for (int n = 0; n < NTI; n++) {
            wmma::fragment<wmma::matrix_b, 16, 16, 16, __nv_bfloat16, wmma::col_major> bh, bl;
            wmma::load_matrix_sync(bh, sBh + (wn * WN + n * 16) * 24, 24);
            wmma::load_matrix_sync(bl, sBl + (wn * WN + n * 16) * 24, 24);
            #pragma unroll
            for (int m = 0; m < 2; m++) {
                wmma::mma_sync(acc[m][n], ah[m], bh, acc[m][n]);
                wmma::mma_sync(acc[m][n], ah[m], bl, acc[m][n]);
                wmma::mma_sync(acc[m][n], al[m], bh, acc[m][n]);
            }
        }
        __syncthreads();
    }

    if (MODE == 2) {
        #pragma unroll
        for (int m = 0; m < 2; m++)
            #pragma unroll
            for (int n = 0; n < NTI; n++)
                wmma::store_matrix_sync(stg + (wm * 32 + m * 16) * NTS + wn * WN + n * 16,
                                        acc[m][n], NTS, wmma::mem_row_major);
        __syncthreads();
        if (tid < 128) {
            int gr = row0 + tid;
            if (gr < M) {
                const float* row = stg + tid * NTS;
                float v[40];
                float mx = -CUDART_INF_F;
                #pragma unroll
                for (int c = 0; c < 40; c++) { v[c] = row[c] + bias[c]; mx = fmaxf(mx, v[c]); }
                float s = 0.f;
                #pragma unroll
                for (int c = 0; c < 40; c++) s += expf(v[c] - mx);
                float lse = mx + logf(s);
                #pragma unroll
                for (int c = 0; c < 40; c += 4) {
                    float4 f = make_float4(v[c] - lse, v[c+1] - lse, v[c+2] - lse, v[c+3] - lse);
                    *(float4*)&out0[(size_t)gr * 40 + c] = f;
                }
            }
        }
    } else {
        #pragma unroll
        for (int m = 0; m < 2; m++) {
            int gr0 = row0 + wm * 32 + m * 16;
            #pragma unroll
            for (int n = 0; n < NTI; n++) {
                int gc = col0 + wn * WN + n * 16;
                if (MODE == 1) {
                    #pragma unroll
                    for (int t = 0; t < acc[m][n].num_elements; t++)
                        acc[m][n].x[t] = fmaxf(acc[m][n].x[t], 0.f);
                    wmma::store_matrix_sync(out0 + (size_t)gr0 * ldc + gc, acc[m][n],
                                            ldc, wmma::mem_row_major);
                } else {
                    float* dst = (gc < 128) ? (out0 + (size_t)gr0 * 128 + gc)
                                            : (out1 + (size_t)gr0 * 128 + gc - 128);
                    wmma::store_matrix_sync(dst, acc[m][n], 128, wmma::mem_row_major);
                }
            }
        }
    }
}

// ---------------- misc1: both scans + both dinv + rowdot4-A ----------------
constexpr int NBA = (NE + 1023) / 1024;
constexpr int NBB = (NN + 1023) / 1024;
constexpr int DINV_B = (PE + PN + 1023) / 1024;
constexpr int RDA_B = (NN + 31) / 32;

__device__ __forceinline__ void scan_body(const int* __restrict__ cnt, int n,
                                          int* __restrict__ incl, int* __restrict__ bsums,
                                          int b) {
    __shared__ int sm[1024];
    int i = b * 1024 + threadIdx.x;
    int v = (i < n) ? cnt[i] : 0;
    sm[threadIdx.x] = v;
    __syncthreads();
    for (int o = 1; o < 1024; o <<= 1) {
        int t = (threadIdx.x >= o) ? sm[threadIdx.x - o] : 0;
        __syncthreads();
        sm[threadIdx.x] += t;
        __syncthreads();
    }
    if (i < n) incl[i] = sm[threadIdx.x];
    if (threadIdx.x == 1023) bsums[b] = sm[1023];
}

__global__ void misc1_k(const int* __restrict__ cntA, int* inclA, int* bsumA,
                        const int* __restrict__ cntB, int* inclB, int* bsumB,
                        const int* __restrict__ degA, float* dinvA,
                        const int* __restrict__ degB, float* dinvB,
                        const float* __restrict__ X, const float* __restrict__ Wks,
                        float* S) {
    int b = blockIdx.x;
    if (b < NBA) { scan_body(cntA, NE, inclA, bsumA, b); return; }
    b -= NBA;
    if (b < NBB) { scan_body(cntB, NN, inclB, bsumB, b); return; }
    b -= NBB;
    if (b < DINV_B) {
        int i = b * 1024 + threadIdx.x;
        if (i < PE) dinvA[i] = rsqrtf((float)(degA[i] + 1));
        else if (i < PE + PN) dinvB[i - PE] = rsqrtf((float)(degB[i - PE] + 1));
        return;
    }
    b -= DINV_B;
    int gw = b * 32 + (threadIdx.x >> 5);
    if (gw < NN) rowdot_body(X, Wks, S, gw, 128, threadIdx.x & 31);
}

// ---------------- fin2: block-total prefix (inline, redundant per block) + finalize ----------------
__global__ void fin2_k(const int* __restrict__ inclA, const int* __restrict__ bsumA, int* offA,
                       const int* __restrict__ inclB, const int* __restrict__ bsumB, int* offB) {
    __shared__ int pfx;
    int b = blockIdx.x;
    if (b < NBA) {
        if (threadIdx.x == 0) {
            int s = 0;
            for (int t = 0; t < b; t++) s += bsumA[t];
            pfx = s;
        }
        __syncthreads();
        int i = b * 1024 + threadIdx.x;
        if (i < NE) offA[i + 1] = inclA[i] + pfx;
        if (i == 0) offA[0] = 0;
    } else {
        b -= NBA;
        if (threadIdx.x == 0) {
            int s = 0;
            for (int t = 0; t < b; t++) s += bsumB[t];
            pfx = s;
        }
        __syncthreads();
        int i = b * 1024 + threadIdx.x;
        if (i < NN) offB[i + 1] = inclB[i] + pfx;
        if (i == 0) offB[0] = 0;
    }
}

__device__ __forceinline__ void scatter_one(const int* src, const int* dst, const int* batch,
                                            const int* map, const float* dinv, const int* off,
                                            int* cursor, int i, int* outG, float* outW) {
    int d = dst[i];
    int s = batch[d];
    int pos = off[s] + atomicAdd(&cursor[s], 1);
    int sc = src[i];
    outG[pos] = map[sc];
    outW[pos] = dinv[sc] * dinv[d];
}

__global__ void scatter2_k(const int* eb_ei, const int* eb_batch, const int* eb_map,
                           const float* dinvA, const int* offA, int* curA,
                           int* srtGA, float* srtWA,
                           const int* nb_ei, const int* nb_batch, const int* nb_map,
                           const float* dinvB, const int* offB, int* curB,
                           int* srtGB, float* srtWB) {
    int i = blockIdx.x * blockDim.x + threadIdx.x;
    if (i < ME)
        scatter_one(eb_ei, eb_ei + ME, eb_batch, eb_map, dinvA, offA, curA, i, srtGA, srtWA);
    else if (i < ME + MN)
        scatter_one(nb_ei, nb_ei + MN, nb_batch, nb_map, dinvB, offB, curB, i - ME, srtGB, srtWB);
}

// ---------------- fused per-segment: GCN-conv mean + PMA softmax pool ----------------
// Warp per segment. Max pass parallelized 8-wide per head (lanes of a head
// stride over incidences, then shfl-reduce within the 8-lane head group).
__global__ void seg_fused_k(const float* __restrict__ H, const float* __restrict__ V,
                            const float* __restrict__ S4, const int* __restrict__ map,
                            const float* __restrict__ dinv,
                            const int* __restrict__ segP, const int* __restrict__ eOff,
                            const int* __restrict__ sG, const float* __restrict__ sW,
                            const float* __restrict__ bias,
                            float* __restrict__ outConv, int ldOut,
                            float* __restrict__ pooled, int S) {
    int w = (blockIdx.x * blockDim.x + threadIdx.x) >> 5;
    if (w >= S) return;
    int lane = threadIdx.x & 31;
    int h = lane >> 3;
    int sub = lane & 7;
    int s = w;
    const float4* H4 = (const float4*)H;
    const float4* V4 = (const float4*)V;

    int p0 = segP[s], p1 = segP[s + 1];
    int e0 = eOff[s], e1 = eOff[s + 1];

    float4 acc = make_float4(0.f, 0.f, 0.f, 0.f);
    int j = e0;
    for (; j + 3 < e1; j += 4) {
        int g0 = sG[j], g1 = sG[j + 1], g2 = sG[j + 2], g3 = sG[j + 3];
        float w0 = sW[j], w1 = sW[j + 1], w2 = sW[j + 2], w3 = sW[j + 3];
        float4 h0 = H4[(size_t)g0 * 32 + lane];
        float4 h1 = H4[(size_t)g1 * 32 + lane];
        float4 h2 = H4[(size_t)g2 * 32 + lane];
        float4 h3 = H4[(size_t)g3 * 32 + lane];
        acc.x += h0.x * w0 + h1.x * w1 + h2.x * w2 + h3.x * w3;
        acc.y += h0.y * w0 + h1.y * w1 + h2.y * w2 + h3.y * w3;
        acc.z += h0.z * w0 + h1.z * w1 + h2.z * w2 + h3.z * w3;
        acc.w += h0.w * w0 + h1.w * w1 + h2.w * w2 + h3.w * w3;
    }
    for (; j < e1; j++) {
        int g = sG[j]; float wt = sW[j];
        float4 hv = H4[(size_t)g * 32 + lane];
        acc.x += hv.x * wt; acc.y += hv.y * wt; acc.z += hv.z * wt; acc.w += hv.w * wt;
    }

    // max pass: 8-wide per head, then reduce across the head's 8 lanes
    float m = -CUDART_INF_F;
    for (int p = p0 + sub; p < p1; p += 8)
        m = fmaxf(m, S4[(size_t)map[p] * 4 + h]);
    #pragma unroll
    for (int o = 1; o < 8; o <<= 1)
        m = fmaxf(m, __shfl_xor_sync(0xffffffffu, m, o));

    // combined pass: self-loop conv + exp-sum + weighted V
    float den = 0.f;
    float4 pv = make_float4(0.f, 0.f, 0.f, 0.f);
    int p = p0;
    for (; p + 1 < p1; p += 2) {
        int ga = map[p], gb = map[p + 1];
        float da = dinv[p], db = dinv[p + 1];
        float wa = da * da, wb = db * db;
        float ea = __expf(S4[(size_t)ga * 4 + h] - m);
        float eb = __expf(S4[(size_t)gb * 4 + h] - m);
        den += ea + eb;
        float4 ha = H4[(size_t)ga * 32 + lane];
        float4 hb = H4[(size_t)gb * 32 + lane];
        float4 va = V4[(size_t)ga * 32 + lane];
        float4 vb = V4[(size_t)gb * 32 + lane];
        acc.x += ha.x * wa + hb.x * wb;  pv.x += va.x * ea + vb.x * eb;
        acc.y += ha.y * wa + hb.y * wb;  pv.y += va.y * ea + vb.y * eb;
        acc.z += ha.z * wa + hb.z * wb;  pv.z += va.z * ea + vb.z * eb;
        acc.w += ha.w * wa + hb.w * wb;  pv.w += va.w * ea + vb.w * eb;
    }
    for (; p < p1; p++) {
        int g = map[p];
        float d = dinv[p];
        float wt = d * d;
        float e = __expf(S4[(size_t)g * 4 + h] - m);
        den += e;
        float4 hv = H4[(size_t)g * 32 + lane];
        float4 vv = V4[(size_t)g * 32 + lane];
        acc.x += hv.x * wt;  pv.x += vv.x * e;
        acc.y += hv.y * wt;  pv.y += vv.y * e;
        acc.z += hv.z * wt;  pv.z += vv.z * e;
        acc.w += hv.w * wt;  pv.w += vv.w * e;
    }

    int cnt = p1 - p0;
    float4 ob;
    if (cnt > 0) {
        float inv = 1.f / (float)cnt;
        float4 b4 = *(const float4*)&bias[lane * 4];
        ob.x = fmaxf(acc.x * inv + b4.x, 0.f);
        ob.y = fmaxf(acc.y * inv + b4.y, 0.f);
        ob.z = fmaxf(acc.z * inv + b4.z, 0.f);
        ob.w = fmaxf(acc.w * inv + b4.w, 0.f);
    } else {
        ob = make_float4(0.f, 0.f, 0.f, 0.f);
    }
    *(float4*)&outConv[(size_t)s * ldOut + lane * 4] = ob;

    float dn = 1.f / fmaxf(den, 1e-9f);
    float4 op;
    op.x = pv.x * dn; op.y = pv.y * dn; op.z = pv.z * dn; op.w = pv.w * dn;
    if (cnt == 0) op = make_float4(0.f, 0.f, 0.f, 0.f);
    *(float4*)&pooled[(size_t)s * 128 + lane * 4] = op;
}

// ---------------- orchestration (single stream, graph-safe) ----------------
static inline int cdiv(int a, int b) { return (a + b - 1) / b; }

extern "C" void kernel_launch(void* const* d_in, const int* in_sizes, int n_in,
                              void* d_out, int out_size) {
    (void)in_sizes; (void)n_in; (void)out_size;
    const float* node_x  = (const float*)d_in[0];
    const int* eb_map    = (const int*)d_in[1];
    const int* eb_ei     = (const int*)d_in[2];
    const int* eb_batch  = (const int*)d_in[3];
    const int* nb_map    = (const int*)d_in[4];
    const int* nb_ei     = (const int*)d_in[5];
    const int* nb_batch  = (const int*)d_in[6];
    const float* W1   = (const float*)d_in[7];
    const float* b1   = (const float*)d_in[8];
    const float* Wk1  = (const float*)d_in[9];
    const float* Wv1  = (const float*)d_in[10];
    const float* sd1  = (const float*)d_in[11];
    const float* Wo1  = (const float*)d_in[12];
    const float* W2   = (const float*)d_in[13];
    const float* b2   = (const float*)d_in[14];
    const float* Wk2  = (const float*)d_in[15];
    const float* Wv2  = (const float*)d_in[16];
    const float* sd2  = (const float*)d_in[17];
    const float* Wo2  = (const float*)d_in[18];
    const float* clsW = (const float*)d_in[19];
    const float* clsb = (const float*)d_in[20];
    float* out = (float*)d_out;

    void* basep = nullptr;
    cudaGetSymbolAddress(&basep, g_scratch);
    char* base = (char*)basep;
    float* nodeH  = (float*)(base + O_NODEH);
    float* nodeV  = (float*)(base + O_NODEV);
    float* nodeS  = (float*)(base + O_NODES);
    int*   degA   = (int*)  (base + O_DEGA);
    float* dinvA  = (float*)(base + O_DINVA);
    int*   segPA  = (int*)  (base + O_SEGPA);
    int*   cntA   = (int*)  (base + O_CNTA);
    int*   offA   = (int*)  (base + O_OFFA);
    int*   curA   = (int*)  (base + O_CURA);
    int*   srtGA  = (int*)  (base + O_SRTGA);
    float* srtWA  = (float*)(base + O_SRTWA);
    float* poolA  = (float*)(base + O_POOLA);
    float* edgeX  = (float*)(base + O_EDGEX);
    float* edgeH  = (float*)(base + O_EDGEH);
    float* edgeV  = (float*)(base + O_EDGEV);
    float* edgeS  = (float*)(base + O_EDGES);
    int*   degB   = (int*)  (base + O_DEGB);
    float* dinvB  = (float*)(base + O_DINVB);
    int*   segPB  = (int*)  (base + O_SEGPB);
    int*   cntB   = (int*)  (base + O_CNTB);
    int*   offB   = (int*)  (base + O_OFFB);
    int*   curB   = (int*)  (base + O_CURB);
    int*   srtGB  = (int*)  (base + O_SRTGB);
    float* srtWB  = (float*)(base + O_SRTWB);
    float* poolB  = (float*)(base + O_POOLB);
    float* nodeO  = (float*)(base + O_NODEO);
    float* WksA   = (float*)(base + O_WKSA);
    float* WksB   = (float*)(base + O_WKSB);
    int*   inclA  = (int*)  (base + O_INCLA);
    int*   bsumA  = (int*)  (base + O_BSUMA);
    int*   inclB  = (int*)  (base + O_INCLB);
    int*   bsumB  = (int*)  (base + O_BSUMB);
    __nv_bfloat16* WAh  = (__nv_bfloat16*)(base + O_WAH);
    __nv_bfloat16* WAl  = (__nv_bfloat16*)(base + O_WAL);
    __nv_bfloat16* WO1h = (__nv_bfloat16*)(base + O_WO1H);
    __nv_bfloat16* WO1l = (__nv_bfloat16*)(base + O_WO1L);
    __nv_bfloat16* WBh  = (__nv_bfloat16*)(base + O_WBH);
    __nv_bfloat16* WBl  = (__nv_bfloat16*)(base + O_WBL);
    __nv_bfloat16* WO2h = (__nv_bfloat16*)(base + O_WO2H);
    __nv_bfloat16* WO2l = (__nv_bfloat16*)(base + O_WO2L);
    __nv_bfloat16* WCh  = (__nv_bfloat16*)(base + O_WCH);
    __nv_bfloat16* WCl  = (__nv_bfloat16*)(base + O_WCL);

    constexpr int SMAB128 = (128 * 24 * 2 + 128 * 24 * 2) * 2;  // 24576
    constexpr int SMCLS   = 128 * (64 + 4) * 4;                 // 34816

    XArgs xnone = {};
    XArgs xdeg = { eb_ei + ME, eb_batch, degA, cntA,
                   nb_ei + MN, nb_batch, degB, cntB,
                   nullptr, nullptr, nullptr, 0 };
    XArgs xrdB = { nullptr, nullptr, nullptr, nullptr,
                   nullptr, nullptr, nullptr, nullptr,
                   edgeX, WksB, edgeS, NE };

    // L1: init + seg_starts + all weight prep
    misc0_k<<<cdiv(M0_R7, 256), 256>>>(eb_batch, nb_batch,
                                       degA, cntA, curA, degB, cntB, curB, segPA, segPB,
                                       W1, Wv1, Wo1, W2, Wv2, Wo2, clsW,
                                       Wk1, sd1, Wk2, sd2,
                                       WAh, WAl, WO1h, WO1l, WBh, WBl,
                                       WO2h, WO2l, WCh, WCl, WksA, WksB);

    // L2: stage-A GEMM  ∥  degcount (both stages)
    {
        int gx = cdiv(NN, 128);
        int extra = cdiv(ME + MN, 256);
        dim3 g(gx + extra, 2);
        wgemm_k<8, 128, 0, 1><<<g, 256, SMAB128>>>(node_x, NN, WAh, WAl, nullptr,
                                                   nodeH, nodeV, 0, gx, xdeg);
    }

    // L3: both scans + both dinv + rowdot4-A
    misc1_k<<<NBA + NBB + DINV_B + RDA_B, 1024>>>(cntA, inclA, bsumA, cntB, inclB, bsumB,
                                                  degA, dinvA, degB, dinvB,
                                                  node_x, WksA, nodeS);
    // L4: finalize offsets (prefix of block totals computed inline)
    fin2_k<<<NBA + NBB, 1024>>>(inclA, bsumA, offA, inclB, bsumB, offB);

    // L5: both scatters
    scatter2_k<<<cdiv(ME + MN, 256), 256>>>(eb_ei, eb_batch, eb_map, dinvA, offA, curA,
                                            srtGA, srtWA,
                                            nb_ei, nb_batch, nb_map, dinvB, offB, curB,
                                            srtGB, srtWB);

    // L6: stage-A fused segment kernel (ncu capture target)
    seg_fused_k<<<cdiv(NE * 32, 256), 256>>>(nodeH, nodeV, nodeS, eb_map, dinvA, segPA, offA,
                                             srtGA, srtWA, b1, edgeX, 256, poolA, NE);
    // L7: Wo1
    {
        int gx = cdiv(NE, 128);
        dim3 g(gx, 1);
        wgemm_k<8, 128, 1, 0><<<g, 256, SMAB128>>>(poolA, NE, WO1h, WO1l, nullptr,
                                                   edgeX + 128, nullptr, 256, gx, xnone);
    }

    // L8: stage-B GEMM  ∥  rowdot4-B
    {
        int gx = cdiv(NE, 128);
        int extra = cdiv(NE * 32, 256);
        dim3 g(gx + extra, 2);
        wgemm_k<16, 128, 0, 2><<<g, 256, SMAB128>>>(edgeX, NE, WBh, WBl, nullptr,
                                                    edgeH, edgeV, 0, gx, xrdB);
    }

    // L9: stage-B fused segment kernel
    seg_fused_k<<<cdiv(NN * 32, 256), 256>>>(edgeH, edgeV, edgeS, nb_map, dinvB, segPB, offB,
                                             srtGB, srtWB, b2, nodeO, 256, poolB, NN);
    // L10: Wo2
    {
        int gx = cdiv(NN, 128);
        dim3 g(gx, 1);
        wgemm_k<8, 128, 1, 0><<<g, 256, SMAB128>>>(poolB, NN, WO2h, WO2l, nullptr,
                                                   nodeO + 128, nullptr, 256, gx, xnone);
    }

    // L11: classifier + fused log-softmax
    {
        int gx = cdiv(NN, 128);
        dim3 g(gx, 1);
        wgemm_k<16, 64, 2, 0><<<g, 256, SMCLS>>>(nodeO, NN, WCh, WCl, clsb,
                                                 out, nullptr, 40, gx, xnone);
    }
}

// round 8
// speedup vs baseline: 1.8923x; 1.0257x over previous
#include <cuda_runtime.h>
#include <cuda_bf16.h>
#include <mma.h>
#include <cstdint>
#include <cstddef>
#include <math_constants.h>

using namespace nvcuda;

// ---------------- problem constants ----------------
#define NN 50000
#define NE 25000
#define PE 400000
#define ME 800000
#define PN 400000
#define MN 800000
#define NNP 50048
#define NEP 25088

static __host__ __device__ constexpr size_t alup(size_t x) { return (x + 255) & ~size_t(255); }

// ---------------- scratch layout ----------------
constexpr size_t O_NODEH = 0;
constexpr size_t O_NODEV = O_NODEH + alup((size_t)NNP * 128 * 4);
constexpr size_t O_NODES = O_NODEV + alup((size_t)NNP * 128 * 4);
constexpr size_t O_DEGA  = O_NODES + alup((size_t)NN * 4 * 4);
constexpr size_t O_DINVA = O_DEGA  + alup((size_t)PE * 4);
constexpr size_t O_SEGPA = O_DINVA + alup((size_t)PE * 4);
constexpr size_t O_CNTA  = O_SEGPA + alup((size_t)(NE + 1) * 4);
constexpr size_t O_OFFA  = O_CNTA  + alup((size_t)NE * 4);
constexpr size_t O_CURA  = O_OFFA  + alup((size_t)(NE + 1) * 4);
constexpr size_t O_SRTGA = O_CURA  + alup((size_t)NE * 4);
constexpr size_t O_SRTWA = O_SRTGA + alup((size_t)ME * 4);
constexpr size_t O_POOLA = O_SRTWA + alup((size_t)ME * 4);
constexpr size_t O_EDGEX = O_POOLA + alup((size_t)NE * 128 * 4);
constexpr size_t O_EDGEH = O_EDGEX + alup((size_t)NEP * 256 * 4);
constexpr size_t O_EDGEV = O_EDGEH + alup((size_t)NEP * 128 * 4);
constexpr size_t O_EDGES = O_EDGEV + alup((size_t)NEP * 128 * 4);
constexpr size_t O_DEGB  = O_EDGES + alup((size_t)NE * 4 * 4);
constexpr size_t O_DINVB = O_DEGB  + alup((size_t)PN * 4);
constexpr size_t O_SEGPB = O_DINVB + alup((size_t)PN * 4);
constexpr size_t O_CNTB  = O_SEGPB + alup((size_t)(NN + 1) * 4);
constexpr size_t O_OFFB  = O_CNTB  + alup((size_t)NN * 4);
constexpr size_t O_CURB  = O_OFFB  + alup((size_t)(NN + 1) * 4);
constexpr size_t O_SRTGB = O_CURB  + alup((size_t)NN * 4);
constexpr size_t O_SRTWB = O_SRTGB + alup((size_t)MN * 4);
constexpr size_t O_POOLB = O_SRTWB + alup((size_t)MN * 4);
constexpr size_t O_NODEO = O_POOLB + alup((size_t)NN * 128 * 4);
constexpr size_t O_WKSA  = O_NODEO + alup((size_t)NNP * 256 * 4);
constexpr size_t O_WKSB  = O_WKSA  + alup((size_t)128 * 4 * 4);
constexpr size_t O_INCLA = O_WKSB  + alup((size_t)256 * 4 * 4);
constexpr size_t O_BSUMA = O_INCLA + alup((size_t)NE * 4);
constexpr size_t O_INCLB = O_BSUMA + alup((size_t)64 * 4);
constexpr size_t O_BSUMB = O_INCLB + alup((size_t)NN * 4);
constexpr size_t O_WAH   = O_BSUMB + alup((size_t)64 * 4);
constexpr size_t O_WAL   = O_WAH   + alup((size_t)256 * 128 * 2);
constexpr size_t O_WO1H  = O_WAL   + alup((size_t)256 * 128 * 2);
constexpr size_t O_WO1L  = O_WO1H  + alup((size_t)128 * 128 * 2);
constexpr size_t O_WBH   = O_WO1L  + alup((size_t)128 * 128 * 2);
constexpr size_t O_WBL   = O_WBH   + alup((size_t)256 * 256 * 2);
constexpr size_t O_WO2H  = O_WBL   + alup((size_t)256 * 256 * 2);
constexpr size_t O_WO2L  = O_WO2H  + alup((size_t)128 * 128 * 2);
constexpr size_t O_WCH   = O_WO2L  + alup((size_t)128 * 128 * 2);
constexpr size_t O_WCL   = O_WCH   + alup((size_t)64 * 256 * 2);
constexpr size_t SCRATCH_TOTAL = O_WCL + alup((size_t)64 * 256 * 2);

__device__ __align__(256) unsigned char g_scratch[SCRATCH_TOTAL];

// ---------------- shared device helpers ----------------
__device__ __forceinline__ void cp16(void* smem_dst, const void* gsrc) {
    uint32_t sa = (uint32_t)__cvta_generic_to_shared(smem_dst);
    asm volatile("cp.async.cg.shared.global [%0], [%1], 16;" :: "r"(sa), "l"(gsrc));
}
#define CP_COMMIT() asm volatile("cp.async.commit_group;" ::: "memory")
#define CP_WAIT0()  asm volatile("cp.async.wait_group 0;" ::: "memory")

__device__ __forceinline__ void cvt_store(const float* W, int N, int i,
                                          __nv_bfloat16* hi, __nv_bfloat16* lo,
                                          int n_off, int ldK) {
    int k = i / N, n = i % N;
    float v = W[i];
    __nv_bfloat16 h = __float2bfloat16(v);
    float r = v - __bfloat162float(h);
    hi[(size_t)(n_off + n) * ldK + k] = h;
    lo[(size_t)(n_off + n) * ldK + k] = __float2bfloat16(r);
}

__device__ __forceinline__ void fold_one(const float* Wk, const float* seed,
                                         float* Wks, int i) {
    int f = i >> 2, h = i & 3;
    float s = 0.f;
    #pragma unroll
    for (int d = 0; d < 32; d++) s += Wk[(size_t)f * 128 + h * 32 + d] * seed[h * 32 + d];
    Wks[i] = s * 0.17677669529663687f;
}

__device__ __forceinline__ void rowdot_body(const float* __restrict__ X,
                                            const float* __restrict__ Wks,
                                            float* __restrict__ out,
                                            int row, int K, int lane) {
    const float* x = X + (size_t)row * K;
    float a0 = 0, a1 = 0, a2 = 0, a3 = 0;
    for (int f0 = lane * 4; f0 < K; f0 += 128) {
        float4 xv = *(const float4*)&x[f0];
        float4 w0 = *(const float4*)&Wks[(size_t)(f0 + 0) * 4];
        float4 w1 = *(const float4*)&Wks[(size_t)(f0 + 1) * 4];
        float4 w2 = *(const float4*)&Wks[(size_t)(f0 + 2) * 4];
        float4 w3 = *(const float4*)&Wks[(size_t)(f0 + 3) * 4];
        a0 += xv.x * w0.x + xv.y * w1.x + xv.z * w2.x + xv.w * w3.x;
        a1 += xv.x * w0.y + xv.y * w1.y + xv.z * w2.y + xv.w * w3.y;
        a2 += xv.x * w0.z + xv.y * w1.z + xv.z * w2.z + xv.w * w3.z;
        a3 += xv.x * w0.w + xv.y * w1.w + xv.z * w2.w + xv.w * w3.w;
    }
    #pragma unroll
    for (int o = 16; o; o >>= 1) {
        a0 += __shfl_xor_sync(0xffffffffu, a0, o);
        a1 += __shfl_xor_sync(0xffffffffu, a1, o);
        a2 += __shfl_xor_sync(0xffffffffu, a2, o);
        a3 += __shfl_xor_sync(0xffffffffu, a3, o);
    }
    if (lane == 0) {
        float* o4 = out + (size_t)row * 4;
        o4[0] = a0; o4[1] = a1; o4[2] = a2; o4[3] = a3;
    }
}

__device__ __forceinline__ void seg_start_one(const int* __restrict__ batch, int P, int s,
                                              int* __restrict__ segP) {
    int lo = 0, hi = P;
    while (lo < hi) {
        int mid = (lo + hi) >> 1;
        if (batch[mid] < s) lo = mid + 1; else hi = mid;
    }
    segP[s] = lo;
}

// ---------------- misc0: init + seg_starts (both) + all weight prep ----------------
constexpr int M0_R1 = PE;
constexpr int M0_R2 = M0_R1 + PN;
constexpr int M0_R3 = M0_R2 + NE;
constexpr int M0_R4 = M0_R3 + NN;
constexpr int M0_R5 = M0_R4 + NE + 1;
constexpr int M0_R6 = M0_R5 + NN + 1;
constexpr int M0_R7 = M0_R6 + 148992;

__global__ void misc0_k(
    const int* __restrict__ eb_batch, const int* __restrict__ nb_batch,
    int* degA, int* cntA, int* curA, int* degB, int* cntB, int* curB,
    int* segPA, int* segPB,
    const float* __restrict__ W1, const float* __restrict__ Wv1, const float* __restrict__ Wo1,
    const float* __restrict__ W2, const float* __restrict__ Wv2, const float* __restrict__ Wo2,
    const float* __restrict__ clsW,
    const float* __restrict__ Wk1, const float* __restrict__ sd1,
    const float* __restrict__ Wk2, const float* __restrict__ sd2,
    __nv_bfloat16* WAh, __nv_bfloat16* WAl, __nv_bfloat16* WO1h, __nv_bfloat16* WO1l,
    __nv_bfloat16* WBh, __nv_bfloat16* WBl, __nv_bfloat16* WO2h, __nv_bfloat16* WO2l,
    __nv_bfloat16* WCh, __nv_bfloat16* WCl, float* WksA, float* WksB) {
    int i = blockIdx.x * blockDim.x + threadIdx.x;
    if (i < M0_R1)      degA[i] = 0;
    else if (i < M0_R2) degB[i - M0_R1] = 0;
    else if (i < M0_R3) { int j = i - M0_R2; cntA[j] = 0; curA[j] = 0; }
    else if (i < M0_R4) { int j = i - M0_R3; cntB[j] = 0; curB[j] = 0; }
    else if (i < M0_R5) seg_start_one(eb_batch, PE, i - M0_R4, segPA);
    else if (i < M0_R6) seg_start_one(nb_batch, PN, i - M0_R5, segPB);
    else if (i < M0_R7) {
        int j = i - M0_R6;
        if (j < 16384)       cvt_store(W1,  128, j, WAh, WAl, 0, 128);
        else if (j < 32768)  cvt_store(Wv1, 128, j - 16384, WAh, WAl, 128, 128);
        else if (j < 49152)  cvt_store(Wo1, 128, j - 32768, WO1h, WO1l, 0, 128);
        else if (j < 81920)  cvt_store(W2,  128, j - 49152, WBh, WBl, 0, 256);
        else if (j < 114688) cvt_store(Wv2, 128, j - 81920, WBh, WBl, 128, 256);
        else if (j < 131072) cvt_store(Wo2, 128, j - 114688, WO2h, WO2l, 0, 128);
        else if (j < 141312) cvt_store(clsW, 40, j - 131072, WCh, WCl, 0, 256);
        else if (j < 147456) {
            int q = j - 141312;
            size_t p = (size_t)(40 + q / 256) * 256 + (q % 256);
            WCh[p] = __float2bfloat16(0.f);
            WCl[p] = __float2bfloat16(0.f);
        }
        else if (j < 147968) fold_one(Wk1, sd1, WksA, j - 147456);
        else                 fold_one(Wk2, sd2, WksB, j - 147968);
    }
}

// ---------------- WMMA bf16 GEMM, 2-stage pipelined (hi/lo 3-term split) ----------------
struct XArgs {
    const int* dstA; const int* batA; int* degA; int* cntA;
    const int* dstB; const int* batB; int* degB; int* cntB;
    const float* X; const float* Wks; float* S; int M;
};

template<int KC, int NT, int MODE, int EXTRA>
__global__ void __launch_bounds__(256, 2)
wgemm_k(const float* __restrict__ A, int M,
        const __nv_bfloat16* __restrict__ Bhi, const __nv_bfloat16* __restrict__ Blo,
        const float* __restrict__ bias,
        float* __restrict__ out0, float* __restrict__ out1, int ldc,
        int gemmGX, XArgs xa) {
    if (EXTRA && blockIdx.x >= gemmGX) {
        if (blockIdx.y != 0) return;
        int id = (blockIdx.x - gemmGX) * 256 + threadIdx.x;
        if (EXTRA == 1) {
            if (id < ME) {
                int d = xa.dstA[id];
                atomicAdd(&xa.degA[d], 1);
                atomicAdd(&xa.cntA[xa.batA[d]], 1);
            } else if (id < ME + MN) {
                id -= ME;
                int d = xa.dstB[id];
                atomicAdd(&xa.degB[d], 1);
                atomicAdd(&xa.cntB[xa.batB[d]], 1);
            }
        } else {
            int gw = id >> 5;
            if (gw < xa.M) rowdot_body(xa.X, xa.Wks, xa.S, gw, 256, threadIdx.x & 31);
        }
        return;
    }

    constexpr int K = KC * 16;
    constexpr int WN = NT / 2;
    constexpr int NTI = WN / 16;
    constexpr int NTS = NT + 4;
    constexpr int STG_E = (256 + 2 * NT) * 24;   // elements per stage

    extern __shared__ char smc[];
    __nv_bfloat16* sb = (__nv_bfloat16*)smc;
    float* stg = (float*)smc;

    int tid = threadIdx.x;
    int wid = tid >> 5;
    int wm = wid >> 1, wn = wid & 1;
    int row0 = blockIdx.x * 128;
    int col0 = blockIdx.y * NT;

    int ar = tid >> 1, akk = (tid & 1) * 8;
    int gr = row0 + ar;
    const float* aptr = (gr < M) ? (A + (size_t)gr * K + akk) : nullptr;

    wmma::fragment<wmma::accumulator, 16, 16, 16, float> acc[2][NTI];
    #pragma unroll
    for (int m = 0; m < 2; m++)
        #pragma unroll
        for (int n = 0; n < NTI; n++) wmma::fill_fragment(acc[m][n], 0.0f);

    float4 pv0, pv1;
    // prime: load A0 regs, cp.async B0, convert/store A0
    {
        pv0 = make_float4(0.f, 0.f, 0.f, 0.f); pv1 = pv0;
        if (aptr) { pv0 = *(const float4*)aptr; pv1 = *(const float4*)(aptr + 4); }
        __nv_bfloat16* sBh0 = sb + 256 * 24;
        __nv_bfloat16* sBl0 = sBh0 + NT * 24;
        for (int i = tid; i < NT * 2; i += 256) {
            int n = i >> 1, kk = (i & 1) * 8;
            size_t g = (size_t)(col0 + n) * K + kk;
            cp16(&sBh0[n * 24 + kk], Bhi + g);
            cp16(&sBl0[n * 24 + kk], Blo + g);
        }
        CP_COMMIT();
        float vv[8] = {pv0.x, pv0.y, pv0.z, pv0.w, pv1.x, pv1.y, pv1.z, pv1.w};
        ushort hs[8], ls[8];
        #pragma unroll
        for (int q = 0; q < 8; q++) {
            __nv_bfloat16 h = __float2bfloat16(vv[q]);
            hs[q] = __bfloat16_as_ushort(h);
            ls[q] = __bfloat16_as_ushort(__float2bfloat16(vv[q] - __bfloat162float(h)));
        }
        uint4 hp, lp;
        hp.x = hs[0] | ((uint32_t)hs[1] << 16); hp.y = hs[2] | ((uint32_t)hs[3] << 16);
        hp.z = hs[4] | ((uint32_t)hs[5] << 16); hp.w = hs[6] | ((uint32_t)hs[7] << 16);
        lp.x = ls[0] | ((uint32_t)ls[1] << 16); lp.y = ls[2] | ((uint32_t)ls[3] << 16);
        lp.z = ls[4] | ((uint32_t)ls[5] << 16); lp.w = ls[6] | ((uint32_t)ls[7] << 16);
        *(uint4*)&sb[ar * 24 + akk] = hp;
        *(uint4*)&sb[128 * 24 + ar * 24 + akk] = lp;
    }

    for (int kc = 0; kc < KC; kc++) {
        int buf = kc & 1;
        __nv_bfloat16* sAh = sb + buf * STG_E;
        __nv_bfloat16* sAl = sAh + 128 * 24;
        __nv_bfloat16* sBh = sAl + 128 * 24;
        __nv_bfloat16* sBl = sBh + NT * 24;
        CP_WAIT0();
        __syncthreads();

        // prefetch next chunk: A -> regs (LDG in flight during MMA), B -> cp.async
        if (kc + 1 < KC) {
            pv0 = make_float4(0.f, 0.f, 0.f, 0.f); pv1 = pv0;
            if (aptr) {
                const float* ap = aptr + (kc + 1) * 16;
                pv0 = *(const float4*)ap; pv1 = *(const float4*)(ap + 4);
            }
            __nv_bfloat16* nBh = sb + (buf ^ 1) * STG_E + 256 * 24;
            __nv_bfloat16* nBl = nBh + NT * 24;
            for (int i = tid; i < NT * 2; i += 256) {
                int n = i >> 1, kk = (i & 1) * 8;
                size_t g = (size_t)(col0 + n) * K + (kc + 1) * 16 + kk;
                cp16(&nBh[n * 24 + kk], Bhi + g);
                cp16(&nBl[n * 24 + kk], Blo + g);
            }
            CP_COMMIT();
        }

        // MMA on current buffer
        wmma::fragment<wmma::matrix_a, 16, 16, 16, __nv_bfloat16, wmma::row_major> ah[2], al[2];
        #pragma unroll
        for (int m = 0; m < 2; m++) {
            wmma::load_matrix_sync(ah[m], sAh + (wm * 32 + m * 16) * 24, 24);
            wmma::load_matrix_sync(al[m], sAl + (wm * 32 + m * 16) * 24, 24);
        }
        #pragma unroll
        for (int n = 0; n < NTI; n++) {
            wmma::fragment<wmma::matrix_b, 16, 16, 16, __nv_bfloat16, wmma::col_major> bh, bl;
            wmma::load_matrix_sync(bh, sBh + (wn * WN + n * 16) * 24, 24);
            wmma::load_matrix_sync(bl, sBl + (wn * WN + n * 16) * 24, 24);
            #pragma unroll
            for (int m = 0; m < 2; m++) {
                wmma::mma_sync(acc[m][n], ah[m], bh, acc[m][n]);
                wmma::mma_sync(acc[m][n], ah[m], bl, acc[m][n]);
                wmma::mma_sync(acc[m][n], al[m], bh, acc[m][n]);
            }
        }

        // convert/store next A chunk into the other buffer (LDG done by now)
        if (kc + 1 < KC) {
            __nv_bfloat16* nAh = sb + (buf ^ 1) * STG_E;
            __nv_bfloat16* nAl = nAh + 128 * 24;
            float vv[8] = {pv0.x, pv0.y, pv0.z, pv0.w, pv1.x, pv1.y, pv1.z, pv1.w};
            ushort hs[8], ls[8];
            #pragma unroll
            for (int q = 0; q < 8; q++) {
                __nv_bfloat16 h = __float2bfloat16(vv[q]);
                hs[q] = __bfloat16_as_ushort(h);
                ls[q] = __bfloat16_as_ushort(__float2bfloat16(vv[q] - __bfloat162float(h)));
            }
            uint4 hp, lp;
            hp.x = hs[0] | ((uint32_t)hs[1] << 16); hp.y = hs[2] | ((uint32_t)hs[3] << 16);
            hp.z = hs[4] | ((uint32_t)hs[5] << 16); hp.w = hs[6] | ((uint32_t)hs[7] << 16);
            lp.x = ls[0] | ((uint32_t)ls[1] << 16); lp.y = ls[2] | ((uint32_t)ls[3] << 16);
            lp.z = ls[4] | ((uint32_t)ls[5] << 16); lp.w = ls[6] | ((uint32_t)ls[7] << 16);
            *(uint4*)&nAh[ar * 24 + akk] = hp;
            *(uint4*)&nAl[ar * 24 + akk] = lp;
        }
    }
    __syncthreads();

    if (MODE == 2) {
        #pragma unroll
        for (int m = 0; m < 2; m++)
            #pragma unroll
            for (int n = 0; n < NTI; n++)
                wmma::store_matrix_sync(stg + (wm * 32 + m * 16) * NTS + wn * WN + n * 16,
                                        acc[m][n], NTS, wmma::mem_row_major);
        __syncthreads();
        if (tid < 128) {
            int r = row0 + tid;
            if (r < M) {
                const float* row = stg + tid * NTS;
                float v[40];
                float mx = -CUDART_INF_F;
                #pragma unroll
                for (int c = 0; c < 40; c++) { v[c] = row[c] + bias[c]; mx = fmaxf(mx, v[c]); }
                float s = 0.f;
                #pragma unroll
                for (int c = 0; c < 40; c++) s += expf(v[c] - mx);
                float lse = mx + logf(s);
                #pragma unroll
                for (int c = 0; c < 40; c += 4) {
                    float4 f = make_float4(v[c] - lse, v[c+1] - lse, v[c+2] - lse, v[c+3] - lse);
                    *(float4*)&out0[(size_t)r * 40 + c] = f;
                }
            }
        }
    } else {
        #pragma unroll
        for (int m = 0; m < 2; m++) {
            int gr0 = row0 + wm * 32 + m * 16;
            #pragma unroll
            for (int n = 0; n < NTI; n++) {
                int gc = col0 + wn * WN + n * 16;
                if (MODE == 1) {
                    #pragma unroll
                    for (int t = 0; t < acc[m][n].num_elements; t++)
                        acc[m][n].x[t] = fmaxf(acc[m][n].x[t], 0.f);
                    wmma::store_matrix_sync(out0 + (size_t)gr0 * ldc + gc, acc[m][n],
                                            ldc, wmma::mem_row_major);
                } else {
                    float* dst = (gc < 128) ? (out0 + (size_t)gr0 * 128 + gc)
                                            : (out1 + (size_t)gr0 * 128 + gc - 128);
                    wmma::store_matrix_sync(dst, acc[m][n], 128, wmma::mem_row_major);
                }
            }
        }
    }
}

// ---------------- misc1: both scans + both dinv + rowdot4-A ----------------
constexpr int NBA = (NE + 1023) / 1024;
constexpr int NBB = (NN + 1023) / 1024;
constexpr int DINV_B = (PE + PN + 1023) / 1024;
constexpr int RDA_B = (NN + 31) / 32;

__device__ __forceinline__ void scan_body(const int* __restrict__ cnt, int n,
                                          int* __restrict__ incl, int* __restrict__ bsums,
                                          int b) {
    __shared__ int sm[1024];
    int i = b * 1024 + threadIdx.x;
    int v = (i < n) ? cnt[i] : 0;
    sm[threadIdx.x] = v;
    __syncthreads();
    for (int o = 1; o < 1024; o <<= 1) {
        int t = (threadIdx.x >= o) ? sm[threadIdx.x - o] : 0;
        __syncthreads();
        sm[threadIdx.x] += t;
        __syncthreads();
    }
    if (i < n) incl[i] = sm[threadIdx.x];
    if (threadIdx.x == 1023) bsums[b] = sm[1023];
}

__global__ void misc1_k(const int* __restrict__ cntA, int* inclA, int* bsumA,
                        const int* __restrict__ cntB, int* inclB, int* bsumB,
                        const int* __restrict__ degA, float* dinvA,
                        const int* __restrict__ degB, float* dinvB,
                        const float* __restrict__ X, const float* __restrict__ Wks,
                        float* S) {
    int b = blockIdx.x;
    if (b < NBA) { scan_body(cntA, NE, inclA, bsumA, b); return; }
    b -= NBA;
    if (b < NBB) { scan_body(cntB, NN, inclB, bsumB, b); return; }
    b -= NBB;
    if (b < DINV_B) {
        int i = b * 1024 + threadIdx.x;
        if (i < PE) dinvA[i] = rsqrtf((float)(degA[i] + 1));
        else if (i < PE + PN) dinvB[i - PE] = rsqrtf((float)(degB[i - PE] + 1));
        return;
    }
    b -= DINV_B;
    int gw = b * 32 + (threadIdx.x >> 5);
    if (gw < NN) rowdot_body(X, Wks, S, gw, 128, threadIdx.x & 31);
}

__global__ void fin2_k(const int* __restrict__ inclA, const int* __restrict__ bsumA, int* offA,
                       const int* __restrict__ inclB, const int* __restrict__ bsumB, int* offB) {
    __shared__ int pfx;
    int b = blockIdx.x;
    if (b < NBA) {
        if (threadIdx.x == 0) {
            int s = 0;
            for (int t = 0; t < b; t++) s += bsumA[t];
            pfx = s;
        }
        __syncthreads();
        int i = b * 1024 + threadIdx.x;
        if (i < NE) offA[i + 1] = inclA[i] + pfx;
        if (i == 0) offA[0] = 0;
    } else {
        b -= NBA;
        if (threadIdx.x == 0) {
            int s = 0;
            for (int t = 0; t < b; t++) s += bsumB[t];
            pfx = s;
        }
        __syncthreads();
        int i = b * 1024 + threadIdx.x;
        if (i < NN) offB[i + 1] = inclB[i] + pfx;
        if (i == 0) offB[0] = 0;
    }
}

__device__ __forceinline__ void scatter_one(const int* src, const int* dst, const int* batch,
                                            const int* map, const float* dinv, const int* off,
                                            int* cursor, int i, int* outG, float* outW) {
    int d = dst[i];
    int s = batch[d];
    int pos = off[s] + atomicAdd(&cursor[s], 1);
    int sc = src[i];
    outG[pos] = map[sc];
    outW[pos] = dinv[sc] * dinv[d];
}

__global__ void scatter2_k(const int* eb_ei, const int* eb_batch, const int* eb_map,
                           const float* dinvA, const int* offA, int* curA,
                           int* srtGA, float* srtWA,
                           const int* nb_ei, const int* nb_batch, const int* nb_map,
                           const float* dinvB, const int* offB, int* curB,
                           int* srtGB, float* srtWB) {
    int i = blockIdx.x * blockDim.x + threadIdx.x;
    if (i < ME)
        scatter_one(eb_ei, eb_ei + ME, eb_batch, eb_map, dinvA, offA, curA, i, srtGA, srtWA);
    else if (i < ME + MN)
        scatter_one(nb_ei, nb_ei + MN, nb_batch, nb_map, dinvB, offB, curB, i - ME, srtGB, srtWB);
}

// ---------------- fused per-segment: GCN-conv mean + PMA softmax pool ----------------
__global__ void seg_fused_k(const float* __restrict__ H, const float* __restrict__ V,
                            const float* __restrict__ S4, const int* __restrict__ map,
                            const float* __restrict__ dinv,
                            const int* __restrict__ segP, const int* __restrict__ eOff,
                            const int* __restrict__ sG, const float* __restrict__ sW,
                            const float* __restrict__ bias,
                            float* __restrict__ outConv, int ldOut,
                            float* __restrict__ pooled, int S) {
    int w = (blockIdx.x * blockDim.x + threadIdx.x) >> 5;
    if (w >= S) return;
    int lane = threadIdx.x & 31;
    int h = lane >> 3;
    int sub = lane & 7;
    int s = w;
    const float4* H4 = (const float4*)H;
    const float4* V4 = (const float4*)V;

    int p0 = segP[s], p1 = segP[s + 1];
    int e0 = eOff[s], e1 = eOff[s + 1];

    float4 acc = make_float4(0.f, 0.f, 0.f, 0.f);
    int j = e0;
    for (; j + 3 < e1; j += 4) {
        int g0 = sG[j], g1 = sG[j + 1], g2 = sG[j + 2], g3 = sG[j + 3];
        float w0 = sW[j], w1 = sW[j + 1], w2 = sW[j + 2], w3 = sW[j + 3];
        float4 h0 = H4[(size_t)g0 * 32 + lane];
        float4 h1 = H4[(size_t)g1 * 32 + lane];
        float4 h2 = H4[(size_t)g2 * 32 + lane];
        float4 h3 = H4[(size_t)g3 * 32 + lane];
        acc.x += h0.x * w0 + h1.x * w1 + h2.x * w2 + h3.x * w3;
        acc.y += h0.y * w0 + h1.y * w1 + h2.y * w2 + h3.y * w3;
        acc.z += h0.z * w0 + h1.z * w1 + h2.z * w2 + h3.z * w3;
        acc.w += h0.w * w0 + h1.w * w1 + h2.w * w2 + h3.w * w3;
    }
    for (; j < e1; j++) {
        int g = sG[j]; float wt = sW[j];
        float4 hv = H4[(size_t)g * 32 + lane];
        acc.x += hv.x * wt; acc.y += hv.y * wt; acc.z += hv.z * wt; acc.w += hv.w * wt;
    }

    float m = -CUDART_INF_F;
    for (int p = p0 + sub; p < p1; p += 8)
        m = fmaxf(m, S4[(size_t)map[p] * 4 + h]);
    #pragma unroll
    for (int o = 1; o < 8; o <<= 1)
        m = fmaxf(m, __shfl_xor_sync(0xffffffffu, m, o));

    float den = 0.f;
    float4 pv = make_float4(0.f, 0.f, 0.f, 0.f);
    int p = p0;
    for (; p + 1 < p1; p += 2) {
        int ga = map[p], gb = map[p + 1];
        float da = dinv[p], db = dinv[p + 1];
        float wa = da * da, wb = db * db;
        float ea = __expf(S4[(size_t)ga * 4 + h] - m);
        float eb = __expf(S4[(size_t)gb * 4 + h] - m);
        den += ea + eb;
        float4 ha = H4[(size_t)ga * 32 + lane];
        float4 hb = H4[(size_t)gb * 32 + lane];
        float4 va = V4[(size_t)ga * 32 + lane];
        float4 vb = V4[(size_t)gb * 32 + lane];
        acc.x += ha.x * wa + hb.x * wb;  pv.x += va.x * ea + vb.x * eb;
        acc.y += ha.y * wa + hb.y * wb;  pv.y += va.y * ea + vb.y * eb;
        acc.z += ha.z * wa + hb.z * wb;  pv.z += va.z * ea + vb.z * eb;
        acc.w += ha.w * wa + hb.w * wb;  pv.w += va.w * ea + vb.w * eb;
    }
    for (; p < p1; p++) {
        int g = map[p];
        float d = dinv[p];
        float wt = d * d;
        float e = __expf(S4[(size_t)g * 4 + h] - m);
        den += e;
        float4 hv = H4[(size_t)g * 32 + lane];
        float4 vv = V4[(size_t)g * 32 + lane];
        acc.x += hv.x * wt;  pv.x += vv.x * e;
        acc.y += hv.y * wt;  pv.y += vv.y * e;
        acc.z += hv.z * wt;  pv.z += vv.z * e;
        acc.w += hv.w * wt;  pv.w += vv.w * e;
    }

    int cnt = p1 - p0;
    float4 ob;
    if (cnt > 0) {
        float inv = 1.f / (float)cnt;
        float4 b4 = *(const float4*)&bias[lane * 4];
        ob.x = fmaxf(acc.x * inv + b4.x, 0.f);
        ob.y = fmaxf(acc.y * inv + b4.y, 0.f);
        ob.z = fmaxf(acc.z * inv + b4.z, 0.f);
        ob.w = fmaxf(acc.w * inv + b4.w, 0.f);
    } else {
        ob = make_float4(0.f, 0.f, 0.f, 0.f);
    }
    *(float4*)&outConv[(size_t)s * ldOut + lane * 4] = ob;

    float dn = 1.f / fmaxf(den, 1e-9f);
    float4 op;
    op.x = pv.x * dn; op.y = pv.y * dn; op.z = pv.z * dn; op.w = pv.w * dn;
    if (cnt == 0) op = make_float4(0.f, 0.f, 0.f, 0.f);
    *(float4*)&pooled[(size_t)s * 128 + lane * 4] = op;
}

// ---------------- orchestration (single stream, graph-safe) ----------------
static inline int cdiv(int a, int b) { return (a + b - 1) / b; }

extern "C" void kernel_launch(void* const* d_in, const int* in_sizes, int n_in,
                              void* d_out, int out_size) {
    (void)in_sizes; (void)n_in; (void)out_size;
    const float* node_x  = (const float*)d_in[0];
    const int* eb_map    = (const int*)d_in[1];
    const int* eb_ei     = (const int*)d_in[2];
    const int* eb_batch  = (const int*)d_in[3];
    const int* nb_map    = (const int*)d_in[4];
    const int* nb_ei     = (const int*)d_in[5];
    const int* nb_batch  = (const int*)d_in[6];
    const float* W1   = (const float*)d_in[7];
    const float* b1   = (const float*)d_in[8];
    const float* Wk1  = (const float*)d_in[9];
    const float* Wv1  = (const float*)d_in[10];
    const float* sd1  = (const float*)d_in[11];
    const float* Wo1  = (const float*)d_in[12];
    const float* W2   = (const float*)d_in[13];
    const float* b2   = (const float*)d_in[14];
    const float* Wk2  = (const float*)d_in[15];
    const float* Wv2  = (const float*)d_in[16];
    const float* sd2  = (const float*)d_in[17];
    const float* Wo2  = (const float*)d_in[18];
    const float* clsW = (const float*)d_in[19];
    const float* clsb = (const float*)d_in[20];
    float* out = (float*)d_out;

    void* basep = nullptr;
    cudaGetSymbolAddress(&basep, g_scratch);
    char* base = (char*)basep;
    float* nodeH  = (float*)(base + O_NODEH);
    float* nodeV  = (float*)(base + O_NODEV);
    float* nodeS  = (float*)(base + O_NODES);
    int*   degA   = (int*)  (base + O_DEGA);
    float* dinvA  = (float*)(base + O_DINVA);
    int*   segPA  = (int*)  (base + O_SEGPA);
    int*   cntA   = (int*)  (base + O_CNTA);
    int*   offA   = (int*)  (base + O_OFFA);
    int*   curA   = (int*)  (base + O_CURA);
    int*   srtGA  = (int*)  (base + O_SRTGA);
    float* srtWA  = (float*)(base + O_SRTWA);
    float* poolA  = (float*)(base + O_POOLA);
    float* edgeX  = (float*)(base + O_EDGEX);
    float* edgeH  = (float*)(base + O_EDGEH);
    float* edgeV  = (float*)(base + O_EDGEV);
    float* edgeS  = (float*)(base + O_EDGES);
    int*   degB   = (int*)  (base + O_DEGB);
    float* dinvB  = (float*)(base + O_DINVB);
    int*   segPB  = (int*)  (base + O_SEGPB);
    int*   cntB   = (int*)  (base + O_CNTB);
    int*   offB   = (int*)  (base + O_OFFB);
    int*   curB   = (int*)  (base + O_CURB);
    int*   srtGB  = (int*)  (base + O_SRTGB);
    float* srtWB  = (float*)(base + O_SRTWB);
    float* poolB  = (float*)(base + O_POOLB);
    float* nodeO  = (float*)(base + O_NODEO);
    float* WksA   = (float*)(base + O_WKSA);
    float* WksB   = (float*)(base + O_WKSB);
    int*   inclA  = (int*)  (base + O_INCLA);
    int*   bsumA  = (int*)  (base + O_BSUMA);
    int*   inclB  = (int*)  (base + O_INCLB);
    int*   bsumB  = (int*)  (base + O_BSUMB);
    __nv_bfloat16* WAh  = (__nv_bfloat16*)(base + O_WAH);
    __nv_bfloat16* WAl  = (__nv_bfloat16*)(base + O_WAL);
    __nv_bfloat16* WO1h = (__nv_bfloat16*)(base + O_WO1H);
    __nv_bfloat16* WO1l = (__nv_bfloat16*)(base + O_WO1L);
    __nv_bfloat16* WBh  = (__nv_bfloat16*)(base + O_WBH);
    __nv_bfloat16* WBl  = (__nv_bfloat16*)(base + O_WBL);
    __nv_bfloat16* WO2h = (__nv_bfloat16*)(base + O_WO2H);
    __nv_bfloat16* WO2l = (__nv_bfloat16*)(base + O_WO2L);
    __nv_bfloat16* WCh  = (__nv_bfloat16*)(base + O_WCH);
    __nv_bfloat16* WCl  = (__nv_bfloat16*)(base + O_WCL);

    constexpr int SMAB128 = 2 * (256 + 2 * 128) * 24 * 2;  // 49152 (two stages)
    constexpr int SMCLS   = 2 * (256 + 2 * 64) * 24 * 2;   // 36864 (>= 34816 staging)
    cudaFuncSetAttribute(wgemm_k<8, 128, 0, 1>,  cudaFuncAttributeMaxDynamicSharedMemorySize, SMAB128);
    cudaFuncSetAttribute(wgemm_k<8, 128, 1, 0>,  cudaFuncAttributeMaxDynamicSharedMemorySize, SMAB128);
    cudaFuncSetAttribute(wgemm_k<16, 128, 0, 2>, cudaFuncAttributeMaxDynamicSharedMemorySize, SMAB128);
    cudaFuncSetAttribute(wgemm_k<16, 64, 2, 0>,  cudaFuncAttributeMaxDynamicSharedMemorySize, SMCLS);

    XArgs xnone = {};
    XArgs xdeg = { eb_ei + ME, eb_batch, degA, cntA,
                   nb_ei + MN, nb_batch, degB, cntB,
                   nullptr, nullptr, nullptr, 0 };
    XArgs xrdB = { nullptr, nullptr, nullptr, nullptr,
                   nullptr, nullptr, nullptr, nullptr,
                   edgeX, WksB, edgeS, NE };

    // L1: init + seg_starts + all weight prep
    misc0_k<<<cdiv(M0_R7, 256), 256>>>(eb_batch, nb_batch,
                                       degA, cntA, curA, degB, cntB, curB, segPA, segPB,
                                       W1, Wv1, Wo1, W2, Wv2, Wo2, clsW,
                                       Wk1, sd1, Wk2, sd2,
                                       WAh, WAl, WO1h, WO1l, WBh, WBl,
                                       WO2h, WO2l, WCh, WCl, WksA, WksB);

    // L2: stage-A GEMM  ∥  degcount (both stages)
    {
        int gx = cdiv(NN, 128);
        int extra = cdiv(ME + MN, 256);
        dim3 g(gx + extra, 2);
        wgemm_k<8, 128, 0, 1><<<g, 256, SMAB128>>>(node_x, NN, WAh, WAl, nullptr,
                                                   nodeH, nodeV, 0, gx, xdeg);
    }

    // L3: both scans + both dinv + rowdot4-A
    misc1_k<<<NBA + NBB + DINV_B + RDA_B, 1024>>>(cntA, inclA, bsumA, cntB, inclB, bsumB,
                                                  degA, dinvA, degB, dinvB,
                                                  node_x, WksA, nodeS);
    // L4: finalize offsets
    fin2_k<<<NBA + NBB, 1024>>>(inclA, bsumA, offA, inclB, bsumB, offB);

    // L5: both scatters
    scatter2_k<<<cdiv(ME + MN, 256), 256>>>(eb_ei, eb_batch, eb_map, dinvA, offA, curA,
                                            srtGA, srtWA,
                                            nb_ei, nb_batch, nb_map, dinvB, offB, curB,
                                            srtGB, srtWB);

    // L6: stage-A fused segment kernel
    seg_fused_k<<<cdiv(NE * 32, 256), 256>>>(nodeH, nodeV, nodeS, eb_map, dinvA, segPA, offA,
                                             srtGA, srtWA, b1, edgeX, 256, poolA, NE);
    // L7: Wo1
    {
        int gx = cdiv(NE, 128);
        dim3 g(gx, 1);
        wgemm_k<8, 128, 1, 0><<<g, 256, SMAB128>>>(poolA, NE, WO1h, WO1l, nullptr,
                                                   edgeX + 128, nullptr, 256, gx, xnone);
    }

    // L8: stage-B GEMM  ∥  rowdot4-B
    {
        int gx = cdiv(NE, 128);
        int extra = cdiv(NE * 32, 256);
        dim3 g(gx + extra, 2);
        wgemm_k<16, 128, 0, 2><<<g, 256, SMAB128>>>(edgeX, NE, WBh, WBl, nullptr,
                                                    edgeH, edgeV, 0, gx, xrdB);
    }

    // L9: stage-B fused segment kernel
    seg_fused_k<<<cdiv(NN * 32, 256), 256>>>(edgeH, edgeV, edgeS, nb_map, dinvB, segPB, offB,
                                             srtGB, srtWB, b2, nodeO, 256, poolB, NN);
    // L10: Wo2
    {
        int gx = cdiv(NN, 128);
        dim3 g(gx, 1);
        wgemm_k<8, 128, 1, 0><<<g, 256, SMAB128>>>(poolB, NN, WO2h, WO2l, nullptr,
                                                   nodeO + 128, nullptr, 256, gx, xnone);
    }

    // L11: classifier + fused log-softmax
    {
        int gx = cdiv(NN, 128);
        dim3 g(gx, 1);
        wgemm_k<16, 64, 2, 0><<<g, 256, SMCLS>>>(nodeO, NN, WCh, WCl, clsb,
                                                 out, nullptr, 40, gx, xnone);
    }
}

// round 10
// speedup vs baseline: 1.9341x; 1.0221x over previous
#include <cuda_runtime.h>
#include <cuda_bf16.h>
#include <mma.h>
#include <cstdint>
#include <cstddef>
#include <math_constants.h>

using namespace nvcuda;

// ---------------- problem constants ----------------
#define NN 50000
#define NE 25000
#define PE 400000
#define ME 800000
#define PN 400000
#define MN 800000
#define NNP 50048
#define NEP 25088

static __host__ __device__ constexpr size_t alup(size_t x) { return (x + 255) & ~size_t(255); }

// ---------------- scratch layout ----------------
constexpr size_t O_NODEH = 0;
constexpr size_t O_NODEV = O_NODEH + alup((size_t)NNP * 128 * 4);
constexpr size_t O_NODES = O_NODEV + alup((size_t)NNP * 128 * 4);
constexpr size_t O_DEGA  = O_NODES + alup((size_t)NN * 4 * 4);
constexpr size_t O_DINVA = O_DEGA  + alup((size_t)PE * 4);
constexpr size_t O_SEGPA = O_DINVA + alup((size_t)PE * 4);
constexpr size_t O_CNTA  = O_SEGPA + alup((size_t)(NE + 1) * 4);
constexpr size_t O_OFFA  = O_CNTA  + alup((size_t)NE * 4);
constexpr size_t O_CURA  = O_OFFA  + alup((size_t)(NE + 1) * 4);
constexpr size_t O_SRTGA = O_CURA  + alup((size_t)NE * 4);
constexpr size_t O_SRTWA = O_SRTGA + alup((size_t)ME * 4);
constexpr size_t O_POOLA = O_SRTWA + alup((size_t)ME * 4);
constexpr size_t O_EDGEX = O_POOLA + alup((size_t)NE * 128 * 4);
constexpr size_t O_EDGEH = O_EDGEX + alup((size_t)NEP * 256 * 4);
constexpr size_t O_EDGEV = O_EDGEH + alup((size_t)NEP * 128 * 4);
constexpr size_t O_EDGES = O_EDGEV + alup((size_t)NEP * 128 * 4);
constexpr size_t O_DEGB  = O_EDGES + alup((size_t)NE * 4 * 4);
constexpr size_t O_DINVB = O_DEGB  + alup((size_t)PN * 4);
constexpr size_t O_SEGPB = O_DINVB + alup((size_t)PN * 4);
constexpr size_t O_CNTB  = O_SEGPB + alup((size_t)(NN + 1) * 4);
constexpr size_t O_OFFB  = O_CNTB  + alup((size_t)NN * 4);
constexpr size_t O_CURB  = O_OFFB  + alup((size_t)(NN + 1) * 4);
constexpr size_t O_SRTGB = O_CURB  + alup((size_t)NN * 4);
constexpr size_t O_SRTWB = O_SRTGB + alup((size_t)MN * 4);
constexpr size_t O_POOLB = O_SRTWB + alup((size_t)MN * 4);
constexpr size_t O_NODEO = O_POOLB + alup((size_t)NN * 128 * 4);
constexpr size_t O_WKSA  = O_NODEO + alup((size_t)NNP * 256 * 4);
constexpr size_t O_WKSB  = O_WKSA  + alup((size_t)128 * 4 * 4);
constexpr size_t O_INCLA = O_WKSB  + alup((size_t)256 * 4 * 4);
constexpr size_t O_BSUMA = O_INCLA + alup((size_t)NE * 4);
constexpr size_t O_INCLB = O_BSUMA + alup((size_t)64 * 4);
constexpr size_t O_BSUMB = O_INCLB + alup((size_t)NN * 4);
constexpr size_t O_WAH   = O_BSUMB + alup((size_t)64 * 4);
constexpr size_t O_WAL   = O_WAH   + alup((size_t)256 * 128 * 2);
constexpr size_t O_WO1H  = O_WAL   + alup((size_t)256 * 128 * 2);
constexpr size_t O_WO1L  = O_WO1H  + alup((size_t)128 * 128 * 2);
constexpr size_t O_WBH   = O_WO1L  + alup((size_t)128 * 128 * 2);
constexpr size_t O_WBL   = O_WBH   + alup((size_t)256 * 256 * 2);
constexpr size_t O_WO2H  = O_WBL   + alup((size_t)256 * 256 * 2);
constexpr size_t O_WO2L  = O_WO2H  + alup((size_t)128 * 128 * 2);
constexpr size_t O_WCH   = O_WO2L  + alup((size_t)128 * 128 * 2);
constexpr size_t O_WCL   = O_WCH   + alup((size_t)64 * 256 * 2);
constexpr size_t SCRATCH_TOTAL = O_WCL + alup((size_t)64 * 256 * 2);

__device__ __align__(256) unsigned char g_scratch[SCRATCH_TOTAL];

// ---------------- shared device helpers ----------------
__device__ __forceinline__ void cp16(void* smem_dst, const void* gsrc) {
    uint32_t sa = (uint32_t)__cvta_generic_to_shared(smem_dst);
    asm volatile("cp.async.cg.shared.global [%0], [%1], 16;" :: "r"(sa), "l"(gsrc));
}
#define CP_COMMIT() asm volatile("cp.async.commit_group;" ::: "memory")
#define CP_WAIT0()  asm volatile("cp.async.wait_group 0;" ::: "memory")

__device__ __forceinline__ void cvt_store(const float* W, int N, int i,
                                          __nv_bfloat16* hi, __nv_bfloat16* lo,
                                          int n_off, int ldK) {
    int k = i / N, n = i % N;
    float v = W[i];
    __nv_bfloat16 h = __float2bfloat16(v);
    float r = v - __bfloat162float(h);
    hi[(size_t)(n_off + n) * ldK + k] = h;
    lo[(size_t)(n_off + n) * ldK + k] = __float2bfloat16(r);
}

__device__ __forceinline__ void fold_one(const float* Wk, const float* seed,
                                         float* Wks, int i) {
    int f = i >> 2, h = i & 3;
    float s = 0.f;
    #pragma unroll
    for (int d = 0; d < 32; d++) s += Wk[(size_t)f * 128 + h * 32 + d] * seed[h * 32 + d];
    Wks[i] = s * 0.17677669529663687f;
}

__device__ __forceinline__ void rowdot_body(const float* __restrict__ X,
                                            const float* __restrict__ Wks,
                                            float* __restrict__ out,
                                            int row, int K, int lane) {
    const float* x = X + (size_t)row * K;
    float a0 = 0, a1 = 0, a2 = 0, a3 = 0;
    for (int f0 = lane * 4; f0 < K; f0 += 128) {
        float4 xv = *(const float4*)&x[f0];
        float4 w0 = *(const float4*)&Wks[(size_t)(f0 + 0) * 4];
        float4 w1 = *(const float4*)&Wks[(size_t)(f0 + 1) * 4];
        float4 w2 = *(const float4*)&Wks[(size_t)(f0 + 2) * 4];
        float4 w3 = *(const float4*)&Wks[(size_t)(f0 + 3) * 4];
        a0 += xv.x * w0.x + xv.y * w1.x + xv.z * w2.x + xv.w * w3.x;
        a1 += xv.x * w0.y + xv.y * w1.y + xv.z * w2.y + xv.w * w3.y;
        a2 += xv.x * w0.z + xv.y * w1.z + xv.z * w2.z + xv.w * w3.z;
        a3 += xv.x * w0.w + xv.y * w1.w + xv.z * w2.w + xv.w * w3.w;
    }
    #pragma unroll
    for (int o = 16; o; o >>= 1) {
        a0 += __shfl_xor_sync(0xffffffffu, a0, o);
        a1 += __shfl_xor_sync(0xffffffffu, a1, o);
        a2 += __shfl_xor_sync(0xffffffffu, a2, o);
        a3 += __shfl_xor_sync(0xffffffffu, a3, o);
    }
    if (lane == 0) {
        float* o4 = out + (size_t)row * 4;
        o4[0] = a0; o4[1] = a1; o4[2] = a2; o4[3] = a3;
    }
}

__device__ __forceinline__ void seg_start_one(const int* __restrict__ batch, int P, int s,
                                              int* __restrict__ segP) {
    int lo = 0, hi = P;
    while (lo < hi) {
        int mid = (lo + hi) >> 1;
        if (batch[mid] < s) lo = mid + 1; else hi = mid;
    }
    segP[s] = lo;
}

// ---------------- misc0 ----------------
constexpr int M0_R1 = PE;
constexpr int M0_R2 = M0_R1 + PN;
constexpr int M0_R3 = M0_R2 + NE;
constexpr int M0_R4 = M0_R3 + NN;
constexpr int M0_R5 = M0_R4 + NE + 1;
constexpr int M0_R6 = M0_R5 + NN + 1;
constexpr int M0_R7 = M0_R6 + 148992;

__global__ void misc0_k(
    const int* __restrict__ eb_batch, const int* __restrict__ nb_batch,
    int* degA, int* cntA, int* curA, int* degB, int* cntB, int* curB,
    int* segPA, int* segPB,
    const float* __restrict__ W1, const float* __restrict__ Wv1, const float* __restrict__ Wo1,
    const float* __restrict__ W2, const float* __restrict__ Wv2, const float* __restrict__ Wo2,
    const float* __restrict__ clsW,
    const float* __restrict__ Wk1, const float* __restrict__ sd1,
    const float* __restrict__ Wk2, const float* __restrict__ sd2,
    __nv_bfloat16* WAh, __nv_bfloat16* WAl, __nv_bfloat16* WO1h, __nv_bfloat16* WO1l,
    __nv_bfloat16* WBh, __nv_bfloat16* WBl, __nv_bfloat16* WO2h, __nv_bfloat16* WO2l,
    __nv_bfloat16* WCh, __nv_bfloat16* WCl, float* WksA, float* WksB) {
    int i = blockIdx.x * blockDim.x + threadIdx.x;
    if (i < M0_R1)      degA[i] = 0;
    else if (i < M0_R2) degB[i - M0_R1] = 0;
    else if (i < M0_R3) { int j = i - M0_R2; cntA[j] = 0; curA[j] = 0; }
    else if (i < M0_R4) { int j = i - M0_R3; cntB[j] = 0; curB[j] = 0; }
    else if (i < M0_R5) seg_start_one(eb_batch, PE, i - M0_R4, segPA);
    else if (i < M0_R6) seg_start_one(nb_batch, PN, i - M0_R5, segPB);
    else if (i < M0_R7) {
        int j = i - M0_R6;
        if (j < 16384)       cvt_store(W1,  128, j, WAh, WAl, 0, 128);
        else if (j < 32768)  cvt_store(Wv1, 128, j - 16384, WAh, WAl, 128, 128);
        else if (j < 49152)  cvt_store(Wo1, 128, j - 32768, WO1h, WO1l, 0, 128);
        else if (j < 81920)  cvt_store(W2,  128, j - 49152, WBh, WBl, 0, 256);
        else if (j < 114688) cvt_store(Wv2, 128, j - 81920, WBh, WBl, 128, 256);
        else if (j < 131072) cvt_store(Wo2, 128, j - 114688, WO2h, WO2l, 0, 128);
        else if (j < 141312) cvt_store(clsW, 40, j - 131072, WCh, WCl, 0, 256);
        else if (j < 147456) {
            int q = j - 141312;
            size_t p = (size_t)(40 + q / 256) * 256 + (q % 256);
            WCh[p] = __float2bfloat16(0.f);
            WCl[p] = __float2bfloat16(0.f);
        }
        else if (j < 147968) fold_one(Wk1, sd1, WksA, j - 147456);
        else                 fold_one(Wk2, sd2, WksB, j - 147968);
    }
}

// ---------------- WMMA bf16 GEMM, 2-stage pipelined (hi/lo 3-term split) ----------------
struct XArgs {
    const int* dstA; const int* batA; int* degA; int* cntA;
    const int* dstB; const int* batB; int* degB; int* cntB;
    const float* X; const float* Wks; float* S; int M;
};

template<int KC, int NT, int MODE, int EXTRA>
__global__ void __launch_bounds__(256, 2)
wgemm_k(const float* __restrict__ A, int M,
        const __nv_bfloat16* __restrict__ Bhi, const __nv_bfloat16* __restrict__ Blo,
        const float* __restrict__ bias,
        float* __restrict__ out0, float* __restrict__ out1, int ldc,
        int gemmGX, XArgs xa) {
    if (EXTRA && blockIdx.x >= gemmGX) {
        if (blockIdx.y != 0) return;
        int id = (blockIdx.x - gemmGX) * 256 + threadIdx.x;
        if (EXTRA == 1) {
            if (id < ME) {
                int d = xa.dstA[id];
                atomicAdd(&xa.degA[d], 1);
                atomicAdd(&xa.cntA[xa.batA[d]], 1);
            } else if (id < ME + MN) {
                id -= ME;
                int d = xa.dstB[id];
                atomicAdd(&xa.degB[d], 1);
                atomicAdd(&xa.cntB[xa.batB[d]], 1);
            }
        } else {
            int gw = id >> 5;
            if (gw < xa.M) rowdot_body(xa.X, xa.Wks, xa.S, gw, 256, threadIdx.x & 31);
        }
        return;
    }

    constexpr int K = KC * 16;
    constexpr int WN = NT / 2;
    constexpr int NTI = WN / 16;
    constexpr int NTS = NT + 4;
    constexpr int STG_E = (256 + 2 * NT) * 24;

    extern __shared__ char smc[];
    __nv_bfloat16* sb = (__nv_bfloat16*)smc;
    float* stg = (float*)smc;

    int tid = threadIdx.x;
    int wid = tid >> 5;
    int wm = wid >> 1, wn = wid & 1;
    int row0 = blockIdx.x * 128;
    int col0 = blockIdx.y * NT;

    int ar = tid >> 1, akk = (tid & 1) * 8;
    int gr = row0 + ar;
    const float* aptr = (gr < M) ? (A + (size_t)gr * K + akk) : nullptr;

    wmma::fragment<wmma::accumulator, 16, 16, 16, float> acc[2][NTI];
    #pragma unroll
    for (int m = 0; m < 2; m++)
        #pragma unroll
        for (int n = 0; n < NTI; n++) wmma::fill_fragment(acc[m][n], 0.0f);

    float4 pv0, pv1;
    {
        pv0 = make_float4(0.f, 0.f, 0.f, 0.f); pv1 = pv0;
        if (aptr) { pv0 = *(const float4*)aptr; pv1 = *(const float4*)(aptr + 4); }
        __nv_bfloat16* sBh0 = sb + 256 * 24;
        __nv_bfloat16* sBl0 = sBh0 + NT * 24;
        for (int i = tid; i < NT * 2; i += 256) {
            int n = i >> 1, kk = (i & 1) * 8;
            size_t g = (size_t)(col0 + n) * K + kk;
            cp16(&sBh0[n * 24 + kk], Bhi + g);
            cp16(&sBl0[n * 24 + kk], Blo + g);
        }
        CP_COMMIT();
        float vv[8] = {pv0.x, pv0.y, pv0.z, pv0.w, pv1.x, pv1.y, pv1.z, pv1.w};
        ushort hs[8], ls[8];
        #pragma unroll
        for (int q = 0; q < 8; q++) {
            __nv_bfloat16 h = __float2bfloat16(vv[q]);
            hs[q] = __bfloat16_as_ushort(h);
            ls[q] = __bfloat16_as_ushort(__float2bfloat16(vv[q] - __bfloat162float(h)));
        }
        uint4 hp, lp;
        hp.x = hs[0] | ((uint32_t)hs[1] << 16); hp.y = hs[2] | ((uint32_t)hs[3] << 16);
        hp.z = hs[4] | ((uint32_t)hs[5] << 16); hp.w = hs[6] | ((uint32_t)hs[7] << 16);
        lp.x = ls[0] | ((uint32_t)ls[1] << 16); lp.y = ls[2] | ((uint32_t)ls[3] << 16);
        lp.z = ls[4] | ((uint32_t)ls[5] << 16); lp.w = ls[6] | ((uint32_t)ls[7] << 16);
        *(uint4*)&sb[ar * 24 + akk] = hp;
        *(uint4*)&sb[128 * 24 + ar * 24 + akk] = lp;
    }

    for (int kc = 0; kc < KC; kc++) {
        int buf = kc & 1;
        __nv_bfloat16* sAh = sb + buf * STG_E;
        __nv_bfloat16* sAl = sAh + 128 * 24;
        __nv_bfloat16* sBh = sAl + 128 * 24;
        __nv_bfloat16* sBl = sBh + NT * 24;
        CP_WAIT0();
        __syncthreads();

        if (kc + 1 < KC) {
            pv0 = make_float4(0.f, 0.f, 0.f, 0.f); pv1 = pv0;
            if (aptr) {
                const float* ap = aptr + (kc + 1) * 16;
                pv0 = *(const float4*)ap; pv1 = *(const float4*)(ap + 4);
            }
            __nv_bfloat16* nBh = sb + (buf ^ 1) * STG_E + 256 * 24;
            __nv_bfloat16* nBl = nBh + NT * 24;
            for (int i = tid; i < NT * 2; i += 256) {
                int n = i >> 1, kk = (i & 1) * 8;
                size_t g = (size_t)(col0 + n) * K + (kc + 1) * 16 + kk;
                cp16(&nBh[n * 24 + kk], Bhi + g);
                cp16(&nBl[n * 24 + kk], Blo + g);
            }
            CP_COMMIT();
        }

        wmma::fragment<wmma::matrix_a, 16, 16, 16, __nv_bfloat16, wmma::row_major> ah[2], al[2];
        #pragma unroll
        for (int m = 0; m < 2; m++) {
            wmma::load_matrix_sync(ah[m], sAh + (wm * 32 + m * 16) * 24, 24);
            wmma::load_matrix_sync(al[m], sAl + (wm * 32 + m * 16) * 24, 24);
        }
        #pragma unroll
        for (int n = 0; n < NTI; n++) {
            wmma::fragment<wmma::matrix_b, 16, 16, 16, __nv_bfloat16, wmma::col_major> bh, bl;
            wmma::load_matrix_sync(bh, sBh + (wn * WN + n * 16) * 24, 24);
            wmma::load_matrix_sync(bl, sBl + (wn * WN + n * 16) * 24, 24);
            #pragma unroll
            for (int m = 0; m < 2; m++) {
                wmma::mma_sync(acc[m][n], ah[m], bh, acc[m][n]);
                wmma::mma_sync(acc[m][n], ah[m], bl, acc[m][n]);
                wmma::mma_sync(acc[m][n], al[m], bh, acc[m][n]);
            }
        }

        if (kc + 1 < KC) {
            __nv_bfloat16* nAh = sb + (buf ^ 1) * STG_E;
            __nv_bfloat16* nAl = nAh + 128 * 24;
            float vv[8] = {pv0.x, pv0.y, pv0.z, pv0.w, pv1.x, pv1.y, pv1.z, pv1.w};
            ushort hs[8], ls[8];
            #pragma unroll
            for (int q = 0; q < 8; q++) {
                __nv_bfloat16 h = __float2bfloat16(vv[q]);
                hs[q] = __bfloat16_as_ushort(h);
                ls[q] = __bfloat16_as_ushort(__float2bfloat16(vv[q] - __bfloat162float(h)));
            }
            uint4 hp, lp;
            hp.x = hs[0] | ((uint32_t)hs[1] << 16); hp.y = hs[2] | ((uint32_t)hs[3] << 16);
            hp.z = hs[4] | ((uint32_t)hs[5] << 16); hp.w = hs[6] | ((uint32_t)hs[7] << 16);
            lp.x = ls[0] | ((uint32_t)ls[1] << 16); lp.y = ls[2] | ((uint32_t)ls[3] << 16);
            lp.z = ls[4] | ((uint32_t)ls[5] << 16); lp.w = ls[6] | ((uint32_t)ls[7] << 16);
            *(uint4*)&nAh[ar * 24 + akk] = hp;
            *(uint4*)&nAl[ar * 24 + akk] = lp;
        }
    }
    __syncthreads();

    if (MODE == 2) {
        #pragma unroll
        for (int m = 0; m < 2; m++)
            #pragma unroll
            for (int n = 0; n < NTI; n++)
                wmma::store_matrix_sync(stg + (wm * 32 + m * 16) * NTS + wn * WN + n * 16,
                                        acc[m][n], NTS, wmma::mem_row_major);
        __syncthreads();
        if (tid < 128) {
            int r = row0 + tid;
            if (r < M) {
                const float* row = stg + tid * NTS;
                float v[40];
                float mx = -CUDART_INF_F;
                #pragma unroll
                for (int c = 0; c < 40; c++) { v[c] = row[c] + bias[c]; mx = fmaxf(mx, v[c]); }
                float s = 0.f;
                #pragma unroll
                for (int c = 0; c < 40; c++) s += expf(v[c] - mx);
                float lse = mx + logf(s);
                #pragma unroll
                for (int c = 0; c < 40; c += 4) {
                    float4 f = make_float4(v[c] - lse, v[c+1] - lse, v[c+2] - lse, v[c+3] - lse);
                    *(float4*)&out0[(size_t)r * 40 + c] = f;
                }
            }
        }
    } else {
        #pragma unroll
        for (int m = 0; m < 2; m++) {
            int gr0 = row0 + wm * 32 + m * 16;
            #pragma unroll
            for (int n = 0; n < NTI; n++) {
                int gc = col0 + wn * WN + n * 16;
                if (MODE == 1) {
                    #pragma unroll
                    for (int t = 0; t < acc[m][n].num_elements; t++)
                        acc[m][n].x[t] = fmaxf(acc[m][n].x[t], 0.f);
                    wmma::store_matrix_sync(out0 + (size_t)gr0 * ldc + gc, acc[m][n],
                                            ldc, wmma::mem_row_major);
                } else {
                    float* dst = (gc < 128) ? (out0 + (size_t)gr0 * 128 + gc)
                                            : (out1 + (size_t)gr0 * 128 + gc - 128);
                    wmma::store_matrix_sync(dst, acc[m][n], 128, wmma::mem_row_major);
                }
            }
        }
    }
}

// ---------------- misc1 / fin2 / scatter2 ----------------
constexpr int NBA = (NE + 1023) / 1024;
constexpr int NBB = (NN + 1023) / 1024;
constexpr int DINV_B = (PE + PN + 1023) / 1024;
constexpr int RDA_B = (NN + 31) / 32;

__device__ __forceinline__ void scan_body(const int* __restrict__ cnt, int n,
                                          int* __restrict__ incl, int* __restrict__ bsums,
                                          int b) {
    __shared__ int sm[1024];
    int i = b * 1024 + threadIdx.x;
    int v = (i < n) ? cnt[i] : 0;
    sm[threadIdx.x] = v;
    __syncthreads();
    for (int o = 1; o < 1024; o <<= 1) {
        int t = (threadIdx.x >= o) ? sm[threadIdx.x - o] : 0;
        __syncthreads();
        sm[threadIdx.x] += t;
        __syncthreads();
    }
    if (i < n) incl[i] = sm[threadIdx.x];
    if (threadIdx.x == 1023) bsums[b] = sm[1023];
}

__global__ void misc1_k(const int* __restrict__ cntA, int* inclA, int* bsumA,
                        const int* __restrict__ cntB, int* inclB, int* bsumB,
                        const int* __restrict__ degA, float* dinvA,
                        const int* __restrict__ degB, float* dinvB,
                        const float* __restrict__ X, const float* __restrict__ Wks,
                        float* S) {
    int b = blockIdx.x;
    if (b < NBA) { scan_body(cntA, NE, inclA, bsumA, b); return; }
    b -= NBA;
    if (b < NBB) { scan_body(cntB, NN, inclB, bsumB, b); return; }
    b -= NBB;
    if (b < DINV_B) {
        int i = b * 1024 + threadIdx.x;
        if (i < PE) dinvA[i] = rsqrtf((float)(degA[i] + 1));
        else if (i < PE + PN) dinvB[i - PE] = rsqrtf((float)(degB[i - PE] + 1));
        return;
    }
    b -= DINV_B;
    int gw = b * 32 + (threadIdx.x >> 5);
    if (gw < NN) rowdot_body(X, Wks, S, gw, 128, threadIdx.x & 31);
}

__global__ void fin2_k(const int* __restrict__ inclA, const int* __restrict__ bsumA, int* offA,
                       const int* __restrict__ inclB, const int* __restrict__ bsumB, int* offB) {
    __shared__ int pfx;
    int b = blockIdx.x;
    if (b < NBA) {
        if (threadIdx.x == 0) {
            int s = 0;
            for (int t = 0; t < b; t++) s += bsumA[t];
            pfx = s;
        }
        __syncthreads();
        int i = b * 1024 + threadIdx.x;
        if (i < NE) offA[i + 1] = inclA[i] + pfx;
        if (i == 0) offA[0] = 0;
    } else {
        b -= NBA;
        if (threadIdx.x == 0) {
            int s = 0;
            for (int t = 0; t < b; t++) s += bsumB[t];
            pfx = s;
        }
        __syncthreads();
        int i = b * 1024 + threadIdx.x;
        if (i < NN) offB[i + 1] = inclB[i] + pfx;
        if (i == 0) offB[0] = 0;
    }
}

__device__ __forceinline__ void scatter_one(const int* src, const int* dst, const int* batch,
                                            const int* map, const float* dinv, const int* off,
                                            int* cursor, int i, int* outG, float* outW) {
    int d = dst[i];
    int s = batch[d];
    int pos = off[s] + atomicAdd(&cursor[s], 1);
    int sc = src[i];
    outG[pos] = map[sc];
    outW[pos] = dinv[sc] * dinv[d];
}

__global__ void scatter2_k(const int* eb_ei, const int* eb_batch, const int* eb_map,
                           const float* dinvA, const int* offA, int* curA,
                           int* srtGA, float* srtWA,
                           const int* nb_ei, const int* nb_batch, const int* nb_map,
                           const float* dinvB, const int* offB, int* curB,
                           int* srtGB, float* srtWB) {
    int i = blockIdx.x * blockDim.x + threadIdx.x;
    if (i < ME)
        scatter_one(eb_ei, eb_ei + ME, eb_batch, eb_map, dinvA, offA, curA, i, srtGA, srtWA);
    else if (i < ME + MN)
        scatter_one(nb_ei, nb_ei + MN, nb_batch, nb_map, dinvB, offB, curB, i - ME, srtGB, srtWB);
}

// ---------------- fused per-segment: GCN-conv mean + PMA softmax pool ----------------
// Warp per segment; deep unroll for memory-level parallelism (8-wide conv gather,
// 4-wide combined incidence pass = 8 row-loads in flight).
__global__ void __launch_bounds__(256)
seg_fused_k(const float* __restrict__ H, const float* __restrict__ V,
            const float* __restrict__ S4, const int* __restrict__ map,
            const float* __restrict__ dinv,
            const int* __restrict__ segP, const int* __restrict__ eOff,
            const int* __restrict__ sG, const float* __restrict__ sW,
            const float* __restrict__ bias,
            float* __restrict__ outConv, int ldOut,
            float* __restrict__ pooled, int S) {
    int w = (blockIdx.x * blockDim.x + threadIdx.x) >> 5;
    if (w >= S) return;
    int lane = threadIdx.x & 31;
    int h = lane >> 3;
    int sub = lane & 7;
    int s = w;
    const float4* H4 = (const float4*)H;
    const float4* V4 = (const float4*)V;

    int p0 = segP[s], p1 = segP[s + 1];
    int e0 = eOff[s], e1 = eOff[s + 1];

    // conv edge gather, 8-wide unroll
    float4 acc = make_float4(0.f, 0.f, 0.f, 0.f);
    int j = e0;
    for (; j + 7 < e1; j += 8) {
        int g[8];
        float wt[8];
        #pragma unroll
        for (int q = 0; q < 8; q++) { g[q] = sG[j + q]; wt[q] = sW[j + q]; }
        float4 hv[8];
        #pragma unroll
        for (int q = 0; q < 8; q++) hv[q] = H4[(size_t)g[q] * 32 + lane];
        #pragma unroll
        for (int q = 0; q < 8; q++) {
            acc.x += hv[q].x * wt[q];
            acc.y += hv[q].y * wt[q];
            acc.z += hv[q].z * wt[q];
            acc.w += hv[q].w * wt[q];
        }
    }
    for (; j < e1; j++) {
        int g = sG[j]; float wt = sW[j];
        float4 hv = H4[(size_t)g * 32 + lane];
        acc.x += hv.x * wt; acc.y += hv.y * wt; acc.z += hv.z * wt; acc.w += hv.w * wt;
    }

    // max pass, 8-wide per head
    float m = -CUDART_INF_F;
    for (int p = p0 + sub; p < p1; p += 8)
        m = fmaxf(m, S4[(size_t)map[p] * 4 + h]);
    #pragma unroll
    for (int o = 1; o < 8; o <<= 1)
        m = fmaxf(m, __shfl_xor_sync(0xffffffffu, m, o));

    // combined pass (self-loop conv + exp-sum + weighted V), 4-wide unroll
    float den = 0.f;
    float4 pv = make_float4(0.f, 0.f, 0.f, 0.f);
    int p = p0;
    for (; p + 3 < p1; p += 4) {
        int g[4];
        float wt[4], e[4];
        #pragma unroll
        for (int q = 0; q < 4; q++) {
            g[q] = map[p + q];
            float d = dinv[p + q];
            wt[q] = d * d;
        }
        float4 hv[4], vv[4];
        #pragma unroll
        for (int q = 0; q < 4; q++) {
            hv[q] = H4[(size_t)g[q] * 32 + lane];
            vv[q] = V4[(size_t)g[q] * 32 + lane];
        }
        #pragma unroll
        for (int q = 0; q < 4; q++) {
            e[q] = __expf(S4[(size_t)g[q] * 4 + h] - m);
            den += e[q];
        }
        #pragma unroll
        for (int q = 0; q < 4; q++) {
            acc.x += hv[q].x * wt[q];  pv.x += vv[q].x * e[q];
            acc.y += hv[q].y * wt[q];  pv.y += vv[q].y * e[q];
            acc.z += hv[q].z * wt[q];  pv.z += vv[q].z * e[q];
            acc.w += hv[q].w * wt[q];  pv.w += vv[q].w * e[q];
        }
    }
    for (; p < p1; p++) {
        int g = map[p];
        float d = dinv[p];
        float wt = d * d;
        float e = __expf(S4[(size_t)g * 4 + h] - m);
        den += e;
        float4 hv = H4[(size_t)g * 32 + lane];
        float4 vv = V4[(size_t)g * 32 + lane];
        acc.x += hv.x * wt;  pv.x += vv.x * e;
        acc.y += hv.y * wt;  pv.y += vv.y * e;
        acc.z += hv.z * wt;  pv.z += vv.z * e;
        acc.w += hv.w * wt;  pv.w += vv.w * e;
    }

    int cnt = p1 - p0;
    float4 ob;
    if (cnt > 0) {
        float inv = 1.f / (float)cnt;
        float4 b4 = *(const float4*)&bias[lane * 4];
        ob.x = fmaxf(acc.x * inv + b4.x, 0.f);
        ob.y = fmaxf(acc.y * inv + b4.y, 0.f);
        ob.z = fmaxf(acc.z * inv + b4.z, 0.f);
        ob.w = fmaxf(acc.w * inv + b4.w, 0.f);
    } else {
        ob = make_float4(0.f, 0.f, 0.f, 0.f);
    }
    *(float4*)&outConv[(size_t)s * ldOut + lane * 4] = ob;

    float dn = 1.f / fmaxf(den, 1e-9f);
    float4 op;
    op.x = pv.x * dn; op.y = pv.y * dn; op.z = pv.z * dn; op.w = pv.w * dn;
    if (cnt == 0) op = make_float4(0.f, 0.f, 0.f, 0.f);
    *(float4*)&pooled[(size_t)s * 128 + lane * 4] = op;
}

// ---------------- orchestration (single stream, graph-safe) ----------------
static inline int cdiv(int a, int b) { return (a + b - 1) / b; }

extern "C" void kernel_launch(void* const* d_in, const int* in_sizes, int n_in,
                              void* d_out, int out_size) {
    (void)in_sizes; (void)n_in; (void)out_size;
    const float* node_x  = (const float*)d_in[0];
    const int* eb_map    = (const int*)d_in[1];
    const int* eb_ei     = (const int*)d_in[2];
    const int* eb_batch  = (const int*)d_in[3];
    const int* nb_map    = (const int*)d_in[4];
    const int* nb_ei     = (const int*)d_in[5];
    const int* nb_batch  = (const int*)d_in[6];
    const float* W1   = (const float*)d_in[7];
    const float* b1   = (const float*)d_in[8];
    const float* Wk1  = (const float*)d_in[9];
    const float* Wv1  = (const float*)d_in[10];
    const float* sd1  = (const float*)d_in[11];
    const float* Wo1  = (const float*)d_in[12];
    const float* W2   = (const float*)d_in[13];
    const float* b2   = (const float*)d_in[14];
    const float* Wk2  = (const float*)d_in[15];
    const float* Wv2  = (const float*)d_in[16];
    const float* sd2  = (const float*)d_in[17];
    const float* Wo2  = (const float*)d_in[18];
    const float* clsW = (const float*)d_in[19];
    const float* clsb = (const float*)d_in[20];
    float* out = (float*)d_out;

    void* basep = nullptr;
    cudaGetSymbolAddress(&basep, g_scratch);
    char* base = (char*)basep;
    float* nodeH  = (float*)(base + O_NODEH);
    float* nodeV  = (float*)(base + O_NODEV);
    float* nodeS  = (float*)(base + O_NODES);
    int*   degA   = (int*)  (base + O_DEGA);
    float* dinvA  = (float*)(base + O_DINVA);
    int*   segPA  = (int*)  (base + O_SEGPA);
    int*   cntA   = (int*)  (base + O_CNTA);
    int*   offA   = (int*)  (base + O_OFFA);
    int*   curA   = (int*)  (base + O_CURA);
    int*   srtGA  = (int*)  (base + O_SRTGA);
    float* srtWA  = (float*)(base + O_SRTWA);
    float* poolA  = (float*)(base + O_POOLA);
    float* edgeX  = (float*)(base + O_EDGEX);
    float* edgeH  = (float*)(base + O_EDGEH);
    float* edgeV  = (float*)(base + O_EDGEV);
    float* edgeS  = (float*)(base + O_EDGES);
    int*   degB   = (int*)  (base + O_DEGB);
    float* dinvB  = (float*)(base + O_DINVB);
    int*   segPB  = (int*)  (base + O_SEGPB);
    int*   cntB   = (int*)  (base + O_CNTB);
    int*   offB   = (int*)  (base + O_OFFB);
    int*   curB   = (int*)  (base + O_CURB);
    int*   srtGB  = (int*)  (base + O_SRTGB);
    float* srtWB  = (float*)(base + O_SRTWB);
    float* poolB  = (float*)(base + O_POOLB);
    float* nodeO  = (float*)(base + O_NODEO);
    float* WksA   = (float*)(base + O_WKSA);
    float* WksB   = (float*)(base + O_WKSB);
    int*   inclA  = (int*)  (base + O_INCLA);
    int*   bsumA  = (int*)  (base + O_BSUMA);
    int*   inclB  = (int*)  (base + O_INCLB);
    int*   bsumB  = (int*)  (base + O_BSUMB);
    __nv_bfloat16* WAh  = (__nv_bfloat16*)(base + O_WAH);
    __nv_bfloat16* WAl  = (__nv_bfloat16*)(base + O_WAL);
    __nv_bfloat16* WO1h = (__nv_bfloat16*)(base + O_WO1H);
    __nv_bfloat16* WO1l = (__nv_bfloat16*)(base + O_WO1L);
    __nv_bfloat16* WBh  = (__nv_bfloat16*)(base + O_WBH);
    __nv_bfloat16* WBl  = (__nv_bfloat16*)(base + O_WBL);
    __nv_bfloat16* WO2h = (__nv_bfloat16*)(base + O_WO2H);
    __nv_bfloat16* WO2l = (__nv_bfloat16*)(base + O_WO2L);
    __nv_bfloat16* WCh  = (__nv_bfloat16*)(base + O_WCH);
    __nv_bfloat16* WCl  = (__nv_bfloat16*)(base + O_WCL);

    constexpr int SMAB128 = 2 * (256 + 2 * 128) * 24 * 2;  // 49152
    constexpr int SMCLS   = 2 * (256 + 2 * 64) * 24 * 2;   // 36864
    cudaFuncSetAttribute(wgemm_k<8, 128, 0, 1>,  cudaFuncAttributeMaxDynamicSharedMemorySize, SMAB128);
    cudaFuncSetAttribute(wgemm_k<8, 128, 1, 0>,  cudaFuncAttributeMaxDynamicSharedMemorySize, SMAB128);
    cudaFuncSetAttribute(wgemm_k<16, 128, 0, 2>, cudaFuncAttributeMaxDynamicSharedMemorySize, SMAB128);
    cudaFuncSetAttribute(wgemm_k<16, 64, 2, 0>,  cudaFuncAttributeMaxDynamicSharedMemorySize, SMCLS);

    XArgs xnone = {};
    XArgs xdeg = { eb_ei + ME, eb_batch, degA, cntA,
                   nb_ei + MN, nb_batch, degB, cntB,
                   nullptr, nullptr, nullptr, 0 };
    XArgs xrdB = { nullptr, nullptr, nullptr, nullptr,
                   nullptr, nullptr, nullptr, nullptr,
                   edgeX, WksB, edgeS, NE };

    // L1: init + seg_starts + all weight prep
    misc0_k<<<cdiv(M0_R7, 256), 256>>>(eb_batch, nb_batch,
                                       degA, cntA, curA, degB, cntB, curB, segPA, segPB,
                                       W1, Wv1, Wo1, W2, Wv2, Wo2, clsW,
                                       Wk1, sd1, Wk2, sd2,
                                       WAh, WAl, WO1h, WO1l, WBh, WBl,
                                       WO2h, WO2l, WCh, WCl, WksA, WksB);

    // L2: stage-A GEMM  ∥  degcount (both stages)
    {
        int gx = cdiv(NN, 128);
        int extra = cdiv(ME + MN, 256);
        dim3 g(gx + extra, 2);
        wgemm_k<8, 128, 0, 1><<<g, 256, SMAB128>>>(node_x, NN, WAh, WAl, nullptr,
                                                   nodeH, nodeV, 0, gx, xdeg);
    }

    // L3: both scans + both dinv + rowdot4-A
    misc1_k<<<NBA + NBB + DINV_B + RDA_B, 1024>>>(cntA, inclA, bsumA, cntB, inclB, bsumB,
                                                  degA, dinvA, degB, dinvB,
                                                  node_x, WksA, nodeS);
    // L4: finalize offsets
    fin2_k<<<NBA + NBB, 1024>>>(inclA, bsumA, offA, inclB, bsumB, offB);

    // L5: both scatters
    scatter2_k<<<cdiv(ME + MN, 256), 256>>>(eb_ei, eb_batch, eb_map, dinvA, offA, curA,
                                            srtGA, srtWA,
                                            nb_ei, nb_batch, nb_map, dinvB, offB, curB,
                                            srtGB, srtWB);

    // L6: stage-A fused segment kernel
    seg_fused_k<<<cdiv(NE * 32, 256), 256>>>(nodeH, nodeV, nodeS, eb_map, dinvA, segPA, offA,
                                             srtGA, srtWA, b1, edgeX, 256, poolA, NE);
    // L7: Wo1
    {
        int gx = cdiv(NE, 128);
        dim3 g(gx, 1);
        wgemm_k<8, 128, 1, 0><<<g, 256, SMAB128>>>(poolA, NE, WO1h, WO1l, nullptr,
                                                   edgeX + 128, nullptr, 256, gx, xnone);
    }

    // L8: stage-B GEMM  ∥  rowdot4-B
    {
        int gx = cdiv(NE, 128);
        int extra = cdiv(NE * 32, 256);
        dim3 g(gx + extra, 2);
        wgemm_k<16, 128, 0, 2><<<g, 256, SMAB128>>>(edgeX, NE, WBh, WBl, nullptr,
                                                    edgeH, edgeV, 0, gx, xrdB);
    }

    // L9: stage-B fused segment kernel
    seg_fused_k<<<cdiv(NN * 32, 256), 256>>>(edgeH, edgeV, edgeS, nb_map, dinvB, segPB, offB,
                                             srtGB, srtWB, b2, nodeO, 256, poolB, NN);
    // L10: Wo2
    {
        int gx = cdiv(NN, 128);
        dim3 g(gx, 1);
        wgemm_k<8, 128, 1, 0><<<g, 256, SMAB128>>>(poolB, NN, WO2h, WO2l, nullptr,
                                                   nodeO + 128, nullptr, 256, gx, xnone);
    }

    // L11: classifier + fused log-softmax
    {
        int gx = cdiv(NN, 128);
        dim3 g(gx, 1);
        wgemm_k<16, 64, 2, 0><<<g, 256, SMCLS>>>(nodeO, NN, WCh, WCl, clsb,
                                                 out, nullptr, 40, gx, xnone);
    }
}